// round 11
// baseline (speedup 1.0000x reference)
#include <cuda_runtime.h>
#include <cuda_bf16.h>
#include <cstdint>
#include <math.h>

#define BB 2
#define SS 2048
#define DMODEL 1024
#define NH 16
#define NKH 4
#define HD 64
#define NQKV 1536

// ---------------------------------------------------------------------------
// Scratch (device globals: allocation-free)
// ---------------------------------------------------------------------------
__device__ __nv_bfloat16 g_xh[BB * SS * DMODEL];
__device__ __nv_bfloat16 g_xl[BB * SS * DMODEL];
__device__ __nv_bfloat16 g_oh[BB * SS * NH * HD];
__device__ __nv_bfloat16 g_ol[BB * SS * NH * HD];
__device__ __nv_bfloat16 g_wqkvh[NQKV * DMODEL];
__device__ __nv_bfloat16 g_wqkvl[NQKV * DMODEL];
__device__ __nv_bfloat16 g_woh[DMODEL * (NH * HD)];
__device__ __nv_bfloat16 g_wol[DMODEL * (NH * HD)];

__device__ __nv_bfloat16 g_qh[BB * SS * NH * HD];
__device__ __nv_bfloat16 g_ql[BB * SS * NH * HD];
__device__ __nv_bfloat16 g_kh2[BB * SS * NKH * HD];
__device__ __nv_bfloat16 g_kl2[BB * SS * NKH * HD];
__device__ __nv_bfloat16 g_vth[BB * NKH * HD * SS];   // [b][kh][d][s]
__device__ __nv_bfloat16 g_vtl[BB * NKH * HD * SS];

// ---------------------------------------------------------------------------
// Warp-level MMA helpers
// ---------------------------------------------------------------------------
__device__ __forceinline__ uint32_t smem_u32(const void* p) {
    uint32_t a;
    asm("{ .reg .u64 t; cvta.to.shared.u64 t, %1; cvt.u32.u64 %0, t; }"
        : "=r"(a) : "l"(p));
    return a;
}

__device__ __forceinline__ void ldsm4(uint32_t& r0, uint32_t& r1,
                                      uint32_t& r2, uint32_t& r3, uint32_t a) {
    asm volatile("ldmatrix.sync.aligned.m8n8.x4.shared.b16 {%0,%1,%2,%3}, [%4];"
                 : "=r"(r0), "=r"(r1), "=r"(r2), "=r"(r3) : "r"(a));
}

__device__ __forceinline__ void mma_bf16(float* c, const uint32_t* a,
                                         const uint32_t* b) {
    asm volatile(
        "mma.sync.aligned.m16n8k16.row.col.f32.bf16.bf16.f32 "
        "{%0,%1,%2,%3}, {%4,%5,%6,%7}, {%8,%9}, {%0,%1,%2,%3};"
        : "+f"(c[0]), "+f"(c[1]), "+f"(c[2]), "+f"(c[3])
        : "r"(a[0]), "r"(a[1]), "r"(a[2]), "r"(a[3]), "r"(b[0]), "r"(b[1]));
}

#define CP_ASYNC16(sa, ga) \
    asm volatile("cp.async.cg.shared.global [%0], [%1], 16;" \
                 :: "r"(sa), "l"(ga))
#define CP_COMMIT() asm volatile("cp.async.commit_group;")
#define CP_WAIT(N)  asm volatile("cp.async.wait_group %0;" :: "n"(N))

// ---------------------------------------------------------------------------
// GEMM common config
// ---------------------------------------------------------------------------
#define BK 32
#define GSTRIDE 40
#define GTILE_B (128 * GSTRIDE * 2)
#define GOFF(t, st) (((st) * 4 + (t)) * GTILE_B)
#define GEMM_SMEM (8 * GTILE_B)
#define TSTR 132   // fp32 epilogue tile stride

#define GEMM_MAINLOOP(OUT_ACC)                                                \
    float OUT_ACC[4][4][4];                                                   \
    _Pragma("unroll")                                                         \
    for (int i = 0; i < 4; i++)                                               \
        _Pragma("unroll")                                                     \
        for (int j = 0; j < 4; j++)                                           \
            _Pragma("unroll")                                                 \
            for (int r = 0; r < 4; r++) OUT_ACC[i][j][r] = 0.0f;              \
    const int nchunk = K / BK;                                                \
    load_stage(0, 0);                                                         \
    const int a_r = lane & 15;                                                \
    const int a_c = (lane >> 4) * 8;                                          \
    const int g4 = lane >> 3;                                                 \
    const int b4_r = (g4 >> 1) * 8 + (lane & 7);                              \
    const int b4_c = (g4 & 1) * 8;                                            \
    for (int c = 0; c < nchunk; c++) {                                        \
        const int st = c & 1;                                                 \
        if (c + 1 < nchunk) { load_stage(c + 1, st ^ 1); CP_WAIT(1); }        \
        else { CP_WAIT(0); }                                                  \
        __syncthreads();                                                      \
        const uint32_t sAh = sb + GOFF(0, st);                                \
        const uint32_t sAl = sb + GOFF(1, st);                                \
        const uint32_t sBh = sb + GOFF(2, st);                                \
        const uint32_t sBl = sb + GOFF(3, st);                                \
        _Pragma("unroll")                                                     \
        for (int kf = 0; kf < 2; kf++) {                                      \
            const int kc = kf * 16;                                           \
            uint32_t ah[4][4], al[4][4], bh[4][2], bl[4][2];                  \
            _Pragma("unroll")                                                 \
            for (int mf = 0; mf < 4; mf++) {                                  \
                uint32_t ad = ((warp_m + mf * 16 + a_r) * GSTRIDE + kc + a_c) * 2; \
                ldsm4(ah[mf][0], ah[mf][1], ah[mf][2], ah[mf][3], sAh + ad);  \
            }                                                                 \
            _Pragma("unroll")                                                 \
            for (int np = 0; np < 2; np++) {                                  \
                uint32_t bd = ((warp_n + np * 16 + b4_r) * GSTRIDE + kc + b4_c) * 2; \
                ldsm4(bh[np * 2][0], bh[np * 2][1],                           \
                      bh[np * 2 + 1][0], bh[np * 2 + 1][1], sBh + bd);        \
                ldsm4(bl[np * 2][0], bl[np * 2][1],                           \
                      bl[np * 2 + 1][0], bl[np * 2 + 1][1], sBl + bd);        \
            }                                                                 \
            _Pragma("unroll")                                                 \
            for (int mf = 0; mf < 4; mf++)                                    \
                _Pragma("unroll")                                             \
                for (int nf = 0; nf < 4; nf++) {                              \
                    mma_bf16(OUT_ACC[mf][nf], ah[mf], bh[nf]);                \
                    mma_bf16(OUT_ACC[mf][nf], ah[mf], bl[nf]);                \
                }                                                             \
            _Pragma("unroll")                                                 \
            for (int mf = 0; mf < 4; mf++) {                                  \
                uint32_t ad = ((warp_m + mf * 16 + a_r) * GSTRIDE + kc + a_c) * 2; \
                ldsm4(al[mf][0], al[mf][1], al[mf][2], al[mf][3], sAl + ad);  \
            }                                                                 \
            _Pragma("unroll")                                                 \
            for (int mf = 0; mf < 4; mf++)                                    \
                _Pragma("unroll")                                             \
                for (int nf = 0; nf < 4; nf++)                                \
                    mma_bf16(OUT_ACC[mf][nf], al[mf], bh[nf]);                \
        }                                                                     \
        __syncthreads();                                                      \
    }

// ---------------------------------------------------------------------------
// bf16x3 HMMA GEMM with plain fp32 C output (out-projection).
// ---------------------------------------------------------------------------
__global__ __launch_bounds__(256, 2) void gemm_bf16x3_kernel(
    const __nv_bfloat16* __restrict__ Ah, const __nv_bfloat16* __restrict__ Al,
    const __nv_bfloat16* __restrict__ Bh, const __nv_bfloat16* __restrict__ Bl,
    float* __restrict__ C, int M, int N, int K)
{
    extern __shared__ __align__(128) char smem[];
    const uint32_t sb = smem_u32(smem);
    const int tid = threadIdx.x;
    const int wid = tid >> 5;
    const int lane = tid & 31;
    const int bm = blockIdx.y * 128;
    const int bn = blockIdx.x * 128;
    const int warp_m = (wid >> 2) * 64;
    const int warp_n = (wid & 3) * 32;

    const __nv_bfloat16* gp[4] = {
        Ah + (size_t)bm * K, Al + (size_t)bm * K,
        Bh + (size_t)bn * K, Bl + (size_t)bn * K };

    const int lrow0 = tid >> 2;
    const int lq = tid & 3;

    auto load_stage = [&](int c, int st) {
#pragma unroll
        for (int t = 0; t < 4; t++) {
            const __nv_bfloat16* P = gp[t] + (size_t)c * BK;
#pragma unroll
            for (int it = 0; it < 2; it++) {
                int row = lrow0 + it * 64;
                uint32_t sa = sb + GOFF(t, st) + (row * GSTRIDE + lq * 8) * 2;
                CP_ASYNC16(sa, P + (size_t)row * K + lq * 8);
            }
        }
        CP_COMMIT();
    };

    GEMM_MAINLOOP(acc)

    const int er = lane >> 2;
    const int ec = (lane & 3) * 2;
#pragma unroll
    for (int mf = 0; mf < 4; mf++) {
#pragma unroll
        for (int nf = 0; nf < 4; nf++) {
            float* base = C + (size_t)(bm + warp_m + mf * 16 + er) * N
                            + bn + warp_n + nf * 8 + ec;
            *(float2*)base = make_float2(acc[mf][nf][0], acc[mf][nf][1]);
            *(float2*)(base + 8 * N) = make_float2(acc[mf][nf][2], acc[mf][nf][3]);
        }
    }
}

// ---------------------------------------------------------------------------
// QKV GEMM with fused RoPE+split / V-transpose+split epilogue.
// Q is scaled by 0.125*log2(e) so flash can use exp2.
// ---------------------------------------------------------------------------
__global__ __launch_bounds__(256, 2) void gemm_qkv_kernel(
    const __nv_bfloat16* __restrict__ Ah, const __nv_bfloat16* __restrict__ Al,
    const __nv_bfloat16* __restrict__ Bh, const __nv_bfloat16* __restrict__ Bl,
    const float* __restrict__ cosb, const float* __restrict__ sinb,
    __nv_bfloat16* __restrict__ qh, __nv_bfloat16* __restrict__ ql,
    __nv_bfloat16* __restrict__ khp, __nv_bfloat16* __restrict__ klp,
    __nv_bfloat16* __restrict__ vh, __nv_bfloat16* __restrict__ vl)
{
    extern __shared__ __align__(128) char smem[];
    const uint32_t sb = smem_u32(smem);
    const int tid = threadIdx.x;
    const int wid = tid >> 5;
    const int lane = tid & 31;
    const int bm = blockIdx.y * 128;
    const int bn = blockIdx.x * 128;
    const int warp_m = (wid >> 2) * 64;
    const int warp_n = (wid & 3) * 32;
    const int K = DMODEL;

    const __nv_bfloat16* gp[4] = {
        Ah + (size_t)bm * K, Al + (size_t)bm * K,
        Bh + (size_t)bn * K, Bl + (size_t)bn * K };

    const int lrow0 = tid >> 2;
    const int lq = tid & 3;

    auto load_stage = [&](int c, int st) {
#pragma unroll
        for (int t = 0; t < 4; t++) {
            const __nv_bfloat16* P = gp[t] + (size_t)c * BK;
#pragma unroll
            for (int it = 0; it < 2; it++) {
                int row = lrow0 + it * 64;
                uint32_t sa = sb + GOFF(t, st) + (row * GSTRIDE + lq * 8) * 2;
                CP_ASYNC16(sa, P + (size_t)row * K + lq * 8);
            }
        }
        CP_COMMIT();
    };

    GEMM_MAINLOOP(acc)

    float* Ts = (float*)smem;
    const int er = lane >> 2;
    const int ec = (lane & 3) * 2;
#pragma unroll
    for (int mf = 0; mf < 4; mf++) {
#pragma unroll
        for (int nf = 0; nf < 4; nf++) {
            int r = warp_m + mf * 16 + er;
            int c = warp_n + nf * 8 + ec;
            *(float2*)&Ts[r * TSTR + c] = make_float2(acc[mf][nf][0], acc[mf][nf][1]);
            *(float2*)&Ts[(r + 8) * TSTR + c] = make_float2(acc[mf][nf][2], acc[mf][nf][3]);
        }
    }
    __syncthreads();

    if (bn < 1280) {
        const bool isq = (bn < 1024);
        const float scl = isq ? 0.125f * 1.4426950408889634f : 1.0f;
        __nv_bfloat16* th = isq ? qh : khp;
        __nv_bfloat16* tl = isq ? ql : klp;
        const int nheads = isq ? NH : NKH;
        const int h0 = isq ? (bn >> 6) : ((bn - 1024) >> 6);

#pragma unroll
        for (int it = 0; it < 8; it++) {
            int idx = tid + it * 256;
            int d0 = (idx & 7) * 4;
            int hh = (idx >> 3) & 1;
            int row = idx >> 4;
            int bs = bm + row;
            int s = bs & (SS - 1);

            const float* tr = &Ts[row * TSTR + hh * 64];
            float4 v0 = *(const float4*)(tr + d0);
            float4 v1 = *(const float4*)(tr + d0 + 32);
            float4 c0 = *(const float4*)(cosb + s * HD + d0);
            float4 c1 = *(const float4*)(cosb + s * HD + d0 + 32);
            float4 s0v = *(const float4*)(sinb + s * HD + d0);
            float4 s1v = *(const float4*)(sinb + s * HD + d0 + 32);

            float r0x = (v0.x * c0.x - v1.x * s0v.x) * scl;
            float r0y = (v0.y * c0.y - v1.y * s0v.y) * scl;
            float r0z = (v0.z * c0.z - v1.z * s0v.z) * scl;
            float r0w = (v0.w * c0.w - v1.w * s0v.w) * scl;
            float r1x = (v1.x * c1.x + v0.x * s1v.x) * scl;
            float r1y = (v1.y * c1.y + v0.y * s1v.y) * scl;
            float r1z = (v1.z * c1.z + v0.z * s1v.z) * scl;
            float r1w = (v1.w * c1.w + v0.w * s1v.w) * scl;

            size_t base = ((size_t)bs * nheads + h0 + hh) * HD;

            __nv_bfloat162 h0a = __float22bfloat162_rn(make_float2(r0x, r0y));
            __nv_bfloat162 h0b = __float22bfloat162_rn(make_float2(r0z, r0w));
            __nv_bfloat162 h1a = __float22bfloat162_rn(make_float2(r1x, r1y));
            __nv_bfloat162 h1b = __float22bfloat162_rn(make_float2(r1z, r1w));
            *(uint2*)(th + base + d0)      = make_uint2(*(uint32_t*)&h0a, *(uint32_t*)&h0b);
            *(uint2*)(th + base + d0 + 32) = make_uint2(*(uint32_t*)&h1a, *(uint32_t*)&h1b);

            __nv_bfloat162 l0a = __float22bfloat162_rn(make_float2(
                r0x - __bfloat162float(h0a.x), r0y - __bfloat162float(h0a.y)));
            __nv_bfloat162 l0b = __float22bfloat162_rn(make_float2(
                r0z - __bfloat162float(h0b.x), r0w - __bfloat162float(h0b.y)));
            __nv_bfloat162 l1a = __float22bfloat162_rn(make_float2(
                r1x - __bfloat162float(h1a.x), r1y - __bfloat162float(h1a.y)));
            __nv_bfloat162 l1b = __float22bfloat162_rn(make_float2(
                r1z - __bfloat162float(h1b.x), r1w - __bfloat162float(h1b.y)));
            *(uint2*)(tl + base + d0)      = make_uint2(*(uint32_t*)&l0a, *(uint32_t*)&l0b);
            *(uint2*)(tl + base + d0 + 32) = make_uint2(*(uint32_t*)&l1a, *(uint32_t*)&l1b);
        }
    } else {
        const int c = tid & 127;
        const int sh = tid >> 7;
        const int khead = ((bn - 1280) >> 6) + (c >> 6);
        const int d = c & 63;
        const int b = bm >> 11;
        const int s0 = (bm & (SS - 1)) + sh * 64;
        size_t base = ((size_t)(b * NKH + khead) * HD + d) * SS + s0;

#pragma unroll 4
        for (int s4 = 0; s4 < 64; s4 += 4) {
            float v0 = Ts[(sh * 64 + s4 + 0) * TSTR + c];
            float v1 = Ts[(sh * 64 + s4 + 1) * TSTR + c];
            float v2 = Ts[(sh * 64 + s4 + 2) * TSTR + c];
            float v3 = Ts[(sh * 64 + s4 + 3) * TSTR + c];
            __nv_bfloat162 p01 = __float22bfloat162_rn(make_float2(v0, v1));
            __nv_bfloat162 p23 = __float22bfloat162_rn(make_float2(v2, v3));
            *(uint2*)(vh + base + s4) = make_uint2(*(uint32_t*)&p01, *(uint32_t*)&p23);
            __nv_bfloat162 q01 = __float22bfloat162_rn(make_float2(
                v0 - __bfloat162float(p01.x), v1 - __bfloat162float(p01.y)));
            __nv_bfloat162 q23 = __float22bfloat162_rn(make_float2(
                v2 - __bfloat162float(p23.x), v3 - __bfloat162float(p23.y)));
            *(uint2*)(vl + base + s4) = make_uint2(*(uint32_t*)&q01, *(uint32_t*)&q23);
        }
    }
}

// ---------------------------------------------------------------------------
// Elementwise split fp32 -> (hi, lo) bf16.
// ---------------------------------------------------------------------------
__global__ void split_kernel(const float4* __restrict__ src,
                             __nv_bfloat162* __restrict__ dh,
                             __nv_bfloat162* __restrict__ dl, int n4)
{
    int i = blockIdx.x * blockDim.x + threadIdx.x;
    if (i >= n4) return;
    float4 v = src[i];
    __nv_bfloat16 h0 = __float2bfloat16(v.x);
    __nv_bfloat16 h1 = __float2bfloat16(v.y);
    __nv_bfloat16 h2 = __float2bfloat16(v.z);
    __nv_bfloat16 h3 = __float2bfloat16(v.w);
    dh[2 * i]     = __nv_bfloat162(h0, h1);
    dh[2 * i + 1] = __nv_bfloat162(h2, h3);
    __nv_bfloat16 l0 = __float2bfloat16(v.x - __bfloat162float(h0));
    __nv_bfloat16 l1 = __float2bfloat16(v.y - __bfloat162float(h1));
    __nv_bfloat16 l2 = __float2bfloat16(v.z - __bfloat162float(h2));
    __nv_bfloat16 l3 = __float2bfloat16(v.w - __bfloat162float(h3));
    dl[2 * i]     = __nv_bfloat162(l0, l1);
    dl[2 * i + 1] = __nv_bfloat162(l2, l3);
}

// ---------------------------------------------------------------------------
// Fused weight prep: all 4 transpose+splits in one launch.
// ---------------------------------------------------------------------------
__global__ void weight_prep_kernel(
    const float* __restrict__ wq, const float* __restrict__ wk,
    const float* __restrict__ wv, const float* __restrict__ wo,
    __nv_bfloat16* __restrict__ wqkvh, __nv_bfloat16* __restrict__ wqkvl,
    __nv_bfloat16* __restrict__ woh, __nv_bfloat16* __restrict__ wol)
{
    __shared__ float t[32][33];
    const int tile = blockIdx.x;
    const float* src;
    __nv_bfloat16 *dh, *dl;
    int N, tloc;
    if (tile < 1024)      { src = wq; dh = wqkvh;                  dl = wqkvl;                  N = 1024; tloc = tile; }
    else if (tile < 1280) { src = wk; dh = wqkvh + 1024 * DMODEL;  dl = wqkvl + 1024 * DMODEL;  N = 256;  tloc = tile - 1024; }
    else if (tile < 1536) { src = wv; dh = wqkvh + 1280 * DMODEL;  dl = wqkvl + 1280 * DMODEL;  N = 256;  tloc = tile - 1280; }
    else                  { src = wo; dh = woh;                    dl = wol;                    N = 1024; tloc = tile - 1536; }
    const int nx = N >> 5;
    const int K = 1024;
    const int n0 = (tloc % nx) * 32;
    const int k0 = (tloc / nx) * 32;
    const int tx = threadIdx.x, ty = threadIdx.y;
#pragma unroll
    for (int i = 0; i < 32; i += 8)
        t[ty + i][tx] = src[(size_t)(k0 + ty + i) * N + n0 + tx];
    __syncthreads();
#pragma unroll
    for (int i = 0; i < 32; i += 8) {
        float v = t[tx][ty + i];
        __nv_bfloat16 h = __float2bfloat16(v);
        float rres = v - __bfloat162float(h);
        size_t o = (size_t)(n0 + ty + i) * K + k0 + tx;
        dh[o] = h;
        dl[o] = __float2bfloat16(rres);
    }
}

// ---------------------------------------------------------------------------
// HMMA bf16x3 flash attention, causal, GQA.
// BLOCK_M=128 (8 warps), BLOCK_N=64; 2-stage pipeline; 2 CTAs/SM; exp2; LPT.
// ---------------------------------------------------------------------------
#define FSTR 72
#define FTILE64 (64 * FSTR * 2)
#define FQ_TILE (128 * FSTR * 2)
#define FQ_H 0
#define FQ_L FQ_TILE
#define FSTG(st) (2 * FQ_TILE + (st) * 4 * FTILE64)
#define FLASH_SMEM (2 * FQ_TILE + 2 * 4 * FTILE64)   // 110592 B -> 2 CTAs/SM

__global__ __launch_bounds__(256, 2) void flash_hmma_kernel(
    const __nv_bfloat16* __restrict__ Qh, const __nv_bfloat16* __restrict__ Ql,
    const __nv_bfloat16* __restrict__ Kh, const __nv_bfloat16* __restrict__ Kl,
    const __nv_bfloat16* __restrict__ Vth, const __nv_bfloat16* __restrict__ Vtl,
    __nv_bfloat16* __restrict__ Oh, __nv_bfloat16* __restrict__ Ol)
{
    extern __shared__ __align__(128) char smem[];
    const uint32_t sb = smem_u32(smem);
    const int tid = threadIdx.x;
    const int wid = tid >> 5;
    const int lane = tid & 31;
    const int qt = gridDim.x - 1 - blockIdx.x;   // LPT
    const int h  = blockIdx.y;
    const int b  = blockIdx.z;
    const int q0 = qt * 128;
    const int khead = h >> 2;
    const int warp_m = wid * 16;

    const int er = lane >> 2;
    const int ec = (lane & 3) * 2;
    const int a_r = lane & 15;
    const int a_c = (lane >> 4) * 8;
    const int g4 = lane >> 3;
    const int b4_r = (g4 >> 1) * 8 + (lane & 7);
    const int b4_c = (g4 & 1) * 8;

    const __nv_bfloat16* qh_g = Qh + ((size_t)(b * SS + q0) * NH + h) * HD;
    const __nv_bfloat16* ql_g = Ql + ((size_t)(b * SS + q0) * NH + h) * HD;
    const __nv_bfloat16* kh_g = Kh + ((size_t)b * SS * NKH + khead) * HD;
    const __nv_bfloat16* kl_g = Kl + ((size_t)b * SS * NKH + khead) * HD;
    const __nv_bfloat16* vth_g = Vth + (size_t)(b * NKH + khead) * HD * SS;
    const __nv_bfloat16* vtl_g = Vtl + (size_t)(b * NKH + khead) * HD * SS;

    auto load_tile64 = [&](const __nv_bfloat16* g, size_t rstride, uint32_t sofs) {
#pragma unroll
        for (int it = 0; it < 2; it++) {
            int ch = tid + it * 256;
            int r = ch >> 3;
            int q8 = ch & 7;
            CP_ASYNC16(sb + sofs + (r * FSTR + q8 * 8) * 2,
                       g + (size_t)r * rstride + q8 * 8);
        }
    };
    auto load_q = [&](const __nv_bfloat16* g, uint32_t sofs) {
#pragma unroll
        for (int it = 0; it < 4; it++) {
            int ch = tid + it * 256;
            int r = ch >> 3;
            int q8 = ch & 7;
            CP_ASYNC16(sb + sofs + (r * FSTR + q8 * 8) * 2,
                       g + (size_t)r * (NH * HD) + q8 * 8);
        }
    };
    auto load_stage = [&](int kt, int st) {
        const int kn = kt * 64;
        load_tile64(kh_g + (size_t)kn * NKH * HD, NKH * HD, FSTG(st) + 0 * FTILE64);
        load_tile64(kl_g + (size_t)kn * NKH * HD, NKH * HD, FSTG(st) + 1 * FTILE64);
        load_tile64(vth_g + kn, SS, FSTG(st) + 2 * FTILE64);
        load_tile64(vtl_g + kn, SS, FSTG(st) + 3 * FTILE64);
        CP_COMMIT();
    };

    const int kt_end = 2 * qt + 1;

    load_q(qh_g, FQ_H);
    load_q(ql_g, FQ_L);
    load_stage(0, 0);

    float m[2] = {-1e30f, -1e30f};
    float l[2] = {0.0f, 0.0f};
    float acc[8][4];
#pragma unroll
    for (int i = 0; i < 8; i++)
#pragma unroll
        for (int r = 0; r < 4; r++) acc[i][r] = 0.0f;

    for (int kt = 0; kt <= kt_end; kt++) {
        const int st = kt & 1;
        if (kt < kt_end) {
            load_stage(kt + 1, st ^ 1);
            CP_WAIT(1);
        } else {
            CP_WAIT(0);
        }
        __syncthreads();

        const int row_lo = q0 + warp_m;
        const bool any  = (kt * 64     <= row_lo + 15);
        const bool full = (kt * 64 + 63 <= row_lo);

        if (any) {
            const uint32_t sKh = sb + FSTG(st) + 0 * FTILE64;
            const uint32_t sKl = sb + FSTG(st) + 1 * FTILE64;
            const uint32_t sVh = sb + FSTG(st) + 2 * FTILE64;
            const uint32_t sVl = sb + FSTG(st) + 3 * FTILE64;

            float sf[8][4];
#pragma unroll
            for (int nf = 0; nf < 8; nf++)
#pragma unroll
                for (int r = 0; r < 4; r++) sf[nf][r] = 0.0f;

#pragma unroll
            for (int kf = 0; kf < 4; kf++) {
                const int kc = kf * 16;
                uint32_t qah[4], qal[4];
                uint32_t ad = ((warp_m + a_r) * FSTR + kc + a_c) * 2;
                ldsm4(qah[0], qah[1], qah[2], qah[3], sb + FQ_H + ad);
                ldsm4(qal[0], qal[1], qal[2], qal[3], sb + FQ_L + ad);
#pragma unroll
                for (int np = 0; np < 4; np++) {
                    uint32_t bd = ((np * 16 + b4_r) * FSTR + kc + b4_c) * 2;
                    uint32_t kbh[4], kbl[4];
                    ldsm4(kbh[0], kbh[1], kbh[2], kbh[3], sKh + bd);
                    ldsm4(kbl[0], kbl[1], kbl[2], kbl[3], sKl + bd);
                    mma_bf16(sf[np * 2],     qah, kbh);
                    mma_bf16(sf[np * 2],     qah, kbl);
                    mma_bf16(sf[np * 2],     qal, kbh);
                    mma_bf16(sf[np * 2 + 1], qah, kbh + 2);
                    mma_bf16(sf[np * 2 + 1], qah, kbl + 2);
                    mma_bf16(sf[np * 2 + 1], qal, kbh + 2);
                }
            }

            // ---- mask (scale and log2e pre-folded into Q) ----
            if (!full) {
                const int i0 = row_lo + er;
#pragma unroll
                for (int nf = 0; nf < 8; nf++) {
                    int j0 = kt * 64 + nf * 8 + ec;
                    if (j0     > i0)     sf[nf][0] = -1e30f;
                    if (j0 + 1 > i0)     sf[nf][1] = -1e30f;
                    if (j0     > i0 + 8) sf[nf][2] = -1e30f;
                    if (j0 + 1 > i0 + 8) sf[nf][3] = -1e30f;
                }
            }

            float rmax0 = -1e30f, rmax1 = -1e30f;
#pragma unroll
            for (int nf = 0; nf < 8; nf++) {
                rmax0 = fmaxf(rmax0, fmaxf(sf[nf][0], sf[nf][1]));
                rmax1 = fmaxf(rmax1, fmaxf(sf[nf][2], sf[nf][3]));
            }
            rmax0 = fmaxf(rmax0, __shfl_xor_sync(0xffffffffu, rmax0, 1));
            rmax0 = fmaxf(rmax0, __shfl_xor_sync(0xffffffffu, rmax0, 2));
            rmax1 = fmaxf(rmax1, __shfl_xor_sync(0xffffffffu, rmax1, 1));
            rmax1 = fmaxf(rmax1, __shfl_xor_sync(0xffffffffu, rmax1, 2));

            float nm0 = fmaxf(m[0], rmax0), nm1 = fmaxf(m[1], rmax1);
            float al0 = exp2f(m[0] - nm0), al1 = exp2f(m[1] - nm1);
            m[0] = nm0; m[1] = nm1;

            float sum0 = 0.0f, sum1 = 0.0f;
#pragma unroll
            for (int nf = 0; nf < 8; nf++) {
                sf[nf][0] = exp2f(sf[nf][0] - nm0);
                sf[nf][1] = exp2f(sf[nf][1] - nm0);
                sf[nf][2] = exp2f(sf[nf][2] - nm1);
                sf[nf][3] = exp2f(sf[nf][3] - nm1);
                sum0 += sf[nf][0] + sf[nf][1];
                sum1 += sf[nf][2] + sf[nf][3];
            }
            sum0 += __shfl_xor_sync(0xffffffffu, sum0, 1);
            sum0 += __shfl_xor_sync(0xffffffffu, sum0, 2);
            sum1 += __shfl_xor_sync(0xffffffffu, sum1, 1);
            sum1 += __shfl_xor_sync(0xffffffffu, sum1, 2);
            l[0] = l[0] * al0 + sum0;
            l[1] = l[1] * al1 + sum1;
#pragma unroll
            for (int i = 0; i < 8; i++) {
                acc[i][0] *= al0; acc[i][1] *= al0;
                acc[i][2] *= al1; acc[i][3] *= al1;
            }

            uint32_t pha[4][4], pla[4][4];
#pragma unroll
            for (int kf = 0; kf < 4; kf++) {
#pragma unroll
                for (int half = 0; half < 2; half++) {
                    const float* s2 = sf[kf * 2 + half];
                    __nv_bfloat162 h01 = __float22bfloat162_rn(make_float2(s2[0], s2[1]));
                    __nv_bfloat162 h23 = __float22bfloat162_rn(make_float2(s2[2], s2[3]));
                    __nv_bfloat162 l01 = __float22bfloat162_rn(make_float2(
                        s2[0] - __bfloat162float(h01.x), s2[1] - __bfloat162float(h01.y)));
                    __nv_bfloat162 l23 = __float22bfloat162_rn(make_float2(
                        s2[2] - __bfloat162float(h23.x), s2[3] - __bfloat162float(h23.y)));
                    pha[kf][half * 2 + 0] = *(uint32_t*)&h01;
                    pha[kf][half * 2 + 1] = *(uint32_t*)&h23;
                    pla[kf][half * 2 + 0] = *(uint32_t*)&l01;
                    pla[kf][half * 2 + 1] = *(uint32_t*)&l23;
                }
            }

#pragma unroll
            for (int kf = 0; kf < 4; kf++) {
#pragma unroll
                for (int np = 0; np < 4; np++) {
                    uint32_t bd = ((np * 16 + b4_r) * FSTR + kf * 16 + b4_c) * 2;
                    uint32_t vbh[4], vbl[4];
                    ldsm4(vbh[0], vbh[1], vbh[2], vbh[3], sVh + bd);
                    ldsm4(vbl[0], vbl[1], vbl[2], vbl[3], sVl + bd);
                    mma_bf16(acc[np * 2],     pha[kf], vbh);
                    mma_bf16(acc[np * 2],     pha[kf], vbl);
                    mma_bf16(acc[np * 2],     pla[kf], vbh);
                    mma_bf16(acc[np * 2 + 1], pha[kf], vbh + 2);
                    mma_bf16(acc[np * 2 + 1], pha[kf], vbl + 2);
                    mma_bf16(acc[np * 2 + 1], pla[kf], vbh + 2);
                }
            }
        }
        __syncthreads();
    }

    float inv0 = 1.0f / l[0], inv1 = 1.0f / l[1];
#pragma unroll
    for (int nf = 0; nf < 8; nf++) {
        size_t o0 = ((size_t)(b * SS + q0 + warp_m + er) * NH + h) * HD + nf * 8 + ec;
        size_t o1 = ((size_t)(b * SS + q0 + warp_m + er + 8) * NH + h) * HD + nf * 8 + ec;
        float v00 = acc[nf][0] * inv0, v01 = acc[nf][1] * inv0;
        float v10 = acc[nf][2] * inv1, v11 = acc[nf][3] * inv1;
        __nv_bfloat162 h0 = __float22bfloat162_rn(make_float2(v00, v01));
        __nv_bfloat162 h1 = __float22bfloat162_rn(make_float2(v10, v11));
        __nv_bfloat162 l0 = __float22bfloat162_rn(make_float2(
            v00 - __bfloat162float(h0.x), v01 - __bfloat162float(h0.y)));
        __nv_bfloat162 l1 = __float22bfloat162_rn(make_float2(
            v10 - __bfloat162float(h1.x), v11 - __bfloat162float(h1.y)));
        *(uint32_t*)(Oh + o0) = *(uint32_t*)&h0;
        *(uint32_t*)(Oh + o1) = *(uint32_t*)&h1;
        *(uint32_t*)(Ol + o0) = *(uint32_t*)&l0;
        *(uint32_t*)(Ol + o1) = *(uint32_t*)&l1;
    }
}

// ---------------------------------------------------------------------------
extern "C" void kernel_launch(void* const* d_in, const int* in_sizes, int n_in,
                              void* d_out, int out_size)
{
    const float* x    = (const float*)d_in[0];
    const float* cosb = (const float*)d_in[1];
    const float* sinb = (const float*)d_in[2];
    const float* wq   = (const float*)d_in[3];
    const float* wk   = (const float*)d_in[4];
    const float* wv   = (const float*)d_in[5];
    const float* wo   = (const float*)d_in[6];
    float* out = (float*)d_out;

    __nv_bfloat16 *xh, *xl, *oh, *ol;
    __nv_bfloat16 *wqkvh, *wqkvl, *woh, *wol;
    __nv_bfloat16 *qh, *ql, *kh2, *kl2, *vth, *vtl;
    cudaGetSymbolAddress((void**)&xh, g_xh);
    cudaGetSymbolAddress((void**)&xl, g_xl);
    cudaGetSymbolAddress((void**)&oh, g_oh);
    cudaGetSymbolAddress((void**)&ol, g_ol);
    cudaGetSymbolAddress((void**)&wqkvh, g_wqkvh);
    cudaGetSymbolAddress((void**)&wqkvl, g_wqkvl);
    cudaGetSymbolAddress((void**)&woh, g_woh);
    cudaGetSymbolAddress((void**)&wol, g_wol);
    cudaGetSymbolAddress((void**)&qh, g_qh);
    cudaGetSymbolAddress((void**)&ql, g_ql);
    cudaGetSymbolAddress((void**)&kh2, g_kh2);
    cudaGetSymbolAddress((void**)&kl2, g_kl2);
    cudaGetSymbolAddress((void**)&vth, g_vth);
    cudaGetSymbolAddress((void**)&vtl, g_vtl);

    cudaFuncSetAttribute(gemm_bf16x3_kernel,
                         cudaFuncAttributeMaxDynamicSharedMemorySize, GEMM_SMEM);
    cudaFuncSetAttribute(gemm_qkv_kernel,
                         cudaFuncAttributeMaxDynamicSharedMemorySize, GEMM_SMEM);
    cudaFuncSetAttribute(flash_hmma_kernel,
                         cudaFuncAttributeMaxDynamicSharedMemorySize, FLASH_SMEM);

    const int M = BB * SS;  // 4096

    // Split activations; fused weight prep
    {
        int n4 = M * DMODEL / 4;
        split_kernel<<<(n4 + 255) / 256, 256>>>(
            (const float4*)x, (__nv_bfloat162*)xh, (__nv_bfloat162*)xl, n4);
        weight_prep_kernel<<<2560, dim3(32, 8)>>>(
            wq, wk, wv, wo, wqkvh, wqkvl, woh, wol);
    }

    // Fused QKV projection + RoPE/split/V-transpose epilogue
    gemm_qkv_kernel<<<dim3(NQKV / 128, M / 128), 256, GEMM_SMEM>>>(
        xh, xl, wqkvh, wqkvl, cosb, sinb, qh, ql, kh2, kl2, vth, vtl);

    // Causal GQA flash attention (HMMA bf16x3, BN=64, 2-stage, 2 CTAs/SM)
    flash_hmma_kernel<<<dim3(SS / 128, NH, BB), 256, FLASH_SMEM>>>(
        qh, ql, kh2, kl2, vth, vtl, oh, ol);

    // Output projection (HMMA bf16x3)
    gemm_bf16x3_kernel<<<dim3(DMODEL / 128, M / 128), 256, GEMM_SMEM>>>(
        oh, ol, woh, wol, out, M, DMODEL, DMODEL);
}

// round 13
// speedup vs baseline: 1.0577x; 1.0577x over previous
#include <cuda_runtime.h>
#include <cuda_bf16.h>
#include <cstdint>
#include <math.h>

#define BB 2
#define SS 2048
#define DMODEL 1024
#define NH 16
#define NKH 4
#define HD 64
#define NQKV 1536

// ---------------------------------------------------------------------------
// Scratch (device globals: allocation-free)
// ---------------------------------------------------------------------------
__device__ __nv_bfloat16 g_xh[BB * SS * DMODEL];
__device__ __nv_bfloat16 g_xl[BB * SS * DMODEL];
__device__ __nv_bfloat16 g_oh[BB * SS * NH * HD];
__device__ __nv_bfloat16 g_ol[BB * SS * NH * HD];
__device__ __nv_bfloat16 g_wqkvh[NQKV * DMODEL];
__device__ __nv_bfloat16 g_wqkvl[NQKV * DMODEL];
__device__ __nv_bfloat16 g_woh[DMODEL * (NH * HD)];
__device__ __nv_bfloat16 g_wol[DMODEL * (NH * HD)];

__device__ __nv_bfloat16 g_qh[BB * SS * NH * HD];
__device__ __nv_bfloat16 g_ql[BB * SS * NH * HD];
__device__ __nv_bfloat16 g_kh2[BB * SS * NKH * HD];
__device__ __nv_bfloat16 g_kl2[BB * SS * NKH * HD];
__device__ __nv_bfloat16 g_vth[BB * NKH * HD * SS];   // [b][kh][d][s]
__device__ __nv_bfloat16 g_vtl[BB * NKH * HD * SS];

// ---------------------------------------------------------------------------
// Warp-level MMA helpers
// ---------------------------------------------------------------------------
__device__ __forceinline__ uint32_t smem_u32(const void* p) {
    uint32_t a;
    asm("{ .reg .u64 t; cvta.to.shared.u64 t, %1; cvt.u32.u64 %0, t; }"
        : "=r"(a) : "l"(p));
    return a;
}

__device__ __forceinline__ void ldsm4(uint32_t& r0, uint32_t& r1,
                                      uint32_t& r2, uint32_t& r3, uint32_t a) {
    asm volatile("ldmatrix.sync.aligned.m8n8.x4.shared.b16 {%0,%1,%2,%3}, [%4];"
                 : "=r"(r0), "=r"(r1), "=r"(r2), "=r"(r3) : "r"(a));
}

__device__ __forceinline__ void mma_bf16(float* c, const uint32_t* a,
                                         const uint32_t* b) {
    asm volatile(
        "mma.sync.aligned.m16n8k16.row.col.f32.bf16.bf16.f32 "
        "{%0,%1,%2,%3}, {%4,%5,%6,%7}, {%8,%9}, {%0,%1,%2,%3};"
        : "+f"(c[0]), "+f"(c[1]), "+f"(c[2]), "+f"(c[3])
        : "r"(a[0]), "r"(a[1]), "r"(a[2]), "r"(a[3]), "r"(b[0]), "r"(b[1]));
}

#define CP_ASYNC16(sa, ga) \
    asm volatile("cp.async.cg.shared.global [%0], [%1], 16;" \
                 :: "r"(sa), "l"(ga))
#define CP_COMMIT() asm volatile("cp.async.commit_group;")
#define CP_WAIT(N)  asm volatile("cp.async.wait_group %0;" :: "n"(N))

// ---------------------------------------------------------------------------
// GEMM common config
// ---------------------------------------------------------------------------
#define BK 32
#define GSTRIDE 40
#define GTILE_B (128 * GSTRIDE * 2)
#define GOFF(t, st) (((st) * 4 + (t)) * GTILE_B)
#define GEMM_SMEM (8 * GTILE_B)
#define TSTR 132   // fp32 epilogue tile stride

#define GEMM_MAINLOOP(OUT_ACC)                                                \
    float OUT_ACC[4][4][4];                                                   \
    _Pragma("unroll")                                                         \
    for (int i = 0; i < 4; i++)                                               \
        _Pragma("unroll")                                                     \
        for (int j = 0; j < 4; j++)                                           \
            _Pragma("unroll")                                                 \
            for (int r = 0; r < 4; r++) OUT_ACC[i][j][r] = 0.0f;              \
    const int nchunk = K / BK;                                                \
    load_stage(0, 0);                                                         \
    const int a_r = lane & 15;                                                \
    const int a_c = (lane >> 4) * 8;                                          \
    const int g4 = lane >> 3;                                                 \
    const int b4_r = (g4 >> 1) * 8 + (lane & 7);                              \
    const int b4_c = (g4 & 1) * 8;                                            \
    for (int c = 0; c < nchunk; c++) {                                        \
        const int st = c & 1;                                                 \
        if (c + 1 < nchunk) { load_stage(c + 1, st ^ 1); CP_WAIT(1); }        \
        else { CP_WAIT(0); }                                                  \
        __syncthreads();                                                      \
        const uint32_t sAh = sb + GOFF(0, st);                                \
        const uint32_t sAl = sb + GOFF(1, st);                                \
        const uint32_t sBh = sb + GOFF(2, st);                                \
        const uint32_t sBl = sb + GOFF(3, st);                                \
        _Pragma("unroll")                                                     \
        for (int kf = 0; kf < 2; kf++) {                                      \
            const int kc = kf * 16;                                           \
            uint32_t ah[4][4], al[4][4], bh[4][2], bl[4][2];                  \
            _Pragma("unroll")                                                 \
            for (int mf = 0; mf < 4; mf++) {                                  \
                uint32_t ad = ((warp_m + mf * 16 + a_r) * GSTRIDE + kc + a_c) * 2; \
                ldsm4(ah[mf][0], ah[mf][1], ah[mf][2], ah[mf][3], sAh + ad);  \
            }                                                                 \
            _Pragma("unroll")                                                 \
            for (int np = 0; np < 2; np++) {                                  \
                uint32_t bd = ((warp_n + np * 16 + b4_r) * GSTRIDE + kc + b4_c) * 2; \
                ldsm4(bh[np * 2][0], bh[np * 2][1],                           \
                      bh[np * 2 + 1][0], bh[np * 2 + 1][1], sBh + bd);        \
                ldsm4(bl[np * 2][0], bl[np * 2][1],                           \
                      bl[np * 2 + 1][0], bl[np * 2 + 1][1], sBl + bd);        \
            }                                                                 \
            _Pragma("unroll")                                                 \
            for (int mf = 0; mf < 4; mf++)                                    \
                _Pragma("unroll")                                             \
                for (int nf = 0; nf < 4; nf++) {                              \
                    mma_bf16(OUT_ACC[mf][nf], ah[mf], bh[nf]);                \
                    mma_bf16(OUT_ACC[mf][nf], ah[mf], bl[nf]);                \
                }                                                             \
            _Pragma("unroll")                                                 \
            for (int mf = 0; mf < 4; mf++) {                                  \
                uint32_t ad = ((warp_m + mf * 16 + a_r) * GSTRIDE + kc + a_c) * 2; \
                ldsm4(al[mf][0], al[mf][1], al[mf][2], al[mf][3], sAl + ad);  \
            }                                                                 \
            _Pragma("unroll")                                                 \
            for (int mf = 0; mf < 4; mf++)                                    \
                _Pragma("unroll")                                             \
                for (int nf = 0; nf < 4; nf++)                                \
                    mma_bf16(OUT_ACC[mf][nf], al[mf], bh[nf]);                \
        }                                                                     \
        __syncthreads();                                                      \
    }

// ---------------------------------------------------------------------------
// bf16x3 HMMA GEMM with plain fp32 C output (out-projection).
// ---------------------------------------------------------------------------
__global__ __launch_bounds__(256, 2) void gemm_bf16x3_kernel(
    const __nv_bfloat16* __restrict__ Ah, const __nv_bfloat16* __restrict__ Al,
    const __nv_bfloat16* __restrict__ Bh, const __nv_bfloat16* __restrict__ Bl,
    float* __restrict__ C, int M, int N, int K)
{
    extern __shared__ __align__(128) char smem[];
    const uint32_t sb = smem_u32(smem);
    const int tid = threadIdx.x;
    const int wid = tid >> 5;
    const int lane = tid & 31;
    const int bm = blockIdx.y * 128;
    const int bn = blockIdx.x * 128;
    const int warp_m = (wid >> 2) * 64;
    const int warp_n = (wid & 3) * 32;

    const __nv_bfloat16* gp[4] = {
        Ah + (size_t)bm * K, Al + (size_t)bm * K,
        Bh + (size_t)bn * K, Bl + (size_t)bn * K };

    const int lrow0 = tid >> 2;
    const int lq = tid & 3;

    auto load_stage = [&](int c, int st) {
#pragma unroll
        for (int t = 0; t < 4; t++) {
            const __nv_bfloat16* P = gp[t] + (size_t)c * BK;
#pragma unroll
            for (int it = 0; it < 2; it++) {
                int row = lrow0 + it * 64;
                uint32_t sa = sb + GOFF(t, st) + (row * GSTRIDE + lq * 8) * 2;
                CP_ASYNC16(sa, P + (size_t)row * K + lq * 8);
            }
        }
        CP_COMMIT();
    };

    GEMM_MAINLOOP(acc)

    const int er = lane >> 2;
    const int ec = (lane & 3) * 2;
#pragma unroll
    for (int mf = 0; mf < 4; mf++) {
#pragma unroll
        for (int nf = 0; nf < 4; nf++) {
            float* base = C + (size_t)(bm + warp_m + mf * 16 + er) * N
                            + bn + warp_n + nf * 8 + ec;
            *(float2*)base = make_float2(acc[mf][nf][0], acc[mf][nf][1]);
            *(float2*)(base + 8 * N) = make_float2(acc[mf][nf][2], acc[mf][nf][3]);
        }
    }
}

// ---------------------------------------------------------------------------
// QKV GEMM with fused RoPE+split / V-transpose+split epilogue.
// Q is scaled by 0.125*log2(e) so flash can use exp2.
// ---------------------------------------------------------------------------
__global__ __launch_bounds__(256, 2) void gemm_qkv_kernel(
    const __nv_bfloat16* __restrict__ Ah, const __nv_bfloat16* __restrict__ Al,
    const __nv_bfloat16* __restrict__ Bh, const __nv_bfloat16* __restrict__ Bl,
    const float* __restrict__ cosb, const float* __restrict__ sinb,
    __nv_bfloat16* __restrict__ qh, __nv_bfloat16* __restrict__ ql,
    __nv_bfloat16* __restrict__ khp, __nv_bfloat16* __restrict__ klp,
    __nv_bfloat16* __restrict__ vh, __nv_bfloat16* __restrict__ vl)
{
    extern __shared__ __align__(128) char smem[];
    const uint32_t sb = smem_u32(smem);
    const int tid = threadIdx.x;
    const int wid = tid >> 5;
    const int lane = tid & 31;
    const int bm = blockIdx.y * 128;
    const int bn = blockIdx.x * 128;
    const int warp_m = (wid >> 2) * 64;
    const int warp_n = (wid & 3) * 32;
    const int K = DMODEL;

    const __nv_bfloat16* gp[4] = {
        Ah + (size_t)bm * K, Al + (size_t)bm * K,
        Bh + (size_t)bn * K, Bl + (size_t)bn * K };

    const int lrow0 = tid >> 2;
    const int lq = tid & 3;

    auto load_stage = [&](int c, int st) {
#pragma unroll
        for (int t = 0; t < 4; t++) {
            const __nv_bfloat16* P = gp[t] + (size_t)c * BK;
#pragma unroll
            for (int it = 0; it < 2; it++) {
                int row = lrow0 + it * 64;
                uint32_t sa = sb + GOFF(t, st) + (row * GSTRIDE + lq * 8) * 2;
                CP_ASYNC16(sa, P + (size_t)row * K + lq * 8);
            }
        }
        CP_COMMIT();
    };

    GEMM_MAINLOOP(acc)

    float* Ts = (float*)smem;
    const int er = lane >> 2;
    const int ec = (lane & 3) * 2;
#pragma unroll
    for (int mf = 0; mf < 4; mf++) {
#pragma unroll
        for (int nf = 0; nf < 4; nf++) {
            int r = warp_m + mf * 16 + er;
            int c = warp_n + nf * 8 + ec;
            *(float2*)&Ts[r * TSTR + c] = make_float2(acc[mf][nf][0], acc[mf][nf][1]);
            *(float2*)&Ts[(r + 8) * TSTR + c] = make_float2(acc[mf][nf][2], acc[mf][nf][3]);
        }
    }
    __syncthreads();

    if (bn < 1280) {
        const bool isq = (bn < 1024);
        const float scl = isq ? 0.125f * 1.4426950408889634f : 1.0f;
        __nv_bfloat16* th = isq ? qh : khp;
        __nv_bfloat16* tl = isq ? ql : klp;
        const int nheads = isq ? NH : NKH;
        const int h0 = isq ? (bn >> 6) : ((bn - 1024) >> 6);

#pragma unroll
        for (int it = 0; it < 8; it++) {
            int idx = tid + it * 256;
            int d0 = (idx & 7) * 4;
            int hh = (idx >> 3) & 1;
            int row = idx >> 4;
            int bs = bm + row;
            int s = bs & (SS - 1);

            const float* tr = &Ts[row * TSTR + hh * 64];
            float4 v0 = *(const float4*)(tr + d0);
            float4 v1 = *(const float4*)(tr + d0 + 32);
            float4 c0 = *(const float4*)(cosb + s * HD + d0);
            float4 c1 = *(const float4*)(cosb + s * HD + d0 + 32);
            float4 s0v = *(const float4*)(sinb + s * HD + d0);
            float4 s1v = *(const float4*)(sinb + s * HD + d0 + 32);

            float r0x = (v0.x * c0.x - v1.x * s0v.x) * scl;
            float r0y = (v0.y * c0.y - v1.y * s0v.y) * scl;
            float r0z = (v0.z * c0.z - v1.z * s0v.z) * scl;
            float r0w = (v0.w * c0.w - v1.w * s0v.w) * scl;
            float r1x = (v1.x * c1.x + v0.x * s1v.x) * scl;
            float r1y = (v1.y * c1.y + v0.y * s1v.y) * scl;
            float r1z = (v1.z * c1.z + v0.z * s1v.z) * scl;
            float r1w = (v1.w * c1.w + v0.w * s1v.w) * scl;

            size_t base = ((size_t)bs * nheads + h0 + hh) * HD;

            __nv_bfloat162 h0a = __float22bfloat162_rn(make_float2(r0x, r0y));
            __nv_bfloat162 h0b = __float22bfloat162_rn(make_float2(r0z, r0w));
            __nv_bfloat162 h1a = __float22bfloat162_rn(make_float2(r1x, r1y));
            __nv_bfloat162 h1b = __float22bfloat162_rn(make_float2(r1z, r1w));
            *(uint2*)(th + base + d0)      = make_uint2(*(uint32_t*)&h0a, *(uint32_t*)&h0b);
            *(uint2*)(th + base + d0 + 32) = make_uint2(*(uint32_t*)&h1a, *(uint32_t*)&h1b);

            __nv_bfloat162 l0a = __float22bfloat162_rn(make_float2(
                r0x - __bfloat162float(h0a.x), r0y - __bfloat162float(h0a.y)));
            __nv_bfloat162 l0b = __float22bfloat162_rn(make_float2(
                r0z - __bfloat162float(h0b.x), r0w - __bfloat162float(h0b.y)));
            __nv_bfloat162 l1a = __float22bfloat162_rn(make_float2(
                r1x - __bfloat162float(h1a.x), r1y - __bfloat162float(h1a.y)));
            __nv_bfloat162 l1b = __float22bfloat162_rn(make_float2(
                r1z - __bfloat162float(h1b.x), r1w - __bfloat162float(h1b.y)));
            *(uint2*)(tl + base + d0)      = make_uint2(*(uint32_t*)&l0a, *(uint32_t*)&l0b);
            *(uint2*)(tl + base + d0 + 32) = make_uint2(*(uint32_t*)&l1a, *(uint32_t*)&l1b);
        }
    } else {
        const int c = tid & 127;
        const int sh = tid >> 7;
        const int khead = ((bn - 1280) >> 6) + (c >> 6);
        const int d = c & 63;
        const int b = bm >> 11;
        const int s0 = (bm & (SS - 1)) + sh * 64;
        size_t base = ((size_t)(b * NKH + khead) * HD + d) * SS + s0;

#pragma unroll 4
        for (int s4 = 0; s4 < 64; s4 += 4) {
            float v0 = Ts[(sh * 64 + s4 + 0) * TSTR + c];
            float v1 = Ts[(sh * 64 + s4 + 1) * TSTR + c];
            float v2 = Ts[(sh * 64 + s4 + 2) * TSTR + c];
            float v3 = Ts[(sh * 64 + s4 + 3) * TSTR + c];
            __nv_bfloat162 p01 = __float22bfloat162_rn(make_float2(v0, v1));
            __nv_bfloat162 p23 = __float22bfloat162_rn(make_float2(v2, v3));
            *(uint2*)(vh + base + s4) = make_uint2(*(uint32_t*)&p01, *(uint32_t*)&p23);
            __nv_bfloat162 q01 = __float22bfloat162_rn(make_float2(
                v0 - __bfloat162float(p01.x), v1 - __bfloat162float(p01.y)));
            __nv_bfloat162 q23 = __float22bfloat162_rn(make_float2(
                v2 - __bfloat162float(p23.x), v3 - __bfloat162float(p23.y)));
            *(uint2*)(vl + base + s4) = make_uint2(*(uint32_t*)&q01, *(uint32_t*)&q23);
        }
    }
}

// ---------------------------------------------------------------------------
// Elementwise split fp32 -> (hi, lo) bf16.
// ---------------------------------------------------------------------------
__global__ void split_kernel(const float4* __restrict__ src,
                             __nv_bfloat162* __restrict__ dh,
                             __nv_bfloat162* __restrict__ dl, int n4)
{
    int i = blockIdx.x * blockDim.x + threadIdx.x;
    if (i >= n4) return;
    float4 v = src[i];
    __nv_bfloat16 h0 = __float2bfloat16(v.x);
    __nv_bfloat16 h1 = __float2bfloat16(v.y);
    __nv_bfloat16 h2 = __float2bfloat16(v.z);
    __nv_bfloat16 h3 = __float2bfloat16(v.w);
    dh[2 * i]     = __nv_bfloat162(h0, h1);
    dh[2 * i + 1] = __nv_bfloat162(h2, h3);
    __nv_bfloat16 l0 = __float2bfloat16(v.x - __bfloat162float(h0));
    __nv_bfloat16 l1 = __float2bfloat16(v.y - __bfloat162float(h1));
    __nv_bfloat16 l2 = __float2bfloat16(v.z - __bfloat162float(h2));
    __nv_bfloat16 l3 = __float2bfloat16(v.w - __bfloat162float(h3));
    dl[2 * i]     = __nv_bfloat162(l0, l1);
    dl[2 * i + 1] = __nv_bfloat162(l2, l3);
}

// ---------------------------------------------------------------------------
// Fused weight prep: all 4 transpose+splits in one launch.
// ---------------------------------------------------------------------------
__global__ void weight_prep_kernel(
    const float* __restrict__ wq, const float* __restrict__ wk,
    const float* __restrict__ wv, const float* __restrict__ wo,
    __nv_bfloat16* __restrict__ wqkvh, __nv_bfloat16* __restrict__ wqkvl,
    __nv_bfloat16* __restrict__ woh, __nv_bfloat16* __restrict__ wol)
{
    __shared__ float t[32][33];
    const int tile = blockIdx.x;
    const float* src;
    __nv_bfloat16 *dh, *dl;
    int N, tloc;
    if (tile < 1024)      { src = wq; dh = wqkvh;                  dl = wqkvl;                  N = 1024; tloc = tile; }
    else if (tile < 1280) { src = wk; dh = wqkvh + 1024 * DMODEL;  dl = wqkvl + 1024 * DMODEL;  N = 256;  tloc = tile - 1024; }
    else if (tile < 1536) { src = wv; dh = wqkvh + 1280 * DMODEL;  dl = wqkvl + 1280 * DMODEL;  N = 256;  tloc = tile - 1280; }
    else                  { src = wo; dh = woh;                    dl = wol;                    N = 1024; tloc = tile - 1536; }
    const int nx = N >> 5;
    const int K = 1024;
    const int n0 = (tloc % nx) * 32;
    const int k0 = (tloc / nx) * 32;
    const int tx = threadIdx.x, ty = threadIdx.y;
#pragma unroll
    for (int i = 0; i < 32; i += 8)
        t[ty + i][tx] = src[(size_t)(k0 + ty + i) * N + n0 + tx];
    __syncthreads();
#pragma unroll
    for (int i = 0; i < 32; i += 8) {
        float v = t[tx][ty + i];
        __nv_bfloat16 h = __float2bfloat16(v);
        float rres = v - __bfloat162float(h);
        size_t o = (size_t)(n0 + ty + i) * K + k0 + tx;
        dh[o] = h;
        dl[o] = __float2bfloat16(rres);
    }
}

// ---------------------------------------------------------------------------
// HMMA bf16x3 flash attention, causal, GQA.
// BLOCK_M=128 (8 warps), BLOCK_N=64; 3-stage pipeline (1 CTA/SM); exp2; LPT.
// Q fragments hoisted into registers across the whole KV loop.
// ---------------------------------------------------------------------------
#define FSTR 72
#define FTILE64 (64 * FSTR * 2)
#define FQ_TILE (128 * FSTR * 2)
#define FQ_H 0
#define FQ_L FQ_TILE
#define FSTG(st) (2 * FQ_TILE + (st) * 4 * FTILE64)
#define FLASH_SMEM (2 * FQ_TILE + 3 * 4 * FTILE64)   // 147456 B

__global__ __launch_bounds__(256) void flash_hmma_kernel(
    const __nv_bfloat16* __restrict__ Qh, const __nv_bfloat16* __restrict__ Ql,
    const __nv_bfloat16* __restrict__ Kh, const __nv_bfloat16* __restrict__ Kl,
    const __nv_bfloat16* __restrict__ Vth, const __nv_bfloat16* __restrict__ Vtl,
    __nv_bfloat16* __restrict__ Oh, __nv_bfloat16* __restrict__ Ol)
{
    extern __shared__ __align__(128) char smem[];
    const uint32_t sb = smem_u32(smem);
    const int tid = threadIdx.x;
    const int wid = tid >> 5;
    const int lane = tid & 31;
    const int qt = gridDim.x - 1 - blockIdx.x;   // LPT
    const int h  = blockIdx.y;
    const int b  = blockIdx.z;
    const int q0 = qt * 128;
    const int khead = h >> 2;
    const int warp_m = wid * 16;

    const int er = lane >> 2;
    const int ec = (lane & 3) * 2;
    const int a_r = lane & 15;
    const int a_c = (lane >> 4) * 8;
    const int g4 = lane >> 3;
    const int b4_r = (g4 >> 1) * 8 + (lane & 7);
    const int b4_c = (g4 & 1) * 8;

    const __nv_bfloat16* qh_g = Qh + ((size_t)(b * SS + q0) * NH + h) * HD;
    const __nv_bfloat16* ql_g = Ql + ((size_t)(b * SS + q0) * NH + h) * HD;
    const __nv_bfloat16* kh_g = Kh + ((size_t)b * SS * NKH + khead) * HD;
    const __nv_bfloat16* kl_g = Kl + ((size_t)b * SS * NKH + khead) * HD;
    const __nv_bfloat16* vth_g = Vth + (size_t)(b * NKH + khead) * HD * SS;
    const __nv_bfloat16* vtl_g = Vtl + (size_t)(b * NKH + khead) * HD * SS;

    auto load_tile64 = [&](const __nv_bfloat16* g, size_t rstride, uint32_t sofs) {
#pragma unroll
        for (int it = 0; it < 2; it++) {
            int ch = tid + it * 256;
            int r = ch >> 3;
            int q8 = ch & 7;
            CP_ASYNC16(sb + sofs + (r * FSTR + q8 * 8) * 2,
                       g + (size_t)r * rstride + q8 * 8);
        }
    };
    auto load_q = [&](const __nv_bfloat16* g, uint32_t sofs) {
#pragma unroll
        for (int it = 0; it < 4; it++) {
            int ch = tid + it * 256;
            int r = ch >> 3;
            int q8 = ch & 7;
            CP_ASYNC16(sb + sofs + (r * FSTR + q8 * 8) * 2,
                       g + (size_t)r * (NH * HD) + q8 * 8);
        }
    };
    auto load_stage = [&](int kt, int st) {
        const int kn = kt * 64;
        load_tile64(kh_g + (size_t)kn * NKH * HD, NKH * HD, FSTG(st) + 0 * FTILE64);
        load_tile64(kl_g + (size_t)kn * NKH * HD, NKH * HD, FSTG(st) + 1 * FTILE64);
        load_tile64(vth_g + kn, SS, FSTG(st) + 2 * FTILE64);
        load_tile64(vtl_g + kn, SS, FSTG(st) + 3 * FTILE64);
        CP_COMMIT();
    };

    const int kt_end = 2 * qt + 1;

    // Q as its own cp.async group, then stages 0 and 1.
    load_q(qh_g, FQ_H);
    load_q(ql_g, FQ_L);
    CP_COMMIT();
    load_stage(0, 0);
    if (kt_end >= 1) { load_stage(1, 1); CP_WAIT(2); }
    else             { CP_WAIT(1); }
    __syncthreads();

    // Preload Q fragments into registers (live across the whole loop).
    uint32_t qah[4][4], qal[4][4];
#pragma unroll
    for (int kf = 0; kf < 4; kf++) {
        uint32_t ad = ((warp_m + a_r) * FSTR + kf * 16 + a_c) * 2;
        ldsm4(qah[kf][0], qah[kf][1], qah[kf][2], qah[kf][3], sb + FQ_H + ad);
        ldsm4(qal[kf][0], qal[kf][1], qal[kf][2], qal[kf][3], sb + FQ_L + ad);
    }

    float m[2] = {-1e30f, -1e30f};
    float l[2] = {0.0f, 0.0f};
    float acc[8][4];
#pragma unroll
    for (int i = 0; i < 8; i++)
#pragma unroll
        for (int r = 0; r < 4; r++) acc[i][r] = 0.0f;

    for (int kt = 0; kt <= kt_end; kt++) {
        const int st = kt % 3;
        if (kt + 2 <= kt_end) {
            load_stage(kt + 2, (kt + 2) % 3);
            CP_WAIT(2);
        } else if (kt + 1 <= kt_end) {
            CP_WAIT(1);
        } else {
            CP_WAIT(0);
        }
        __syncthreads();

        const int row_lo = q0 + warp_m;
        const bool any  = (kt * 64     <= row_lo + 15);
        const bool full = (kt * 64 + 63 <= row_lo);

        if (any) {
            const uint32_t sKh = sb + FSTG(st) + 0 * FTILE64;
            const uint32_t sKl = sb + FSTG(st) + 1 * FTILE64;
            const uint32_t sVh = sb + FSTG(st) + 2 * FTILE64;
            const uint32_t sVl = sb + FSTG(st) + 3 * FTILE64;

            float sf[8][4];
#pragma unroll
            for (int nf = 0; nf < 8; nf++)
#pragma unroll
                for (int r = 0; r < 4; r++) sf[nf][r] = 0.0f;

#pragma unroll
            for (int kf = 0; kf < 4; kf++) {
                const int kc = kf * 16;
#pragma unroll
                for (int np = 0; np < 4; np++) {
                    uint32_t bd = ((np * 16 + b4_r) * FSTR + kc + b4_c) * 2;
                    uint32_t kbh[4], kbl[4];
                    ldsm4(kbh[0], kbh[1], kbh[2], kbh[3], sKh + bd);
                    ldsm4(kbl[0], kbl[1], kbl[2], kbl[3], sKl + bd);
                    mma_bf16(sf[np * 2],     qah[kf], kbh);
                    mma_bf16(sf[np * 2],     qah[kf], kbl);
                    mma_bf16(sf[np * 2],     qal[kf], kbh);
                    mma_bf16(sf[np * 2 + 1], qah[kf], kbh + 2);
                    mma_bf16(sf[np * 2 + 1], qah[kf], kbl + 2);
                    mma_bf16(sf[np * 2 + 1], qal[kf], kbh + 2);
                }
            }

            // ---- mask (scale and log2e pre-folded into Q) ----
            if (!full) {
                const int i0 = row_lo + er;
#pragma unroll
                for (int nf = 0; nf < 8; nf++) {
                    int j0 = kt * 64 + nf * 8 + ec;
                    if (j0     > i0)     sf[nf][0] = -1e30f;
                    if (j0 + 1 > i0)     sf[nf][1] = -1e30f;
                    if (j0     > i0 + 8) sf[nf][2] = -1e30f;
                    if (j0 + 1 > i0 + 8) sf[nf][3] = -1e30f;
                }
            }

            float rmax0 = -1e30f, rmax1 = -1e30f;
#pragma unroll
            for (int nf = 0; nf < 8; nf++) {
                rmax0 = fmaxf(rmax0, fmaxf(sf[nf][0], sf[nf][1]));
                rmax1 = fmaxf(rmax1, fmaxf(sf[nf][2], sf[nf][3]));
            }
            rmax0 = fmaxf(rmax0, __shfl_xor_sync(0xffffffffu, rmax0, 1));
            rmax0 = fmaxf(rmax0, __shfl_xor_sync(0xffffffffu, rmax0, 2));
            rmax1 = fmaxf(rmax1, __shfl_xor_sync(0xffffffffu, rmax1, 1));
            rmax1 = fmaxf(rmax1, __shfl_xor_sync(0xffffffffu, rmax1, 2));

            float nm0 = fmaxf(m[0], rmax0), nm1 = fmaxf(m[1], rmax1);
            float al0 = exp2f(m[0] - nm0), al1 = exp2f(m[1] - nm1);
            m[0] = nm0; m[1] = nm1;

            float sum0 = 0.0f, sum1 = 0.0f;
#pragma unroll
            for (int nf = 0; nf < 8; nf++) {
                sf[nf][0] = exp2f(sf[nf][0] - nm0);
                sf[nf][1] = exp2f(sf[nf][1] - nm0);
                sf[nf][2] = exp2f(sf[nf][2] - nm1);
                sf[nf][3] = exp2f(sf[nf][3] - nm1);
                sum0 += sf[nf][0] + sf[nf][1];
                sum1 += sf[nf][2] + sf[nf][3];
            }
            sum0 += __shfl_xor_sync(0xffffffffu, sum0, 1);
            sum0 += __shfl_xor_sync(0xffffffffu, sum0, 2);
            sum1 += __shfl_xor_sync(0xffffffffu, sum1, 1);
            sum1 += __shfl_xor_sync(0xffffffffu, sum1, 2);
            l[0] = l[0] * al0 + sum0;
            l[1] = l[1] * al1 + sum1;
#pragma unroll
            for (int i = 0; i < 8; i++) {
                acc[i][0] *= al0; acc[i][1] *= al0;
                acc[i][2] *= al1; acc[i][3] *= al1;
            }

            // ---- split P to bf16 hi/lo (3-term PV: required for accuracy) ----
            uint32_t pha[4][4], pla[4][4];
#pragma unroll
            for (int kf = 0; kf < 4; kf++) {
#pragma unroll
                for (int half = 0; half < 2; half++) {
                    const float* s2 = sf[kf * 2 + half];
                    __nv_bfloat162 h01 = __float22bfloat162_rn(make_float2(s2[0], s2[1]));
                    __nv_bfloat162 h23 = __float22bfloat162_rn(make_float2(s2[2], s2[3]));
                    __nv_bfloat162 l01 = __float22bfloat162_rn(make_float2(
                        s2[0] - __bfloat162float(h01.x), s2[1] - __bfloat162float(h01.y)));
                    __nv_bfloat162 l23 = __float22bfloat162_rn(make_float2(
                        s2[2] - __bfloat162float(h23.x), s2[3] - __bfloat162float(h23.y)));
                    pha[kf][half * 2 + 0] = *(uint32_t*)&h01;
                    pha[kf][half * 2 + 1] = *(uint32_t*)&h23;
                    pla[kf][half * 2 + 0] = *(uint32_t*)&l01;
                    pla[kf][half * 2 + 1] = *(uint32_t*)&l23;
                }
            }

#pragma unroll
            for (int kf = 0; kf < 4; kf++) {
#pragma unroll
                for (int np = 0; np < 4; np++) {
                    uint32_t bd = ((np * 16 + b4_r) * FSTR + kf * 16 + b4_c) * 2;
                    uint32_t vbh[4], vbl[4];
                    ldsm4(vbh[0], vbh[1], vbh[2], vbh[3], sVh + bd);
                    ldsm4(vbl[0], vbl[1], vbl[2], vbl[3], sVl + bd);
                    mma_bf16(acc[np * 2],     pha[kf], vbh);
                    mma_bf16(acc[np * 2],     pha[kf], vbl);
                    mma_bf16(acc[np * 2],     pla[kf], vbh);
                    mma_bf16(acc[np * 2 + 1], pha[kf], vbh + 2);
                    mma_bf16(acc[np * 2 + 1], pha[kf], vbl + 2);
                    mma_bf16(acc[np * 2 + 1], pla[kf], vbh + 2);
                }
            }
        }
        __syncthreads();
    }

    float inv0 = 1.0f / l[0], inv1 = 1.0f / l[1];
#pragma unroll
    for (int nf = 0; nf < 8; nf++) {
        size_t o0 = ((size_t)(b * SS + q0 + warp_m + er) * NH + h) * HD + nf * 8 + ec;
        size_t o1 = ((size_t)(b * SS + q0 + warp_m + er + 8) * NH + h) * HD + nf * 8 + ec;
        float v00 = acc[nf][0] * inv0, v01 = acc[nf][1] * inv0;
        float v10 = acc[nf][2] * inv1, v11 = acc[nf][3] * inv1;
        __nv_bfloat162 h0 = __float22bfloat162_rn(make_float2(v00, v01));
        __nv_bfloat162 h1 = __float22bfloat162_rn(make_float2(v10, v11));
        __nv_bfloat162 l0 = __float22bfloat162_rn(make_float2(
            v00 - __bfloat162float(h0.x), v01 - __bfloat162float(h0.y)));
        __nv_bfloat162 l1 = __float22bfloat162_rn(make_float2(
            v10 - __bfloat162float(h1.x), v11 - __bfloat162float(h1.y)));
        *(uint32_t*)(Oh + o0) = *(uint32_t*)&h0;
        *(uint32_t*)(Oh + o1) = *(uint32_t*)&h1;
        *(uint32_t*)(Ol + o0) = *(uint32_t*)&l0;
        *(uint32_t*)(Ol + o1) = *(uint32_t*)&l1;
    }
}

// ---------------------------------------------------------------------------
extern "C" void kernel_launch(void* const* d_in, const int* in_sizes, int n_in,
                              void* d_out, int out_size)
{
    const float* x    = (const float*)d_in[0];
    const float* cosb = (const float*)d_in[1];
    const float* sinb = (const float*)d_in[2];
    const float* wq   = (const float*)d_in[3];
    const float* wk   = (const float*)d_in[4];
    const float* wv   = (const float*)d_in[5];
    const float* wo   = (const float*)d_in[6];
    float* out = (float*)d_out;

    __nv_bfloat16 *xh, *xl, *oh, *ol;
    __nv_bfloat16 *wqkvh, *wqkvl, *woh, *wol;
    __nv_bfloat16 *qh, *ql, *kh2, *kl2, *vth, *vtl;
    cudaGetSymbolAddress((void**)&xh, g_xh);
    cudaGetSymbolAddress((void**)&xl, g_xl);
    cudaGetSymbolAddress((void**)&oh, g_oh);
    cudaGetSymbolAddress((void**)&ol, g_ol);
    cudaGetSymbolAddress((void**)&wqkvh, g_wqkvh);
    cudaGetSymbolAddress((void**)&wqkvl, g_wqkvl);
    cudaGetSymbolAddress((void**)&woh, g_woh);
    cudaGetSymbolAddress((void**)&wol, g_wol);
    cudaGetSymbolAddress((void**)&qh, g_qh);
    cudaGetSymbolAddress((void**)&ql, g_ql);
    cudaGetSymbolAddress((void**)&kh2, g_kh2);
    cudaGetSymbolAddress((void**)&kl2, g_kl2);
    cudaGetSymbolAddress((void**)&vth, g_vth);
    cudaGetSymbolAddress((void**)&vtl, g_vtl);

    cudaFuncSetAttribute(gemm_bf16x3_kernel,
                         cudaFuncAttributeMaxDynamicSharedMemorySize, GEMM_SMEM);
    cudaFuncSetAttribute(gemm_qkv_kernel,
                         cudaFuncAttributeMaxDynamicSharedMemorySize, GEMM_SMEM);
    cudaFuncSetAttribute(flash_hmma_kernel,
                         cudaFuncAttributeMaxDynamicSharedMemorySize, FLASH_SMEM);

    const int M = BB * SS;  // 4096

    // Split activations; fused weight prep
    {
        int n4 = M * DMODEL / 4;
        split_kernel<<<(n4 + 255) / 256, 256>>>(
            (const float4*)x, (__nv_bfloat162*)xh, (__nv_bfloat162*)xl, n4);
        weight_prep_kernel<<<2560, dim3(32, 8)>>>(
            wq, wk, wv, wo, wqkvh, wqkvl, woh, wol);
    }

    // Fused QKV projection + RoPE/split/V-transpose epilogue
    gemm_qkv_kernel<<<dim3(NQKV / 128, M / 128), 256, GEMM_SMEM>>>(
        xh, xl, wqkvh, wqkvl, cosb, sinb, qh, ql, kh2, kl2, vth, vtl);

    // Causal GQA flash attention (3-stage, 1 CTA/SM, Q in registers)
    flash_hmma_kernel<<<dim3(SS / 128, NH, BB), 256, FLASH_SMEM>>>(
        qh, ql, kh2, kl2, vth, vtl, oh, ol);

    // Output projection (HMMA bf16x3)
    gemm_bf16x3_kernel<<<dim3(DMODEL / 128, M / 128), 256, GEMM_SMEM>>>(
        oh, ol, woh, wol, out, M, DMODEL, DMODEL);
}

// round 14
// speedup vs baseline: 1.1272x; 1.0657x over previous
#include <cuda_runtime.h>
#include <cuda_bf16.h>
#include <cuda_fp16.h>
#include <cstdint>
#include <math.h>

#define BB 2
#define SS 2048
#define DMODEL 1024
#define NH 16
#define NKH 4
#define HD 64
#define NQKV 1536

// ---------------------------------------------------------------------------
// Scratch (device globals: allocation-free)
// ---------------------------------------------------------------------------
__device__ __nv_bfloat16 g_xh[BB * SS * DMODEL];
__device__ __nv_bfloat16 g_xl[BB * SS * DMODEL];
__device__ __nv_bfloat16 g_oh[BB * SS * NH * HD];
__device__ __nv_bfloat16 g_ol[BB * SS * NH * HD];
__device__ __nv_bfloat16 g_wqkvh[NQKV * DMODEL];
__device__ __nv_bfloat16 g_wqkvl[NQKV * DMODEL];
__device__ __nv_bfloat16 g_woh[DMODEL * (NH * HD)];
__device__ __nv_bfloat16 g_wol[DMODEL * (NH * HD)];

__device__ __nv_bfloat16 g_qh[BB * SS * NH * HD];
__device__ __nv_bfloat16 g_ql[BB * SS * NH * HD];
__device__ __nv_bfloat16 g_kh2[BB * SS * NKH * HD];
__device__ __nv_bfloat16 g_kl2[BB * SS * NKH * HD];
__device__ __half g_vth[BB * NKH * HD * SS];   // [b][kh][d][s]  fp16 hi
__device__ __half g_vtl[BB * NKH * HD * SS];   // fp16 lo

// ---------------------------------------------------------------------------
// Warp-level MMA helpers
// ---------------------------------------------------------------------------
__device__ __forceinline__ uint32_t smem_u32(const void* p) {
    uint32_t a;
    asm("{ .reg .u64 t; cvta.to.shared.u64 t, %1; cvt.u32.u64 %0, t; }"
        : "=r"(a) : "l"(p));
    return a;
}

__device__ __forceinline__ void ldsm4(uint32_t& r0, uint32_t& r1,
                                      uint32_t& r2, uint32_t& r3, uint32_t a) {
    asm volatile("ldmatrix.sync.aligned.m8n8.x4.shared.b16 {%0,%1,%2,%3}, [%4];"
                 : "=r"(r0), "=r"(r1), "=r"(r2), "=r"(r3) : "r"(a));
}

__device__ __forceinline__ void mma_bf16(float* c, const uint32_t* a,
                                         const uint32_t* b) {
    asm volatile(
        "mma.sync.aligned.m16n8k16.row.col.f32.bf16.bf16.f32 "
        "{%0,%1,%2,%3}, {%4,%5,%6,%7}, {%8,%9}, {%0,%1,%2,%3};"
        : "+f"(c[0]), "+f"(c[1]), "+f"(c[2]), "+f"(c[3])
        : "r"(a[0]), "r"(a[1]), "r"(a[2]), "r"(a[3]), "r"(b[0]), "r"(b[1]));
}

__device__ __forceinline__ void mma_f16(float* c, const uint32_t* a,
                                        const uint32_t* b) {
    asm volatile(
        "mma.sync.aligned.m16n8k16.row.col.f32.f16.f16.f32 "
        "{%0,%1,%2,%3}, {%4,%5,%6,%7}, {%8,%9}, {%0,%1,%2,%3};"
        : "+f"(c[0]), "+f"(c[1]), "+f"(c[2]), "+f"(c[3])
        : "r"(a[0]), "r"(a[1]), "r"(a[2]), "r"(a[3]), "r"(b[0]), "r"(b[1]));
}

#define CP_ASYNC16(sa, ga) \
    asm volatile("cp.async.cg.shared.global [%0], [%1], 16;" \
                 :: "r"(sa), "l"(ga))
#define CP_COMMIT() asm volatile("cp.async.commit_group;")
#define CP_WAIT(N)  asm volatile("cp.async.wait_group %0;" :: "n"(N))

// ---------------------------------------------------------------------------
// GEMM common config
// ---------------------------------------------------------------------------
#define BK 32
#define GSTRIDE 40
#define GTILE_B (128 * GSTRIDE * 2)
#define GOFF(t, st) (((st) * 4 + (t)) * GTILE_B)
#define GEMM_SMEM (8 * GTILE_B)
#define TSTR 132   // fp32 epilogue tile stride

#define GEMM_MAINLOOP(OUT_ACC)                                                \
    float OUT_ACC[4][4][4];                                                   \
    _Pragma("unroll")                                                         \
    for (int i = 0; i < 4; i++)                                               \
        _Pragma("unroll")                                                     \
        for (int j = 0; j < 4; j++)                                           \
            _Pragma("unroll")                                                 \
            for (int r = 0; r < 4; r++) OUT_ACC[i][j][r] = 0.0f;              \
    const int nchunk = K / BK;                                                \
    load_stage(0, 0);                                                         \
    const int a_r = lane & 15;                                                \
    const int a_c = (lane >> 4) * 8;                                          \
    const int g4 = lane >> 3;                                                 \
    const int b4_r = (g4 >> 1) * 8 + (lane & 7);                              \
    const int b4_c = (g4 & 1) * 8;                                            \
    for (int c = 0; c < nchunk; c++) {                                        \
        const int st = c & 1;                                                 \
        if (c + 1 < nchunk) { load_stage(c + 1, st ^ 1); CP_WAIT(1); }        \
        else { CP_WAIT(0); }                                                  \
        __syncthreads();                                                      \
        const uint32_t sAh = sb + GOFF(0, st);                                \
        const uint32_t sAl = sb + GOFF(1, st);                                \
        const uint32_t sBh = sb + GOFF(2, st);                                \
        const uint32_t sBl = sb + GOFF(3, st);                                \
        _Pragma("unroll")                                                     \
        for (int kf = 0; kf < 2; kf++) {                                      \
            const int kc = kf * 16;                                           \
            uint32_t ah[4][4], al[4][4], bh[4][2], bl[4][2];                  \
            _Pragma("unroll")                                                 \
            for (int mf = 0; mf < 4; mf++) {                                  \
                uint32_t ad = ((warp_m + mf * 16 + a_r) * GSTRIDE + kc + a_c) * 2; \
                ldsm4(ah[mf][0], ah[mf][1], ah[mf][2], ah[mf][3], sAh + ad);  \
            }                                                                 \
            _Pragma("unroll")                                                 \
            for (int np = 0; np < 2; np++) {                                  \
                uint32_t bd = ((warp_n + np * 16 + b4_r) * GSTRIDE + kc + b4_c) * 2; \
                ldsm4(bh[np * 2][0], bh[np * 2][1],                           \
                      bh[np * 2 + 1][0], bh[np * 2 + 1][1], sBh + bd);        \
                ldsm4(bl[np * 2][0], bl[np * 2][1],                           \
                      bl[np * 2 + 1][0], bl[np * 2 + 1][1], sBl + bd);        \
            }                                                                 \
            _Pragma("unroll")                                                 \
            for (int mf = 0; mf < 4; mf++)                                    \
                _Pragma("unroll")                                             \
                for (int nf = 0; nf < 4; nf++) {                              \
                    mma_bf16(OUT_ACC[mf][nf], ah[mf], bh[nf]);                \
                    mma_bf16(OUT_ACC[mf][nf], ah[mf], bl[nf]);                \
                }                                                             \
            _Pragma("unroll")                                                 \
            for (int mf = 0; mf < 4; mf++) {                                  \
                uint32_t ad = ((warp_m + mf * 16 + a_r) * GSTRIDE + kc + a_c) * 2; \
                ldsm4(al[mf][0], al[mf][1], al[mf][2], al[mf][3], sAl + ad);  \
            }                                                                 \
            _Pragma("unroll")                                                 \
            for (int mf = 0; mf < 4; mf++)                                    \
                _Pragma("unroll")                                             \
                for (int nf = 0; nf < 4; nf++)                                \
                    mma_bf16(OUT_ACC[mf][nf], al[mf], bh[nf]);                \
        }                                                                     \
        __syncthreads();                                                      \
    }

// ---------------------------------------------------------------------------
// bf16x3 HMMA GEMM with plain fp32 C output (out-projection).
// ---------------------------------------------------------------------------
__global__ __launch_bounds__(256, 2) void gemm_bf16x3_kernel(
    const __nv_bfloat16* __restrict__ Ah, const __nv_bfloat16* __restrict__ Al,
    const __nv_bfloat16* __restrict__ Bh, const __nv_bfloat16* __restrict__ Bl,
    float* __restrict__ C, int M, int N, int K)
{
    extern __shared__ __align__(128) char smem[];
    const uint32_t sb = smem_u32(smem);
    const int tid = threadIdx.x;
    const int wid = tid >> 5;
    const int lane = tid & 31;
    const int bm = blockIdx.y * 128;
    const int bn = blockIdx.x * 128;
    const int warp_m = (wid >> 2) * 64;
    const int warp_n = (wid & 3) * 32;

    const __nv_bfloat16* gp[4] = {
        Ah + (size_t)bm * K, Al + (size_t)bm * K,
        Bh + (size_t)bn * K, Bl + (size_t)bn * K };

    const int lrow0 = tid >> 2;
    const int lq = tid & 3;

    auto load_stage = [&](int c, int st) {
#pragma unroll
        for (int t = 0; t < 4; t++) {
            const __nv_bfloat16* P = gp[t] + (size_t)c * BK;
#pragma unroll
            for (int it = 0; it < 2; it++) {
                int row = lrow0 + it * 64;
                uint32_t sa = sb + GOFF(t, st) + (row * GSTRIDE + lq * 8) * 2;
                CP_ASYNC16(sa, P + (size_t)row * K + lq * 8);
            }
        }
        CP_COMMIT();
    };

    GEMM_MAINLOOP(acc)

    const int er = lane >> 2;
    const int ec = (lane & 3) * 2;
#pragma unroll
    for (int mf = 0; mf < 4; mf++) {
#pragma unroll
        for (int nf = 0; nf < 4; nf++) {
            float* base = C + (size_t)(bm + warp_m + mf * 16 + er) * N
                            + bn + warp_n + nf * 8 + ec;
            *(float2*)base = make_float2(acc[mf][nf][0], acc[mf][nf][1]);
            *(float2*)(base + 8 * N) = make_float2(acc[mf][nf][2], acc[mf][nf][3]);
        }
    }
}

// ---------------------------------------------------------------------------
// QKV GEMM with fused RoPE+split / V-transpose+split epilogue.
// Q scaled by 0.125*log2(e); V written as fp16 hi/lo.
// ---------------------------------------------------------------------------
__global__ __launch_bounds__(256, 2) void gemm_qkv_kernel(
    const __nv_bfloat16* __restrict__ Ah, const __nv_bfloat16* __restrict__ Al,
    const __nv_bfloat16* __restrict__ Bh, const __nv_bfloat16* __restrict__ Bl,
    const float* __restrict__ cosb, const float* __restrict__ sinb,
    __nv_bfloat16* __restrict__ qh, __nv_bfloat16* __restrict__ ql,
    __nv_bfloat16* __restrict__ khp, __nv_bfloat16* __restrict__ klp,
    __half* __restrict__ vh, __half* __restrict__ vl)
{
    extern __shared__ __align__(128) char smem[];
    const uint32_t sb = smem_u32(smem);
    const int tid = threadIdx.x;
    const int wid = tid >> 5;
    const int lane = tid & 31;
    const int bm = blockIdx.y * 128;
    const int bn = blockIdx.x * 128;
    const int warp_m = (wid >> 2) * 64;
    const int warp_n = (wid & 3) * 32;
    const int K = DMODEL;

    const __nv_bfloat16* gp[4] = {
        Ah + (size_t)bm * K, Al + (size_t)bm * K,
        Bh + (size_t)bn * K, Bl + (size_t)bn * K };

    const int lrow0 = tid >> 2;
    const int lq = tid & 3;

    auto load_stage = [&](int c, int st) {
#pragma unroll
        for (int t = 0; t < 4; t++) {
            const __nv_bfloat16* P = gp[t] + (size_t)c * BK;
#pragma unroll
            for (int it = 0; it < 2; it++) {
                int row = lrow0 + it * 64;
                uint32_t sa = sb + GOFF(t, st) + (row * GSTRIDE + lq * 8) * 2;
                CP_ASYNC16(sa, P + (size_t)row * K + lq * 8);
            }
        }
        CP_COMMIT();
    };

    GEMM_MAINLOOP(acc)

    float* Ts = (float*)smem;
    const int er = lane >> 2;
    const int ec = (lane & 3) * 2;
#pragma unroll
    for (int mf = 0; mf < 4; mf++) {
#pragma unroll
        for (int nf = 0; nf < 4; nf++) {
            int r = warp_m + mf * 16 + er;
            int c = warp_n + nf * 8 + ec;
            *(float2*)&Ts[r * TSTR + c] = make_float2(acc[mf][nf][0], acc[mf][nf][1]);
            *(float2*)&Ts[(r + 8) * TSTR + c] = make_float2(acc[mf][nf][2], acc[mf][nf][3]);
        }
    }
    __syncthreads();

    if (bn < 1280) {
        const bool isq = (bn < 1024);
        const float scl = isq ? 0.125f * 1.4426950408889634f : 1.0f;
        __nv_bfloat16* th = isq ? qh : khp;
        __nv_bfloat16* tl = isq ? ql : klp;
        const int nheads = isq ? NH : NKH;
        const int h0 = isq ? (bn >> 6) : ((bn - 1024) >> 6);

#pragma unroll
        for (int it = 0; it < 8; it++) {
            int idx = tid + it * 256;
            int d0 = (idx & 7) * 4;
            int hh = (idx >> 3) & 1;
            int row = idx >> 4;
            int bs = bm + row;
            int s = bs & (SS - 1);

            const float* tr = &Ts[row * TSTR + hh * 64];
            float4 v0 = *(const float4*)(tr + d0);
            float4 v1 = *(const float4*)(tr + d0 + 32);
            float4 c0 = *(const float4*)(cosb + s * HD + d0);
            float4 c1 = *(const float4*)(cosb + s * HD + d0 + 32);
            float4 s0v = *(const float4*)(sinb + s * HD + d0);
            float4 s1v = *(const float4*)(sinb + s * HD + d0 + 32);

            float r0x = (v0.x * c0.x - v1.x * s0v.x) * scl;
            float r0y = (v0.y * c0.y - v1.y * s0v.y) * scl;
            float r0z = (v0.z * c0.z - v1.z * s0v.z) * scl;
            float r0w = (v0.w * c0.w - v1.w * s0v.w) * scl;
            float r1x = (v1.x * c1.x + v0.x * s1v.x) * scl;
            float r1y = (v1.y * c1.y + v0.y * s1v.y) * scl;
            float r1z = (v1.z * c1.z + v0.z * s1v.z) * scl;
            float r1w = (v1.w * c1.w + v0.w * s1v.w) * scl;

            size_t base = ((size_t)bs * nheads + h0 + hh) * HD;

            __nv_bfloat162 h0a = __float22bfloat162_rn(make_float2(r0x, r0y));
            __nv_bfloat162 h0b = __float22bfloat162_rn(make_float2(r0z, r0w));
            __nv_bfloat162 h1a = __float22bfloat162_rn(make_float2(r1x, r1y));
            __nv_bfloat162 h1b = __float22bfloat162_rn(make_float2(r1z, r1w));
            *(uint2*)(th + base + d0)      = make_uint2(*(uint32_t*)&h0a, *(uint32_t*)&h0b);
            *(uint2*)(th + base + d0 + 32) = make_uint2(*(uint32_t*)&h1a, *(uint32_t*)&h1b);

            __nv_bfloat162 l0a = __float22bfloat162_rn(make_float2(
                r0x - __bfloat162float(h0a.x), r0y - __bfloat162float(h0a.y)));
            __nv_bfloat162 l0b = __float22bfloat162_rn(make_float2(
                r0z - __bfloat162float(h0b.x), r0w - __bfloat162float(h0b.y)));
            __nv_bfloat162 l1a = __float22bfloat162_rn(make_float2(
                r1x - __bfloat162float(h1a.x), r1y - __bfloat162float(h1a.y)));
            __nv_bfloat162 l1b = __float22bfloat162_rn(make_float2(
                r1z - __bfloat162float(h1b.x), r1w - __bfloat162float(h1b.y)));
            *(uint2*)(tl + base + d0)      = make_uint2(*(uint32_t*)&l0a, *(uint32_t*)&l0b);
            *(uint2*)(tl + base + d0 + 32) = make_uint2(*(uint32_t*)&l1a, *(uint32_t*)&l1b);
        }
    } else {
        // V transpose + fp16 hi/lo split
        const int c = tid & 127;
        const int sh = tid >> 7;
        const int khead = ((bn - 1280) >> 6) + (c >> 6);
        const int d = c & 63;
        const int b = bm >> 11;
        const int s0 = (bm & (SS - 1)) + sh * 64;
        size_t base = ((size_t)(b * NKH + khead) * HD + d) * SS + s0;

#pragma unroll 4
        for (int s4 = 0; s4 < 64; s4 += 4) {
            float v0 = Ts[(sh * 64 + s4 + 0) * TSTR + c];
            float v1 = Ts[(sh * 64 + s4 + 1) * TSTR + c];
            float v2 = Ts[(sh * 64 + s4 + 2) * TSTR + c];
            float v3 = Ts[(sh * 64 + s4 + 3) * TSTR + c];
            __half2 p01 = __floats2half2_rn(v0, v1);
            __half2 p23 = __floats2half2_rn(v2, v3);
            *(uint2*)(vh + base + s4) = make_uint2(*(uint32_t*)&p01, *(uint32_t*)&p23);
            __half2 q01 = __floats2half2_rn(v0 - __low2float(p01), v1 - __high2float(p01));
            __half2 q23 = __floats2half2_rn(v2 - __low2float(p23), v3 - __high2float(p23));
            *(uint2*)(vl + base + s4) = make_uint2(*(uint32_t*)&q01, *(uint32_t*)&q23);
        }
    }
}

// ---------------------------------------------------------------------------
// Fused prep: blocks [0,4096) split x elementwise; [4096, 6656) weight tiles.
// ---------------------------------------------------------------------------
#define SPLIT_BLOCKS 4096

__global__ void prep_kernel(
    const float4* __restrict__ x4,
    __nv_bfloat162* __restrict__ xh2, __nv_bfloat162* __restrict__ xl2,
    const float* __restrict__ wq, const float* __restrict__ wk,
    const float* __restrict__ wv, const float* __restrict__ wo,
    __nv_bfloat16* __restrict__ wqkvh, __nv_bfloat16* __restrict__ wqkvl,
    __nv_bfloat16* __restrict__ woh, __nv_bfloat16* __restrict__ wol)
{
    __shared__ float t[32][33];
    const int tid = threadIdx.x;

    if (blockIdx.x < SPLIT_BLOCKS) {
        int i = blockIdx.x * 256 + tid;   // n4 = 1048576 = 4096*256 exactly
        float4 v = x4[i];
        __nv_bfloat16 h0 = __float2bfloat16(v.x);
        __nv_bfloat16 h1 = __float2bfloat16(v.y);
        __nv_bfloat16 h2 = __float2bfloat16(v.z);
        __nv_bfloat16 h3 = __float2bfloat16(v.w);
        xh2[2 * i]     = __nv_bfloat162(h0, h1);
        xh2[2 * i + 1] = __nv_bfloat162(h2, h3);
        xl2[2 * i]     = __nv_bfloat162(
            __float2bfloat16(v.x - __bfloat162float(h0)),
            __float2bfloat16(v.y - __bfloat162float(h1)));
        xl2[2 * i + 1] = __nv_bfloat162(
            __float2bfloat16(v.z - __bfloat162float(h2)),
            __float2bfloat16(v.w - __bfloat162float(h3)));
    } else {
        const int tile = blockIdx.x - SPLIT_BLOCKS;
        const float* src;
        __nv_bfloat16 *dh, *dl;
        int N, tloc;
        if (tile < 1024)      { src = wq; dh = wqkvh;                  dl = wqkvl;                  N = 1024; tloc = tile; }
        else if (tile < 1280) { src = wk; dh = wqkvh + 1024 * DMODEL;  dl = wqkvl + 1024 * DMODEL;  N = 256;  tloc = tile - 1024; }
        else if (tile < 1536) { src = wv; dh = wqkvh + 1280 * DMODEL;  dl = wqkvl + 1280 * DMODEL;  N = 256;  tloc = tile - 1280; }
        else                  { src = wo; dh = woh;                    dl = wol;                    N = 1024; tloc = tile - 1536; }
        const int nx = N >> 5;
        const int K = 1024;
        const int n0 = (tloc % nx) * 32;
        const int k0 = (tloc / nx) * 32;
        const int tx = tid & 31, ty = tid >> 5;
#pragma unroll
        for (int i = 0; i < 32; i += 8)
            t[ty + i][tx] = src[(size_t)(k0 + ty + i) * N + n0 + tx];
        __syncthreads();
#pragma unroll
        for (int i = 0; i < 32; i += 8) {
            float v = t[tx][ty + i];
            __nv_bfloat16 h = __float2bfloat16(v);
            float rres = v - __bfloat162float(h);
            size_t o = (size_t)(n0 + ty + i) * K + k0 + tx;
            dh[o] = h;
            dl[o] = __float2bfloat16(rres);
        }
    }
}

// ---------------------------------------------------------------------------
// HMMA flash attention, causal, GQA.
// BLOCK_M=128 (8 warps), BLOCK_N=64; 3-stage pipeline; exp2; LPT; Q in regs.
// S: bf16x3.  PV: fp16 P (single) x fp16 V (hi+lo) = 2 MMAs.
// ---------------------------------------------------------------------------
#define FSTR 72
#define FTILE64 (64 * FSTR * 2)
#define FQ_TILE (128 * FSTR * 2)
#define FQ_H 0
#define FQ_L FQ_TILE
#define FSTG(st) (2 * FQ_TILE + (st) * 4 * FTILE64)
#define FLASH_SMEM (2 * FQ_TILE + 3 * 4 * FTILE64)   // 147456 B

__global__ __launch_bounds__(256) void flash_hmma_kernel(
    const __nv_bfloat16* __restrict__ Qh, const __nv_bfloat16* __restrict__ Ql,
    const __nv_bfloat16* __restrict__ Kh, const __nv_bfloat16* __restrict__ Kl,
    const __half* __restrict__ Vth, const __half* __restrict__ Vtl,
    __nv_bfloat16* __restrict__ Oh, __nv_bfloat16* __restrict__ Ol)
{
    extern __shared__ __align__(128) char smem[];
    const uint32_t sb = smem_u32(smem);
    const int tid = threadIdx.x;
    const int wid = tid >> 5;
    const int lane = tid & 31;
    const int qt = gridDim.x - 1 - blockIdx.x;   // LPT
    const int h  = blockIdx.y;
    const int b  = blockIdx.z;
    const int q0 = qt * 128;
    const int khead = h >> 2;
    const int warp_m = wid * 16;

    const int er = lane >> 2;
    const int ec = (lane & 3) * 2;
    const int a_r = lane & 15;
    const int a_c = (lane >> 4) * 8;
    const int g4 = lane >> 3;
    const int b4_r = (g4 >> 1) * 8 + (lane & 7);
    const int b4_c = (g4 & 1) * 8;

    const __nv_bfloat16* qh_g = Qh + ((size_t)(b * SS + q0) * NH + h) * HD;
    const __nv_bfloat16* ql_g = Ql + ((size_t)(b * SS + q0) * NH + h) * HD;
    const __nv_bfloat16* kh_g = Kh + ((size_t)b * SS * NKH + khead) * HD;
    const __nv_bfloat16* kl_g = Kl + ((size_t)b * SS * NKH + khead) * HD;
    const __half* vth_g = Vth + (size_t)(b * NKH + khead) * HD * SS;
    const __half* vtl_g = Vtl + (size_t)(b * NKH + khead) * HD * SS;

    auto load_tile64 = [&](const void* g, size_t rstride_elt, uint32_t sofs) {
#pragma unroll
        for (int it = 0; it < 2; it++) {
            int ch = tid + it * 256;
            int r = ch >> 3;
            int q8 = ch & 7;
            CP_ASYNC16(sb + sofs + (r * FSTR + q8 * 8) * 2,
                       (const char*)g + ((size_t)r * rstride_elt + q8 * 8) * 2);
        }
    };
    auto load_q = [&](const __nv_bfloat16* g, uint32_t sofs) {
#pragma unroll
        for (int it = 0; it < 4; it++) {
            int ch = tid + it * 256;
            int r = ch >> 3;
            int q8 = ch & 7;
            CP_ASYNC16(sb + sofs + (r * FSTR + q8 * 8) * 2,
                       g + (size_t)r * (NH * HD) + q8 * 8);
        }
    };
    auto load_stage = [&](int kt, int st) {
        const int kn = kt * 64;
        load_tile64(kh_g + (size_t)kn * NKH * HD, NKH * HD, FSTG(st) + 0 * FTILE64);
        load_tile64(kl_g + (size_t)kn * NKH * HD, NKH * HD, FSTG(st) + 1 * FTILE64);
        load_tile64(vth_g + kn, SS, FSTG(st) + 2 * FTILE64);
        load_tile64(vtl_g + kn, SS, FSTG(st) + 3 * FTILE64);
        CP_COMMIT();
    };

    const int kt_end = 2 * qt + 1;

    load_q(qh_g, FQ_H);
    load_q(ql_g, FQ_L);
    CP_COMMIT();
    load_stage(0, 0);
    if (kt_end >= 1) { load_stage(1, 1); CP_WAIT(2); }
    else             { CP_WAIT(1); }
    __syncthreads();

    uint32_t qah[4][4], qal[4][4];
#pragma unroll
    for (int kf = 0; kf < 4; kf++) {
        uint32_t ad = ((warp_m + a_r) * FSTR + kf * 16 + a_c) * 2;
        ldsm4(qah[kf][0], qah[kf][1], qah[kf][2], qah[kf][3], sb + FQ_H + ad);
        ldsm4(qal[kf][0], qal[kf][1], qal[kf][2], qal[kf][3], sb + FQ_L + ad);
    }

    float m[2] = {-1e30f, -1e30f};
    float l[2] = {0.0f, 0.0f};
    float acc[8][4];
#pragma unroll
    for (int i = 0; i < 8; i++)
#pragma unroll
        for (int r = 0; r < 4; r++) acc[i][r] = 0.0f;

    for (int kt = 0; kt <= kt_end; kt++) {
        const int st = kt % 3;
        if (kt + 2 <= kt_end) {
            load_stage(kt + 2, (kt + 2) % 3);
            CP_WAIT(2);
        } else if (kt + 1 <= kt_end) {
            CP_WAIT(1);
        } else {
            CP_WAIT(0);
        }
        __syncthreads();

        const int row_lo = q0 + warp_m;
        const bool any  = (kt * 64     <= row_lo + 15);
        const bool full = (kt * 64 + 63 <= row_lo);

        if (any) {
            const uint32_t sKh = sb + FSTG(st) + 0 * FTILE64;
            const uint32_t sKl = sb + FSTG(st) + 1 * FTILE64;
            const uint32_t sVh = sb + FSTG(st) + 2 * FTILE64;
            const uint32_t sVl = sb + FSTG(st) + 3 * FTILE64;

            float sf[8][4];
#pragma unroll
            for (int nf = 0; nf < 8; nf++)
#pragma unroll
                for (int r = 0; r < 4; r++) sf[nf][r] = 0.0f;

#pragma unroll
            for (int kf = 0; kf < 4; kf++) {
                const int kc = kf * 16;
#pragma unroll
                for (int np = 0; np < 4; np++) {
                    uint32_t bd = ((np * 16 + b4_r) * FSTR + kc + b4_c) * 2;
                    uint32_t kbh[4], kbl[4];
                    ldsm4(kbh[0], kbh[1], kbh[2], kbh[3], sKh + bd);
                    ldsm4(kbl[0], kbl[1], kbl[2], kbl[3], sKl + bd);
                    mma_bf16(sf[np * 2],     qah[kf], kbh);
                    mma_bf16(sf[np * 2],     qah[kf], kbl);
                    mma_bf16(sf[np * 2],     qal[kf], kbh);
                    mma_bf16(sf[np * 2 + 1], qah[kf], kbh + 2);
                    mma_bf16(sf[np * 2 + 1], qah[kf], kbl + 2);
                    mma_bf16(sf[np * 2 + 1], qal[kf], kbh + 2);
                }
            }

            if (!full) {
                const int i0 = row_lo + er;
#pragma unroll
                for (int nf = 0; nf < 8; nf++) {
                    int j0 = kt * 64 + nf * 8 + ec;
                    if (j0     > i0)     sf[nf][0] = -1e30f;
                    if (j0 + 1 > i0)     sf[nf][1] = -1e30f;
                    if (j0     > i0 + 8) sf[nf][2] = -1e30f;
                    if (j0 + 1 > i0 + 8) sf[nf][3] = -1e30f;
                }
            }

            float rmax0 = -1e30f, rmax1 = -1e30f;
#pragma unroll
            for (int nf = 0; nf < 8; nf++) {
                rmax0 = fmaxf(rmax0, fmaxf(sf[nf][0], sf[nf][1]));
                rmax1 = fmaxf(rmax1, fmaxf(sf[nf][2], sf[nf][3]));
            }
            rmax0 = fmaxf(rmax0, __shfl_xor_sync(0xffffffffu, rmax0, 1));
            rmax0 = fmaxf(rmax0, __shfl_xor_sync(0xffffffffu, rmax0, 2));
            rmax1 = fmaxf(rmax1, __shfl_xor_sync(0xffffffffu, rmax1, 1));
            rmax1 = fmaxf(rmax1, __shfl_xor_sync(0xffffffffu, rmax1, 2));

            float nm0 = fmaxf(m[0], rmax0), nm1 = fmaxf(m[1], rmax1);
            float al0 = exp2f(m[0] - nm0), al1 = exp2f(m[1] - nm1);
            m[0] = nm0; m[1] = nm1;

            float sum0 = 0.0f, sum1 = 0.0f;
#pragma unroll
            for (int nf = 0; nf < 8; nf++) {
                sf[nf][0] = exp2f(sf[nf][0] - nm0);
                sf[nf][1] = exp2f(sf[nf][1] - nm0);
                sf[nf][2] = exp2f(sf[nf][2] - nm1);
                sf[nf][3] = exp2f(sf[nf][3] - nm1);
                sum0 += sf[nf][0] + sf[nf][1];
                sum1 += sf[nf][2] + sf[nf][3];
            }
            sum0 += __shfl_xor_sync(0xffffffffu, sum0, 1);
            sum0 += __shfl_xor_sync(0xffffffffu, sum0, 2);
            sum1 += __shfl_xor_sync(0xffffffffu, sum1, 1);
            sum1 += __shfl_xor_sync(0xffffffffu, sum1, 2);
            l[0] = l[0] * al0 + sum0;
            l[1] = l[1] * al1 + sum1;
#pragma unroll
            for (int i = 0; i < 8; i++) {
                acc[i][0] *= al0; acc[i][1] *= al0;
                acc[i][2] *= al1; acc[i][3] *= al1;
            }

            // ---- P as single fp16 (A-fragment layout) ----
            uint32_t pha[4][4];
#pragma unroll
            for (int kf = 0; kf < 4; kf++) {
#pragma unroll
                for (int half = 0; half < 2; half++) {
                    const float* s2 = sf[kf * 2 + half];
                    __half2 h01 = __floats2half2_rn(s2[0], s2[1]);
                    __half2 h23 = __floats2half2_rn(s2[2], s2[3]);
                    pha[kf][half * 2 + 0] = *(uint32_t*)&h01;
                    pha[kf][half * 2 + 1] = *(uint32_t*)&h23;
                }
            }

            // ---- O += P (Vh + Vl), fp16 MMA, 2 terms ----
#pragma unroll
            for (int kf = 0; kf < 4; kf++) {
#pragma unroll
                for (int np = 0; np < 4; np++) {
                    uint32_t bd = ((np * 16 + b4_r) * FSTR + kf * 16 + b4_c) * 2;
                    uint32_t vbh[4], vbl[4];
                    ldsm4(vbh[0], vbh[1], vbh[2], vbh[3], sVh + bd);
                    ldsm4(vbl[0], vbl[1], vbl[2], vbl[3], sVl + bd);
                    mma_f16(acc[np * 2],     pha[kf], vbh);
                    mma_f16(acc[np * 2],     pha[kf], vbl);
                    mma_f16(acc[np * 2 + 1], pha[kf], vbh + 2);
                    mma_f16(acc[np * 2 + 1], pha[kf], vbl + 2);
                }
            }
        }
        __syncthreads();
    }

    float inv0 = 1.0f / l[0], inv1 = 1.0f / l[1];
#pragma unroll
    for (int nf = 0; nf < 8; nf++) {
        size_t o0 = ((size_t)(b * SS + q0 + warp_m + er) * NH + h) * HD + nf * 8 + ec;
        size_t o1 = ((size_t)(b * SS + q0 + warp_m + er + 8) * NH + h) * HD + nf * 8 + ec;
        float v00 = acc[nf][0] * inv0, v01 = acc[nf][1] * inv0;
        float v10 = acc[nf][2] * inv1, v11 = acc[nf][3] * inv1;
        __nv_bfloat162 h0 = __float22bfloat162_rn(make_float2(v00, v01));
        __nv_bfloat162 h1 = __float22bfloat162_rn(make_float2(v10, v11));
        __nv_bfloat162 l0 = __float22bfloat162_rn(make_float2(
            v00 - __bfloat162float(h0.x), v01 - __bfloat162float(h0.y)));
        __nv_bfloat162 l1 = __float22bfloat162_rn(make_float2(
            v10 - __bfloat162float(h1.x), v11 - __bfloat162float(h1.y)));
        *(uint32_t*)(Oh + o0) = *(uint32_t*)&h0;
        *(uint32_t*)(Oh + o1) = *(uint32_t*)&h1;
        *(uint32_t*)(Ol + o0) = *(uint32_t*)&l0;
        *(uint32_t*)(Ol + o1) = *(uint32_t*)&l1;
    }
}

// ---------------------------------------------------------------------------
extern "C" void kernel_launch(void* const* d_in, const int* in_sizes, int n_in,
                              void* d_out, int out_size)
{
    const float* x    = (const float*)d_in[0];
    const float* cosb = (const float*)d_in[1];
    const float* sinb = (const float*)d_in[2];
    const float* wq   = (const float*)d_in[3];
    const float* wk   = (const float*)d_in[4];
    const float* wv   = (const float*)d_in[5];
    const float* wo   = (const float*)d_in[6];
    float* out = (float*)d_out;

    __nv_bfloat16 *xh, *xl, *oh, *ol;
    __nv_bfloat16 *wqkvh, *wqkvl, *woh, *wol;
    __nv_bfloat16 *qh, *ql, *kh2, *kl2;
    __half *vth, *vtl;
    cudaGetSymbolAddress((void**)&xh, g_xh);
    cudaGetSymbolAddress((void**)&xl, g_xl);
    cudaGetSymbolAddress((void**)&oh, g_oh);
    cudaGetSymbolAddress((void**)&ol, g_ol);
    cudaGetSymbolAddress((void**)&wqkvh, g_wqkvh);
    cudaGetSymbolAddress((void**)&wqkvl, g_wqkvl);
    cudaGetSymbolAddress((void**)&woh, g_woh);
    cudaGetSymbolAddress((void**)&wol, g_wol);
    cudaGetSymbolAddress((void**)&qh, g_qh);
    cudaGetSymbolAddress((void**)&ql, g_ql);
    cudaGetSymbolAddress((void**)&kh2, g_kh2);
    cudaGetSymbolAddress((void**)&kl2, g_kl2);
    cudaGetSymbolAddress((void**)&vth, g_vth);
    cudaGetSymbolAddress((void**)&vtl, g_vtl);

    cudaFuncSetAttribute(gemm_bf16x3_kernel,
                         cudaFuncAttributeMaxDynamicSharedMemorySize, GEMM_SMEM);
    cudaFuncSetAttribute(gemm_qkv_kernel,
                         cudaFuncAttributeMaxDynamicSharedMemorySize, GEMM_SMEM);
    cudaFuncSetAttribute(flash_hmma_kernel,
                         cudaFuncAttributeMaxDynamicSharedMemorySize, FLASH_SMEM);

    const int M = BB * SS;  // 4096

    // Fused prep: x split + all weight transposes, one launch
    prep_kernel<<<SPLIT_BLOCKS + 2560, 256>>>(
        (const float4*)x, (__nv_bfloat162*)xh, (__nv_bfloat162*)xl,
        wq, wk, wv, wo, wqkvh, wqkvl, woh, wol);

    // Fused QKV projection + RoPE/split/V-transpose epilogue
    gemm_qkv_kernel<<<dim3(NQKV / 128, M / 128), 256, GEMM_SMEM>>>(
        xh, xl, wqkvh, wqkvl, cosb, sinb, qh, ql, kh2, kl2, vth, vtl);

    // Causal GQA flash attention (3-stage, Q in regs, fp16 PV)
    flash_hmma_kernel<<<dim3(SS / 128, NH, BB), 256, FLASH_SMEM>>>(
        qh, ql, kh2, kl2, vth, vtl, oh, ol);

    // Output projection (HMMA bf16x3)
    gemm_bf16x3_kernel<<<dim3(DMODEL / 128, M / 128), 256, GEMM_SMEM>>>(
        oh, ol, woh, wol, out, M, DMODEL, DMODEL);
}

// round 15
// speedup vs baseline: 1.2106x; 1.0740x over previous
#include <cuda_runtime.h>
#include <cuda_bf16.h>
#include <cuda_fp16.h>
#include <cstdint>
#include <math.h>

#define BB 2
#define SS 2048
#define DMODEL 1024
#define NH 16
#define NKH 4
#define HD 64
#define NQKV 1536

// ---------------------------------------------------------------------------
// Scratch (device globals: allocation-free)
// ---------------------------------------------------------------------------
__device__ __nv_bfloat16 g_xh[BB * SS * DMODEL];
__device__ __nv_bfloat16 g_xl[BB * SS * DMODEL];
__device__ __half        g_of[BB * SS * NH * HD];    // attn out, single fp16
__device__ __nv_bfloat16 g_wqkvh[NQKV * DMODEL];
__device__ __nv_bfloat16 g_wqkvl[NQKV * DMODEL];
__device__ __half        g_woh[DMODEL * (NH * HD)];  // wo fp16 hi
__device__ __half        g_wol[DMODEL * (NH * HD)];  // wo fp16 lo

__device__ __nv_bfloat16 g_qh[BB * SS * NH * HD];
__device__ __nv_bfloat16 g_ql[BB * SS * NH * HD];
__device__ __nv_bfloat16 g_kh2[BB * SS * NKH * HD];
__device__ __nv_bfloat16 g_kl2[BB * SS * NKH * HD];
__device__ __half g_vth[BB * NKH * HD * SS];   // [b][kh][d][s]
__device__ __half g_vtl[BB * NKH * HD * SS];

// ---------------------------------------------------------------------------
// Warp-level MMA helpers
// ---------------------------------------------------------------------------
__device__ __forceinline__ uint32_t smem_u32(const void* p) {
    uint32_t a;
    asm("{ .reg .u64 t; cvta.to.shared.u64 t, %1; cvt.u32.u64 %0, t; }"
        : "=r"(a) : "l"(p));
    return a;
}

__device__ __forceinline__ void ldsm4(uint32_t& r0, uint32_t& r1,
                                      uint32_t& r2, uint32_t& r3, uint32_t a) {
    asm volatile("ldmatrix.sync.aligned.m8n8.x4.shared.b16 {%0,%1,%2,%3}, [%4];"
                 : "=r"(r0), "=r"(r1), "=r"(r2), "=r"(r3) : "r"(a));
}

__device__ __forceinline__ void mma_bf16(float* c, const uint32_t* a,
                                         const uint32_t* b) {
    asm volatile(
        "mma.sync.aligned.m16n8k16.row.col.f32.bf16.bf16.f32 "
        "{%0,%1,%2,%3}, {%4,%5,%6,%7}, {%8,%9}, {%0,%1,%2,%3};"
        : "+f"(c[0]), "+f"(c[1]), "+f"(c[2]), "+f"(c[3])
        : "r"(a[0]), "r"(a[1]), "r"(a[2]), "r"(a[3]), "r"(b[0]), "r"(b[1]));
}

__device__ __forceinline__ void mma_f16(float* c, const uint32_t* a,
                                        const uint32_t* b) {
    asm volatile(
        "mma.sync.aligned.m16n8k16.row.col.f32.f16.f16.f32 "
        "{%0,%1,%2,%3}, {%4,%5,%6,%7}, {%8,%9}, {%0,%1,%2,%3};"
        : "+f"(c[0]), "+f"(c[1]), "+f"(c[2]), "+f"(c[3])
        : "r"(a[0]), "r"(a[1]), "r"(a[2]), "r"(a[3]), "r"(b[0]), "r"(b[1]));
}

#define CP_ASYNC16(sa, ga) \
    asm volatile("cp.async.cg.shared.global [%0], [%1], 16;" \
                 :: "r"(sa), "l"(ga))
#define CP_COMMIT() asm volatile("cp.async.commit_group;")
#define CP_WAIT(N)  asm volatile("cp.async.wait_group %0;" :: "n"(N))

// ---------------------------------------------------------------------------
// GEMM common config
// ---------------------------------------------------------------------------
#define BK 32
#define GSTRIDE 40
#define GTILE_B (128 * GSTRIDE * 2)
#define GOFF(t, st) (((st) * 4 + (t)) * GTILE_B)
#define GEMM_SMEM (8 * GTILE_B)
#define OOFF(t, st) (((st) * 3 + (t)) * GTILE_B)
#define OUT_SMEM (6 * GTILE_B)                       // 61440 B
#define TSTR 132

#define GEMM_MAINLOOP(OUT_ACC)                                                \
    float OUT_ACC[4][4][4];                                                   \
    _Pragma("unroll")                                                         \
    for (int i = 0; i < 4; i++)                                               \
        _Pragma("unroll")                                                     \
        for (int j = 0; j < 4; j++)                                           \
            _Pragma("unroll")                                                 \
            for (int r = 0; r < 4; r++) OUT_ACC[i][j][r] = 0.0f;              \
    const int nchunk = K / BK;                                                \
    load_stage(0, 0);                                                         \
    const int a_r = lane & 15;                                                \
    const int a_c = (lane >> 4) * 8;                                          \
    const int g4 = lane >> 3;                                                 \
    const int b4_r = (g4 >> 1) * 8 + (lane & 7);                              \
    const int b4_c = (g4 & 1) * 8;                                            \
    for (int c = 0; c < nchunk; c++) {                                        \
        const int st = c & 1;                                                 \
        if (c + 1 < nchunk) { load_stage(c + 1, st ^ 1); CP_WAIT(1); }        \
        else { CP_WAIT(0); }                                                  \
        __syncthreads();                                                      \
        const uint32_t sAh = sb + GOFF(0, st);                                \
        const uint32_t sAl = sb + GOFF(1, st);                                \
        const uint32_t sBh = sb + GOFF(2, st);                                \
        const uint32_t sBl = sb + GOFF(3, st);                                \
        _Pragma("unroll")                                                     \
        for (int kf = 0; kf < 2; kf++) {                                      \
            const int kc = kf * 16;                                           \
            uint32_t ah[4][4], al[4][4], bh[4][2], bl[4][2];                  \
            _Pragma("unroll")                                                 \
            for (int mf = 0; mf < 4; mf++) {                                  \
                uint32_t ad = ((warp_m + mf * 16 + a_r) * GSTRIDE + kc + a_c) * 2; \
                ldsm4(ah[mf][0], ah[mf][1], ah[mf][2], ah[mf][3], sAh + ad);  \
            }                                                                 \
            _Pragma("unroll")                                                 \
            for (int np = 0; np < 2; np++) {                                  \
                uint32_t bd = ((warp_n + np * 16 + b4_r) * GSTRIDE + kc + b4_c) * 2; \
                ldsm4(bh[np * 2][0], bh[np * 2][1],                           \
                      bh[np * 2 + 1][0], bh[np * 2 + 1][1], sBh + bd);        \
                ldsm4(bl[np * 2][0], bl[np * 2][1],                           \
                      bl[np * 2 + 1][0], bl[np * 2 + 1][1], sBl + bd);        \
            }                                                                 \
            _Pragma("unroll")                                                 \
            for (int mf = 0; mf < 4; mf++)                                    \
                _Pragma("unroll")                                             \
                for (int nf = 0; nf < 4; nf++) {                              \
                    mma_bf16(OUT_ACC[mf][nf], ah[mf], bh[nf]);                \
                    mma_bf16(OUT_ACC[mf][nf], ah[mf], bl[nf]);                \
                }                                                             \
            _Pragma("unroll")                                                 \
            for (int mf = 0; mf < 4; mf++) {                                  \
                uint32_t ad = ((warp_m + mf * 16 + a_r) * GSTRIDE + kc + a_c) * 2; \
                ldsm4(al[mf][0], al[mf][1], al[mf][2], al[mf][3], sAl + ad);  \
            }                                                                 \
            _Pragma("unroll")                                                 \
            for (int mf = 0; mf < 4; mf++)                                    \
                _Pragma("unroll")                                             \
                for (int nf = 0; nf < 4; nf++)                                \
                    mma_bf16(OUT_ACC[mf][nf], al[mf], bh[nf]);                \
        }                                                                     \
        __syncthreads();                                                      \
    }

// ---------------------------------------------------------------------------
// Out-projection GEMM: fp16 2-term. C = Af @ (Bh + Bl)^T, fp32 out.
// A single fp16 [M][K]; B fp16 hi/lo [N][K]. 3 tiles/stage.
// ---------------------------------------------------------------------------
__global__ __launch_bounds__(256, 2) void gemm_out_f16_kernel(
    const __half* __restrict__ Af,
    const __half* __restrict__ Bh, const __half* __restrict__ Bl,
    float* __restrict__ C, int M, int N, int K)
{
    extern __shared__ __align__(128) char smem[];
    const uint32_t sb = smem_u32(smem);
    const int tid = threadIdx.x;
    const int wid = tid >> 5;
    const int lane = tid & 31;
    const int bm = blockIdx.y * 128;
    const int bn = blockIdx.x * 128;
    const int warp_m = (wid >> 2) * 64;
    const int warp_n = (wid & 3) * 32;

    const __half* gp[3] = {
        Af + (size_t)bm * K, Bh + (size_t)bn * K, Bl + (size_t)bn * K };

    const int lrow0 = tid >> 2;
    const int lq = tid & 3;

    auto load_stage = [&](int c, int st) {
#pragma unroll
        for (int t = 0; t < 3; t++) {
            const __half* P = gp[t] + (size_t)c * BK;
#pragma unroll
            for (int it = 0; it < 2; it++) {
                int row = lrow0 + it * 64;
                uint32_t sa = sb + OOFF(t, st) + (row * GSTRIDE + lq * 8) * 2;
                CP_ASYNC16(sa, P + (size_t)row * K + lq * 8);
            }
        }
        CP_COMMIT();
    };

    float acc[4][4][4];
#pragma unroll
    for (int i = 0; i < 4; i++)
#pragma unroll
        for (int j = 0; j < 4; j++)
#pragma unroll
            for (int r = 0; r < 4; r++) acc[i][j][r] = 0.0f;

    const int nchunk = K / BK;
    load_stage(0, 0);

    const int a_r = lane & 15;
    const int a_c = (lane >> 4) * 8;
    const int g4 = lane >> 3;
    const int b4_r = (g4 >> 1) * 8 + (lane & 7);
    const int b4_c = (g4 & 1) * 8;

    for (int c = 0; c < nchunk; c++) {
        const int st = c & 1;
        if (c + 1 < nchunk) { load_stage(c + 1, st ^ 1); CP_WAIT(1); }
        else { CP_WAIT(0); }
        __syncthreads();

        const uint32_t sAf = sb + OOFF(0, st);
        const uint32_t sBh = sb + OOFF(1, st);
        const uint32_t sBl = sb + OOFF(2, st);

#pragma unroll
        for (int kf = 0; kf < 2; kf++) {
            const int kc = kf * 16;
            uint32_t af[4][4], bh[4][2], bl[4][2];
#pragma unroll
            for (int mf = 0; mf < 4; mf++) {
                uint32_t ad = ((warp_m + mf * 16 + a_r) * GSTRIDE + kc + a_c) * 2;
                ldsm4(af[mf][0], af[mf][1], af[mf][2], af[mf][3], sAf + ad);
            }
#pragma unroll
            for (int np = 0; np < 2; np++) {
                uint32_t bd = ((warp_n + np * 16 + b4_r) * GSTRIDE + kc + b4_c) * 2;
                ldsm4(bh[np * 2][0], bh[np * 2][1],
                      bh[np * 2 + 1][0], bh[np * 2 + 1][1], sBh + bd);
                ldsm4(bl[np * 2][0], bl[np * 2][1],
                      bl[np * 2 + 1][0], bl[np * 2 + 1][1], sBl + bd);
            }
#pragma unroll
            for (int mf = 0; mf < 4; mf++)
#pragma unroll
                for (int nf = 0; nf < 4; nf++) {
                    mma_f16(acc[mf][nf], af[mf], bh[nf]);
                    mma_f16(acc[mf][nf], af[mf], bl[nf]);
                }
        }
        __syncthreads();
    }

    const int er = lane >> 2;
    const int ec = (lane & 3) * 2;
#pragma unroll
    for (int mf = 0; mf < 4; mf++) {
#pragma unroll
        for (int nf = 0; nf < 4; nf++) {
            float* base = C + (size_t)(bm + warp_m + mf * 16 + er) * N
                            + bn + warp_n + nf * 8 + ec;
            *(float2*)base = make_float2(acc[mf][nf][0], acc[mf][nf][1]);
            *(float2*)(base + 8 * N) = make_float2(acc[mf][nf][2], acc[mf][nf][3]);
        }
    }
}

// ---------------------------------------------------------------------------
// QKV GEMM (bf16x3, precision-critical) with fused RoPE/split/V epilogue.
// ---------------------------------------------------------------------------
__global__ __launch_bounds__(256, 2) void gemm_qkv_kernel(
    const __nv_bfloat16* __restrict__ Ah, const __nv_bfloat16* __restrict__ Al,
    const __nv_bfloat16* __restrict__ Bh, const __nv_bfloat16* __restrict__ Bl,
    const float* __restrict__ cosb, const float* __restrict__ sinb,
    __nv_bfloat16* __restrict__ qh, __nv_bfloat16* __restrict__ ql,
    __nv_bfloat16* __restrict__ khp, __nv_bfloat16* __restrict__ klp,
    __half* __restrict__ vh, __half* __restrict__ vl)
{
    extern __shared__ __align__(128) char smem[];
    const uint32_t sb = smem_u32(smem);
    const int tid = threadIdx.x;
    const int wid = tid >> 5;
    const int lane = tid & 31;
    const int bm = blockIdx.y * 128;
    const int bn = blockIdx.x * 128;
    const int warp_m = (wid >> 2) * 64;
    const int warp_n = (wid & 3) * 32;
    const int K = DMODEL;

    const __nv_bfloat16* gp[4] = {
        Ah + (size_t)bm * K, Al + (size_t)bm * K,
        Bh + (size_t)bn * K, Bl + (size_t)bn * K };

    const int lrow0 = tid >> 2;
    const int lq = tid & 3;

    auto load_stage = [&](int c, int st) {
#pragma unroll
        for (int t = 0; t < 4; t++) {
            const __nv_bfloat16* P = gp[t] + (size_t)c * BK;
#pragma unroll
            for (int it = 0; it < 2; it++) {
                int row = lrow0 + it * 64;
                uint32_t sa = sb + GOFF(t, st) + (row * GSTRIDE + lq * 8) * 2;
                CP_ASYNC16(sa, P + (size_t)row * K + lq * 8);
            }
        }
        CP_COMMIT();
    };

    GEMM_MAINLOOP(acc)

    float* Ts = (float*)smem;
    const int er = lane >> 2;
    const int ec = (lane & 3) * 2;
#pragma unroll
    for (int mf = 0; mf < 4; mf++) {
#pragma unroll
        for (int nf = 0; nf < 4; nf++) {
            int r = warp_m + mf * 16 + er;
            int c = warp_n + nf * 8 + ec;
            *(float2*)&Ts[r * TSTR + c] = make_float2(acc[mf][nf][0], acc[mf][nf][1]);
            *(float2*)&Ts[(r + 8) * TSTR + c] = make_float2(acc[mf][nf][2], acc[mf][nf][3]);
        }
    }
    __syncthreads();

    if (bn < 1280) {
        const bool isq = (bn < 1024);
        const float scl = isq ? 0.125f * 1.4426950408889634f : 1.0f;
        __nv_bfloat16* th = isq ? qh : khp;
        __nv_bfloat16* tl = isq ? ql : klp;
        const int nheads = isq ? NH : NKH;
        const int h0 = isq ? (bn >> 6) : ((bn - 1024) >> 6);

#pragma unroll
        for (int it = 0; it < 8; it++) {
            int idx = tid + it * 256;
            int d0 = (idx & 7) * 4;
            int hh = (idx >> 3) & 1;
            int row = idx >> 4;
            int bs = bm + row;
            int s = bs & (SS - 1);

            const float* tr = &Ts[row * TSTR + hh * 64];
            float4 v0 = *(const float4*)(tr + d0);
            float4 v1 = *(const float4*)(tr + d0 + 32);
            float4 c0 = *(const float4*)(cosb + s * HD + d0);
            float4 c1 = *(const float4*)(cosb + s * HD + d0 + 32);
            float4 s0v = *(const float4*)(sinb + s * HD + d0);
            float4 s1v = *(const float4*)(sinb + s * HD + d0 + 32);

            float r0x = (v0.x * c0.x - v1.x * s0v.x) * scl;
            float r0y = (v0.y * c0.y - v1.y * s0v.y) * scl;
            float r0z = (v0.z * c0.z - v1.z * s0v.z) * scl;
            float r0w = (v0.w * c0.w - v1.w * s0v.w) * scl;
            float r1x = (v1.x * c1.x + v0.x * s1v.x) * scl;
            float r1y = (v1.y * c1.y + v0.y * s1v.y) * scl;
            float r1z = (v1.z * c1.z + v0.z * s1v.z) * scl;
            float r1w = (v1.w * c1.w + v0.w * s1v.w) * scl;

            size_t base = ((size_t)bs * nheads + h0 + hh) * HD;

            __nv_bfloat162 h0a = __float22bfloat162_rn(make_float2(r0x, r0y));
            __nv_bfloat162 h0b = __float22bfloat162_rn(make_float2(r0z, r0w));
            __nv_bfloat162 h1a = __float22bfloat162_rn(make_float2(r1x, r1y));
            __nv_bfloat162 h1b = __float22bfloat162_rn(make_float2(r1z, r1w));
            *(uint2*)(th + base + d0)      = make_uint2(*(uint32_t*)&h0a, *(uint32_t*)&h0b);
            *(uint2*)(th + base + d0 + 32) = make_uint2(*(uint32_t*)&h1a, *(uint32_t*)&h1b);

            __nv_bfloat162 l0a = __float22bfloat162_rn(make_float2(
                r0x - __bfloat162float(h0a.x), r0y - __bfloat162float(h0a.y)));
            __nv_bfloat162 l0b = __float22bfloat162_rn(make_float2(
                r0z - __bfloat162float(h0b.x), r0w - __bfloat162float(h0b.y)));
            __nv_bfloat162 l1a = __float22bfloat162_rn(make_float2(
                r1x - __bfloat162float(h1a.x), r1y - __bfloat162float(h1a.y)));
            __nv_bfloat162 l1b = __float22bfloat162_rn(make_float2(
                r1z - __bfloat162float(h1b.x), r1w - __bfloat162float(h1b.y)));
            *(uint2*)(tl + base + d0)      = make_uint2(*(uint32_t*)&l0a, *(uint32_t*)&l0b);
            *(uint2*)(tl + base + d0 + 32) = make_uint2(*(uint32_t*)&l1a, *(uint32_t*)&l1b);
        }
    } else {
        const int c = tid & 127;
        const int sh = tid >> 7;
        const int khead = ((bn - 1280) >> 6) + (c >> 6);
        const int d = c & 63;
        const int b = bm >> 11;
        const int s0 = (bm & (SS - 1)) + sh * 64;
        size_t base = ((size_t)(b * NKH + khead) * HD + d) * SS + s0;

#pragma unroll 4
        for (int s4 = 0; s4 < 64; s4 += 4) {
            float v0 = Ts[(sh * 64 + s4 + 0) * TSTR + c];
            float v1 = Ts[(sh * 64 + s4 + 1) * TSTR + c];
            float v2 = Ts[(sh * 64 + s4 + 2) * TSTR + c];
            float v3 = Ts[(sh * 64 + s4 + 3) * TSTR + c];
            __half2 p01 = __floats2half2_rn(v0, v1);
            __half2 p23 = __floats2half2_rn(v2, v3);
            *(uint2*)(vh + base + s4) = make_uint2(*(uint32_t*)&p01, *(uint32_t*)&p23);
            __half2 q01 = __floats2half2_rn(v0 - __low2float(p01), v1 - __high2float(p01));
            __half2 q23 = __floats2half2_rn(v2 - __low2float(p23), v3 - __high2float(p23));
            *(uint2*)(vl + base + s4) = make_uint2(*(uint32_t*)&q01, *(uint32_t*)&q23);
        }
    }
}

// ---------------------------------------------------------------------------
// Fused prep: [0,4096) split x (bf16 pair); [4096,6656) weight tiles
// (wq/wk/wv -> bf16 pair; wo -> fp16 pair).
// ---------------------------------------------------------------------------
#define SPLIT_BLOCKS 4096

__global__ void prep_kernel(
    const float4* __restrict__ x4,
    __nv_bfloat162* __restrict__ xh2, __nv_bfloat162* __restrict__ xl2,
    const float* __restrict__ wq, const float* __restrict__ wk,
    const float* __restrict__ wv, const float* __restrict__ wo,
    __nv_bfloat16* __restrict__ wqkvh, __nv_bfloat16* __restrict__ wqkvl,
    __half* __restrict__ woh, __half* __restrict__ wol)
{
    __shared__ float t[32][33];
    const int tid = threadIdx.x;

    if (blockIdx.x < SPLIT_BLOCKS) {
        int i = blockIdx.x * 256 + tid;
        float4 v = x4[i];
        __nv_bfloat16 h0 = __float2bfloat16(v.x);
        __nv_bfloat16 h1 = __float2bfloat16(v.y);
        __nv_bfloat16 h2 = __float2bfloat16(v.z);
        __nv_bfloat16 h3 = __float2bfloat16(v.w);
        xh2[2 * i]     = __nv_bfloat162(h0, h1);
        xh2[2 * i + 1] = __nv_bfloat162(h2, h3);
        xl2[2 * i]     = __nv_bfloat162(
            __float2bfloat16(v.x - __bfloat162float(h0)),
            __float2bfloat16(v.y - __bfloat162float(h1)));
        xl2[2 * i + 1] = __nv_bfloat162(
            __float2bfloat16(v.z - __bfloat162float(h2)),
            __float2bfloat16(v.w - __bfloat162float(h3)));
    } else {
        const int tile = blockIdx.x - SPLIT_BLOCKS;
        const float* src;
        int N, tloc, iswo = 0;
        __nv_bfloat16 *dh = nullptr, *dl = nullptr;
        if (tile < 1024)      { src = wq; dh = wqkvh;                  dl = wqkvl;                  N = 1024; tloc = tile; }
        else if (tile < 1280) { src = wk; dh = wqkvh + 1024 * DMODEL;  dl = wqkvl + 1024 * DMODEL;  N = 256;  tloc = tile - 1024; }
        else if (tile < 1536) { src = wv; dh = wqkvh + 1280 * DMODEL;  dl = wqkvl + 1280 * DMODEL;  N = 256;  tloc = tile - 1280; }
        else                  { src = wo; iswo = 1;                                                 N = 1024; tloc = tile - 1536; }
        const int nx = N >> 5;
        const int K = 1024;
        const int n0 = (tloc % nx) * 32;
        const int k0 = (tloc / nx) * 32;
        const int tx = tid & 31, ty = tid >> 5;
#pragma unroll
        for (int i = 0; i < 32; i += 8)
            t[ty + i][tx] = src[(size_t)(k0 + ty + i) * N + n0 + tx];
        __syncthreads();
#pragma unroll
        for (int i = 0; i < 32; i += 8) {
            float v = t[tx][ty + i];
            size_t o = (size_t)(n0 + ty + i) * K + k0 + tx;
            if (iswo) {
                __half h = __float2half_rn(v);
                woh[o] = h;
                wol[o] = __float2half_rn(v - __half2float(h));
            } else {
                __nv_bfloat16 h = __float2bfloat16(v);
                dh[o] = h;
                dl[o] = __float2bfloat16(v - __bfloat162float(h));
            }
        }
    }
}

// ---------------------------------------------------------------------------
// HMMA flash attention, causal, GQA.
// BM=128 (8 warps), BN=64; 3-stage; exp2; LPT; Q in regs.
// S: bf16x3.  PV: fp16 P x fp16 V (hi+lo).  Output: single fp16.
// ---------------------------------------------------------------------------
#define FSTR 72
#define FTILE64 (64 * FSTR * 2)
#define FQ_TILE (128 * FSTR * 2)
#define FQ_H 0
#define FQ_L FQ_TILE
#define FSTG(st) (2 * FQ_TILE + (st) * 4 * FTILE64)
#define FLASH_SMEM (2 * FQ_TILE + 3 * 4 * FTILE64)   // 147456 B

__global__ __launch_bounds__(256) void flash_hmma_kernel(
    const __nv_bfloat16* __restrict__ Qh, const __nv_bfloat16* __restrict__ Ql,
    const __nv_bfloat16* __restrict__ Kh, const __nv_bfloat16* __restrict__ Kl,
    const __half* __restrict__ Vth, const __half* __restrict__ Vtl,
    __half* __restrict__ Of)
{
    extern __shared__ __align__(128) char smem[];
    const uint32_t sb = smem_u32(smem);
    const int tid = threadIdx.x;
    const int wid = tid >> 5;
    const int lane = tid & 31;
    const int qt = gridDim.x - 1 - blockIdx.x;   // LPT
    const int h  = blockIdx.y;
    const int b  = blockIdx.z;
    const int q0 = qt * 128;
    const int khead = h >> 2;
    const int warp_m = wid * 16;

    const int er = lane >> 2;
    const int ec = (lane & 3) * 2;
    const int a_r = lane & 15;
    const int a_c = (lane >> 4) * 8;
    const int g4 = lane >> 3;
    const int b4_r = (g4 >> 1) * 8 + (lane & 7);
    const int b4_c = (g4 & 1) * 8;

    const __nv_bfloat16* qh_g = Qh + ((size_t)(b * SS + q0) * NH + h) * HD;
    const __nv_bfloat16* ql_g = Ql + ((size_t)(b * SS + q0) * NH + h) * HD;
    const __nv_bfloat16* kh_g = Kh + ((size_t)b * SS * NKH + khead) * HD;
    const __nv_bfloat16* kl_g = Kl + ((size_t)b * SS * NKH + khead) * HD;
    const __half* vth_g = Vth + (size_t)(b * NKH + khead) * HD * SS;
    const __half* vtl_g = Vtl + (size_t)(b * NKH + khead) * HD * SS;

    auto load_tile64 = [&](const void* g, size_t rstride_elt, uint32_t sofs) {
#pragma unroll
        for (int it = 0; it < 2; it++) {
            int ch = tid + it * 256;
            int r = ch >> 3;
            int q8 = ch & 7;
            CP_ASYNC16(sb + sofs + (r * FSTR + q8 * 8) * 2,
                       (const char*)g + ((size_t)r * rstride_elt + q8 * 8) * 2);
        }
    };
    auto load_q = [&](const __nv_bfloat16* g, uint32_t sofs) {
#pragma unroll
        for (int it = 0; it < 4; it++) {
            int ch = tid + it * 256;
            int r = ch >> 3;
            int q8 = ch & 7;
            CP_ASYNC16(sb + sofs + (r * FSTR + q8 * 8) * 2,
                       g + (size_t)r * (NH * HD) + q8 * 8);
        }
    };
    auto load_stage = [&](int kt, int st) {
        const int kn = kt * 64;
        load_tile64(kh_g + (size_t)kn * NKH * HD, NKH * HD, FSTG(st) + 0 * FTILE64);
        load_tile64(kl_g + (size_t)kn * NKH * HD, NKH * HD, FSTG(st) + 1 * FTILE64);
        load_tile64(vth_g + kn, SS, FSTG(st) + 2 * FTILE64);
        load_tile64(vtl_g + kn, SS, FSTG(st) + 3 * FTILE64);
        CP_COMMIT();
    };

    const int kt_end = 2 * qt + 1;

    load_q(qh_g, FQ_H);
    load_q(ql_g, FQ_L);
    CP_COMMIT();
    load_stage(0, 0);
    if (kt_end >= 1) { load_stage(1, 1); CP_WAIT(2); }
    else             { CP_WAIT(1); }
    __syncthreads();

    uint32_t qah[4][4], qal[4][4];
#pragma unroll
    for (int kf = 0; kf < 4; kf++) {
        uint32_t ad = ((warp_m + a_r) * FSTR + kf * 16 + a_c) * 2;
        ldsm4(qah[kf][0], qah[kf][1], qah[kf][2], qah[kf][3], sb + FQ_H + ad);
        ldsm4(qal[kf][0], qal[kf][1], qal[kf][2], qal[kf][3], sb + FQ_L + ad);
    }

    float m[2] = {-1e30f, -1e30f};
    float l[2] = {0.0f, 0.0f};
    float acc[8][4];
#pragma unroll
    for (int i = 0; i < 8; i++)
#pragma unroll
        for (int r = 0; r < 4; r++) acc[i][r] = 0.0f;

    for (int kt = 0; kt <= kt_end; kt++) {
        const int st = kt % 3;
        if (kt + 2 <= kt_end) {
            load_stage(kt + 2, (kt + 2) % 3);
            CP_WAIT(2);
        } else if (kt + 1 <= kt_end) {
            CP_WAIT(1);
        } else {
            CP_WAIT(0);
        }
        __syncthreads();

        const int row_lo = q0 + warp_m;
        const bool any  = (kt * 64     <= row_lo + 15);
        const bool full = (kt * 64 + 63 <= row_lo);

        if (any) {
            const uint32_t sKh = sb + FSTG(st) + 0 * FTILE64;
            const uint32_t sKl = sb + FSTG(st) + 1 * FTILE64;
            const uint32_t sVh = sb + FSTG(st) + 2 * FTILE64;
            const uint32_t sVl = sb + FSTG(st) + 3 * FTILE64;

            float sf[8][4];
#pragma unroll
            for (int nf = 0; nf < 8; nf++)
#pragma unroll
                for (int r = 0; r < 4; r++) sf[nf][r] = 0.0f;

#pragma unroll
            for (int kf = 0; kf < 4; kf++) {
                const int kc = kf * 16;
#pragma unroll
                for (int np = 0; np < 4; np++) {
                    uint32_t bd = ((np * 16 + b4_r) * FSTR + kc + b4_c) * 2;
                    uint32_t kbh[4], kbl[4];
                    ldsm4(kbh[0], kbh[1], kbh[2], kbh[3], sKh + bd);
                    ldsm4(kbl[0], kbl[1], kbl[2], kbl[3], sKl + bd);
                    mma_bf16(sf[np * 2],     qah[kf], kbh);
                    mma_bf16(sf[np * 2],     qah[kf], kbl);
                    mma_bf16(sf[np * 2],     qal[kf], kbh);
                    mma_bf16(sf[np * 2 + 1], qah[kf], kbh + 2);
                    mma_bf16(sf[np * 2 + 1], qah[kf], kbl + 2);
                    mma_bf16(sf[np * 2 + 1], qal[kf], kbh + 2);
                }
            }

            if (!full) {
                const int i0 = row_lo + er;
#pragma unroll
                for (int nf = 0; nf < 8; nf++) {
                    int j0 = kt * 64 + nf * 8 + ec;
                    if (j0     > i0)     sf[nf][0] = -1e30f;
                    if (j0 + 1 > i0)     sf[nf][1] = -1e30f;
                    if (j0     > i0 + 8) sf[nf][2] = -1e30f;
                    if (j0 + 1 > i0 + 8) sf[nf][3] = -1e30f;
                }
            }

            float rmax0 = -1e30f, rmax1 = -1e30f;
#pragma unroll
            for (int nf = 0; nf < 8; nf++) {
                rmax0 = fmaxf(rmax0, fmaxf(sf[nf][0], sf[nf][1]));
                rmax1 = fmaxf(rmax1, fmaxf(sf[nf][2], sf[nf][3]));
            }
            rmax0 = fmaxf(rmax0, __shfl_xor_sync(0xffffffffu, rmax0, 1));
            rmax0 = fmaxf(rmax0, __shfl_xor_sync(0xffffffffu, rmax0, 2));
            rmax1 = fmaxf(rmax1, __shfl_xor_sync(0xffffffffu, rmax1, 1));
            rmax1 = fmaxf(rmax1, __shfl_xor_sync(0xffffffffu, rmax1, 2));

            float nm0 = fmaxf(m[0], rmax0), nm1 = fmaxf(m[1], rmax1);
            float al0 = exp2f(m[0] - nm0), al1 = exp2f(m[1] - nm1);
            m[0] = nm0; m[1] = nm1;

            float sum0 = 0.0f, sum1 = 0.0f;
#pragma unroll
            for (int nf = 0; nf < 8; nf++) {
                sf[nf][0] = exp2f(sf[nf][0] - nm0);
                sf[nf][1] = exp2f(sf[nf][1] - nm0);
                sf[nf][2] = exp2f(sf[nf][2] - nm1);
                sf[nf][3] = exp2f(sf[nf][3] - nm1);
                sum0 += sf[nf][0] + sf[nf][1];
                sum1 += sf[nf][2] + sf[nf][3];
            }
            sum0 += __shfl_xor_sync(0xffffffffu, sum0, 1);
            sum0 += __shfl_xor_sync(0xffffffffu, sum0, 2);
            sum1 += __shfl_xor_sync(0xffffffffu, sum1, 1);
            sum1 += __shfl_xor_sync(0xffffffffu, sum1, 2);
            l[0] = l[0] * al0 + sum0;
            l[1] = l[1] * al1 + sum1;
#pragma unroll
            for (int i = 0; i < 8; i++) {
                acc[i][0] *= al0; acc[i][1] *= al0;
                acc[i][2] *= al1; acc[i][3] *= al1;
            }

            uint32_t pha[4][4];
#pragma unroll
            for (int kf = 0; kf < 4; kf++) {
#pragma unroll
                for (int half = 0; half < 2; half++) {
                    const float* s2 = sf[kf * 2 + half];
                    __half2 h01 = __floats2half2_rn(s2[0], s2[1]);
                    __half2 h23 = __floats2half2_rn(s2[2], s2[3]);
                    pha[kf][half * 2 + 0] = *(uint32_t*)&h01;
                    pha[kf][half * 2 + 1] = *(uint32_t*)&h23;
                }
            }

#pragma unroll
            for (int kf = 0; kf < 4; kf++) {
#pragma unroll
                for (int np = 0; np < 4; np++) {
                    uint32_t bd = ((np * 16 + b4_r) * FSTR + kf * 16 + b4_c) * 2;
                    uint32_t vbh[4], vbl[4];
                    ldsm4(vbh[0], vbh[1], vbh[2], vbh[3], sVh + bd);
                    ldsm4(vbl[0], vbl[1], vbl[2], vbl[3], sVl + bd);
                    mma_f16(acc[np * 2],     pha[kf], vbh);
                    mma_f16(acc[np * 2],     pha[kf], vbl);
                    mma_f16(acc[np * 2 + 1], pha[kf], vbh + 2);
                    mma_f16(acc[np * 2 + 1], pha[kf], vbl + 2);
                }
            }
        }
        __syncthreads();
    }

    // normalize + write single fp16 output
    float inv0 = 1.0f / l[0], inv1 = 1.0f / l[1];
#pragma unroll
    for (int nf = 0; nf < 8; nf++) {
        size_t o0 = ((size_t)(b * SS + q0 + warp_m + er) * NH + h) * HD + nf * 8 + ec;
        size_t o1 = ((size_t)(b * SS + q0 + warp_m + er + 8) * NH + h) * HD + nf * 8 + ec;
        __half2 h0 = __floats2half2_rn(acc[nf][0] * inv0, acc[nf][1] * inv0);
        __half2 h1 = __floats2half2_rn(acc[nf][2] * inv1, acc[nf][3] * inv1);
        *(uint32_t*)(Of + o0) = *(uint32_t*)&h0;
        *(uint32_t*)(Of + o1) = *(uint32_t*)&h1;
    }
}

// ---------------------------------------------------------------------------
extern "C" void kernel_launch(void* const* d_in, const int* in_sizes, int n_in,
                              void* d_out, int out_size)
{
    const float* x    = (const float*)d_in[0];
    const float* cosb = (const float*)d_in[1];
    const float* sinb = (const float*)d_in[2];
    const float* wq   = (const float*)d_in[3];
    const float* wk   = (const float*)d_in[4];
    const float* wv   = (const float*)d_in[5];
    const float* wo   = (const float*)d_in[6];
    float* out = (float*)d_out;

    __nv_bfloat16 *xh, *xl, *wqkvh, *wqkvl;
    __nv_bfloat16 *qh, *ql, *kh2, *kl2;
    __half *of, *woh, *wol, *vth, *vtl;
    cudaGetSymbolAddress((void**)&xh, g_xh);
    cudaGetSymbolAddress((void**)&xl, g_xl);
    cudaGetSymbolAddress((void**)&of, g_of);
    cudaGetSymbolAddress((void**)&wqkvh, g_wqkvh);
    cudaGetSymbolAddress((void**)&wqkvl, g_wqkvl);
    cudaGetSymbolAddress((void**)&woh, g_woh);
    cudaGetSymbolAddress((void**)&wol, g_wol);
    cudaGetSymbolAddress((void**)&qh, g_qh);
    cudaGetSymbolAddress((void**)&ql, g_ql);
    cudaGetSymbolAddress((void**)&kh2, g_kh2);
    cudaGetSymbolAddress((void**)&kl2, g_kl2);
    cudaGetSymbolAddress((void**)&vth, g_vth);
    cudaGetSymbolAddress((void**)&vtl, g_vtl);

    cudaFuncSetAttribute(gemm_qkv_kernel,
                         cudaFuncAttributeMaxDynamicSharedMemorySize, GEMM_SMEM);
    cudaFuncSetAttribute(gemm_out_f16_kernel,
                         cudaFuncAttributeMaxDynamicSharedMemorySize, OUT_SMEM);
    cudaFuncSetAttribute(flash_hmma_kernel,
                         cudaFuncAttributeMaxDynamicSharedMemorySize, FLASH_SMEM);

    const int M = BB * SS;  // 4096

    // Fused prep: x split + weight transposes (wo in fp16), one launch
    prep_kernel<<<SPLIT_BLOCKS + 2560, 256>>>(
        (const float4*)x, (__nv_bfloat162*)xh, (__nv_bfloat162*)xl,
        wq, wk, wv, wo, wqkvh, wqkvl, woh, wol);

    // QKV projection (bf16x3) + RoPE/split/V-transpose epilogue
    gemm_qkv_kernel<<<dim3(NQKV / 128, M / 128), 256, GEMM_SMEM>>>(
        xh, xl, wqkvh, wqkvl, cosb, sinb, qh, ql, kh2, kl2, vth, vtl);

    // Causal GQA flash attention (3-stage, Q in regs, fp16 PV, fp16 out)
    flash_hmma_kernel<<<dim3(SS / 128, NH, BB), 256, FLASH_SMEM>>>(
        qh, ql, kh2, kl2, vth, vtl, of);

    // Output projection (fp16 2-term)
    gemm_out_f16_kernel<<<dim3(DMODEL / 128, M / 128), 256, OUT_SMEM>>>(
        of, woh, wol, out, M, DMODEL, DMODEL);
}

// round 16
// speedup vs baseline: 1.2150x; 1.0036x over previous
#include <cuda_runtime.h>
#include <cuda_bf16.h>
#include <cuda_fp16.h>
#include <cstdint>
#include <math.h>

#define BB 2
#define SS 2048
#define DMODEL 1024
#define NH 16
#define NKH 4
#define HD 64
#define NQKV 1536

// ---------------------------------------------------------------------------
// Scratch (device globals: allocation-free)
// ---------------------------------------------------------------------------
__device__ __nv_bfloat16 g_xh[BB * SS * DMODEL];
__device__ __nv_bfloat16 g_xl[BB * SS * DMODEL];
__device__ __half        g_of[BB * SS * NH * HD];
__device__ __nv_bfloat16 g_wqkvh[NQKV * DMODEL];
__device__ __nv_bfloat16 g_wqkvl[NQKV * DMODEL];
__device__ __half        g_woh[DMODEL * (NH * HD)];
__device__ __half        g_wol[DMODEL * (NH * HD)];

__device__ __nv_bfloat16 g_qh[BB * SS * NH * HD];
__device__ __nv_bfloat16 g_ql[BB * SS * NH * HD];
__device__ __nv_bfloat16 g_kh2[BB * SS * NKH * HD];
__device__ __nv_bfloat16 g_kl2[BB * SS * NKH * HD];
__device__ __half g_vth[BB * NKH * HD * SS];   // [b][kh][d][s]
__device__ __half g_vtl[BB * NKH * HD * SS];

// ---------------------------------------------------------------------------
// Warp-level MMA helpers
// ---------------------------------------------------------------------------
__device__ __forceinline__ uint32_t smem_u32(const void* p) {
    uint32_t a;
    asm("{ .reg .u64 t; cvta.to.shared.u64 t, %1; cvt.u32.u64 %0, t; }"
        : "=r"(a) : "l"(p));
    return a;
}

__device__ __forceinline__ void ldsm4(uint32_t& r0, uint32_t& r1,
                                      uint32_t& r2, uint32_t& r3, uint32_t a) {
    asm volatile("ldmatrix.sync.aligned.m8n8.x4.shared.b16 {%0,%1,%2,%3}, [%4];"
                 : "=r"(r0), "=r"(r1), "=r"(r2), "=r"(r3) : "r"(a));
}

__device__ __forceinline__ void mma_bf16(float* c, const uint32_t* a,
                                         const uint32_t* b) {
    asm volatile(
        "mma.sync.aligned.m16n8k16.row.col.f32.bf16.bf16.f32 "
        "{%0,%1,%2,%3}, {%4,%5,%6,%7}, {%8,%9}, {%0,%1,%2,%3};"
        : "+f"(c[0]), "+f"(c[1]), "+f"(c[2]), "+f"(c[3])
        : "r"(a[0]), "r"(a[1]), "r"(a[2]), "r"(a[3]), "r"(b[0]), "r"(b[1]));
}

__device__ __forceinline__ void mma_f16(float* c, const uint32_t* a,
                                        const uint32_t* b) {
    asm volatile(
        "mma.sync.aligned.m16n8k16.row.col.f32.f16.f16.f32 "
        "{%0,%1,%2,%3}, {%4,%5,%6,%7}, {%8,%9}, {%0,%1,%2,%3};"
        : "+f"(c[0]), "+f"(c[1]), "+f"(c[2]), "+f"(c[3])
        : "r"(a[0]), "r"(a[1]), "r"(a[2]), "r"(a[3]), "r"(b[0]), "r"(b[1]));
}

#define CP_ASYNC16(sa, ga) \
    asm volatile("cp.async.cg.shared.global [%0], [%1], 16;" \
                 :: "r"(sa), "l"(ga))
#define CP_COMMIT() asm volatile("cp.async.commit_group;")
#define CP_WAIT(N)  asm volatile("cp.async.wait_group %0;" :: "n"(N))

// ---------------------------------------------------------------------------
// GEMM common config
// ---------------------------------------------------------------------------
#define BK 32
#define GSTRIDE 40
#define GTILE_B (128 * GSTRIDE * 2)
#define GOFF(t, st) (((st) * 4 + (t)) * GTILE_B)
#define GEMM_SMEM (8 * GTILE_B)
#define OOFF(t, st) (((st) * 3 + (t)) * GTILE_B)
#define OUT_SMEM (9 * GTILE_B)                       // 3-stage x 3 tiles
#define TSTR 132

// bf16x3 mainloop with dependency-broken MMA order.
#define GEMM_MAINLOOP(OUT_ACC)                                                \
    float OUT_ACC[4][4][4];                                                   \
    _Pragma("unroll")                                                         \
    for (int i = 0; i < 4; i++)                                               \
        _Pragma("unroll")                                                     \
        for (int j = 0; j < 4; j++)                                           \
            _Pragma("unroll")                                                 \
            for (int r = 0; r < 4; r++) OUT_ACC[i][j][r] = 0.0f;              \
    const int nchunk = K / BK;                                                \
    load_stage(0, 0);                                                         \
    const int a_r = lane & 15;                                                \
    const int a_c = (lane >> 4) * 8;                                          \
    const int g4 = lane >> 3;                                                 \
    const int b4_r = (g4 >> 1) * 8 + (lane & 7);                              \
    const int b4_c = (g4 & 1) * 8;                                            \
    for (int c = 0; c < nchunk; c++) {                                        \
        const int st = c & 1;                                                 \
        if (c + 1 < nchunk) { load_stage(c + 1, st ^ 1); CP_WAIT(1); }        \
        else { CP_WAIT(0); }                                                  \
        __syncthreads();                                                      \
        const uint32_t sAh = sb + GOFF(0, st);                                \
        const uint32_t sAl = sb + GOFF(1, st);                                \
        const uint32_t sBh = sb + GOFF(2, st);                                \
        const uint32_t sBl = sb + GOFF(3, st);                                \
        _Pragma("unroll")                                                     \
        for (int kf = 0; kf < 2; kf++) {                                      \
            const int kc = kf * 16;                                           \
            uint32_t ah[4][4], al[4][4], bh[4][2], bl[4][2];                  \
            _Pragma("unroll")                                                 \
            for (int mf = 0; mf < 4; mf++) {                                  \
                uint32_t ad = ((warp_m + mf * 16 + a_r) * GSTRIDE + kc + a_c) * 2; \
                ldsm4(ah[mf][0], ah[mf][1], ah[mf][2], ah[mf][3], sAh + ad);  \
            }                                                                 \
            _Pragma("unroll")                                                 \
            for (int np = 0; np < 2; np++) {                                  \
                uint32_t bd = ((warp_n + np * 16 + b4_r) * GSTRIDE + kc + b4_c) * 2; \
                ldsm4(bh[np * 2][0], bh[np * 2][1],                           \
                      bh[np * 2 + 1][0], bh[np * 2 + 1][1], sBh + bd);        \
                ldsm4(bl[np * 2][0], bl[np * 2][1],                           \
                      bl[np * 2 + 1][0], bl[np * 2 + 1][1], sBl + bd);        \
            }                                                                 \
            _Pragma("unroll")                                                 \
            for (int mf = 0; mf < 4; mf++)                                    \
                _Pragma("unroll")                                             \
                for (int nf = 0; nf < 4; nf++)                                \
                    mma_bf16(OUT_ACC[mf][nf], ah[mf], bh[nf]);                \
            _Pragma("unroll")                                                 \
            for (int mf = 0; mf < 4; mf++) {                                  \
                uint32_t ad = ((warp_m + mf * 16 + a_r) * GSTRIDE + kc + a_c) * 2; \
                ldsm4(al[mf][0], al[mf][1], al[mf][2], al[mf][3], sAl + ad);  \
            }                                                                 \
            _Pragma("unroll")                                                 \
            for (int mf = 0; mf < 4; mf++)                                    \
                _Pragma("unroll")                                             \
                for (int nf = 0; nf < 4; nf++)                                \
                    mma_bf16(OUT_ACC[mf][nf], ah[mf], bl[nf]);                \
            _Pragma("unroll")                                                 \
            for (int mf = 0; mf < 4; mf++)                                    \
                _Pragma("unroll")                                             \
                for (int nf = 0; nf < 4; nf++)                                \
                    mma_bf16(OUT_ACC[mf][nf], al[mf], bh[nf]);                \
        }                                                                     \
        __syncthreads();                                                      \
    }

// ---------------------------------------------------------------------------
// Out-projection GEMM: fp16 2-term, 3-stage pipeline, dependency-broken.
// ---------------------------------------------------------------------------
__global__ __launch_bounds__(256, 2) void gemm_out_f16_kernel(
    const __half* __restrict__ Af,
    const __half* __restrict__ Bh, const __half* __restrict__ Bl,
    float* __restrict__ C, int M, int N, int K)
{
    extern __shared__ __align__(128) char smem[];
    const uint32_t sb = smem_u32(smem);
    const int tid = threadIdx.x;
    const int wid = tid >> 5;
    const int lane = tid & 31;
    const int bm = blockIdx.y * 128;
    const int bn = blockIdx.x * 128;
    const int warp_m = (wid >> 2) * 64;
    const int warp_n = (wid & 3) * 32;

    const __half* gp[3] = {
        Af + (size_t)bm * K, Bh + (size_t)bn * K, Bl + (size_t)bn * K };

    const int lrow0 = tid >> 2;
    const int lq = tid & 3;

    auto load_stage = [&](int c, int st) {
#pragma unroll
        for (int t = 0; t < 3; t++) {
            const __half* P = gp[t] + (size_t)c * BK;
#pragma unroll
            for (int it = 0; it < 2; it++) {
                int row = lrow0 + it * 64;
                uint32_t sa = sb + OOFF(t, st) + (row * GSTRIDE + lq * 8) * 2;
                CP_ASYNC16(sa, P + (size_t)row * K + lq * 8);
            }
        }
        CP_COMMIT();
    };

    float acc[4][4][4];
#pragma unroll
    for (int i = 0; i < 4; i++)
#pragma unroll
        for (int j = 0; j < 4; j++)
#pragma unroll
            for (int r = 0; r < 4; r++) acc[i][j][r] = 0.0f;

    const int nchunk = K / BK;
    load_stage(0, 0);
    load_stage(1, 1);

    const int a_r = lane & 15;
    const int a_c = (lane >> 4) * 8;
    const int g4 = lane >> 3;
    const int b4_r = (g4 >> 1) * 8 + (lane & 7);
    const int b4_c = (g4 & 1) * 8;

    for (int c = 0; c < nchunk; c++) {
        const int st = c % 3;
        if (c + 2 < nchunk) { load_stage(c + 2, (c + 2) % 3); CP_WAIT(2); }
        else if (c + 1 < nchunk) { CP_WAIT(1); }
        else { CP_WAIT(0); }
        __syncthreads();

        const uint32_t sAf = sb + OOFF(0, st);
        const uint32_t sBh = sb + OOFF(1, st);
        const uint32_t sBl = sb + OOFF(2, st);

#pragma unroll
        for (int kf = 0; kf < 2; kf++) {
            const int kc = kf * 16;
            uint32_t af[4][4], bh[4][2], bl[4][2];
#pragma unroll
            for (int mf = 0; mf < 4; mf++) {
                uint32_t ad = ((warp_m + mf * 16 + a_r) * GSTRIDE + kc + a_c) * 2;
                ldsm4(af[mf][0], af[mf][1], af[mf][2], af[mf][3], sAf + ad);
            }
#pragma unroll
            for (int np = 0; np < 2; np++) {
                uint32_t bd = ((warp_n + np * 16 + b4_r) * GSTRIDE + kc + b4_c) * 2;
                ldsm4(bh[np * 2][0], bh[np * 2][1],
                      bh[np * 2 + 1][0], bh[np * 2 + 1][1], sBh + bd);
                ldsm4(bl[np * 2][0], bl[np * 2][1],
                      bl[np * 2 + 1][0], bl[np * 2 + 1][1], sBl + bd);
            }
#pragma unroll
            for (int mf = 0; mf < 4; mf++)
#pragma unroll
                for (int nf = 0; nf < 4; nf++)
                    mma_f16(acc[mf][nf], af[mf], bh[nf]);
#pragma unroll
            for (int mf = 0; mf < 4; mf++)
#pragma unroll
                for (int nf = 0; nf < 4; nf++)
                    mma_f16(acc[mf][nf], af[mf], bl[nf]);
        }
        __syncthreads();
    }

    const int er = lane >> 2;
    const int ec = (lane & 3) * 2;
#pragma unroll
    for (int mf = 0; mf < 4; mf++) {
#pragma unroll
        for (int nf = 0; nf < 4; nf++) {
            float* base = C + (size_t)(bm + warp_m + mf * 16 + er) * N
                            + bn + warp_n + nf * 8 + ec;
            *(float2*)base = make_float2(acc[mf][nf][0], acc[mf][nf][1]);
            *(float2*)(base + 8 * N) = make_float2(acc[mf][nf][2], acc[mf][nf][3]);
        }
    }
}

// ---------------------------------------------------------------------------
// QKV GEMM (bf16x3) with fused RoPE/split/V epilogue.
// ---------------------------------------------------------------------------
__global__ __launch_bounds__(256, 2) void gemm_qkv_kernel(
    const __nv_bfloat16* __restrict__ Ah, const __nv_bfloat16* __restrict__ Al,
    const __nv_bfloat16* __restrict__ Bh, const __nv_bfloat16* __restrict__ Bl,
    const float* __restrict__ cosb, const float* __restrict__ sinb,
    __nv_bfloat16* __restrict__ qh, __nv_bfloat16* __restrict__ ql,
    __nv_bfloat16* __restrict__ khp, __nv_bfloat16* __restrict__ klp,
    __half* __restrict__ vh, __half* __restrict__ vl)
{
    extern __shared__ __align__(128) char smem[];
    const uint32_t sb = smem_u32(smem);
    const int tid = threadIdx.x;
    const int wid = tid >> 5;
    const int lane = tid & 31;
    const int bm = blockIdx.y * 128;
    const int bn = blockIdx.x * 128;
    const int warp_m = (wid >> 2) * 64;
    const int warp_n = (wid & 3) * 32;
    const int K = DMODEL;

    const __nv_bfloat16* gp[4] = {
        Ah + (size_t)bm * K, Al + (size_t)bm * K,
        Bh + (size_t)bn * K, Bl + (size_t)bn * K };

    const int lrow0 = tid >> 2;
    const int lq = tid & 3;

    auto load_stage = [&](int c, int st) {
#pragma unroll
        for (int t = 0; t < 4; t++) {
            const __nv_bfloat16* P = gp[t] + (size_t)c * BK;
#pragma unroll
            for (int it = 0; it < 2; it++) {
                int row = lrow0 + it * 64;
                uint32_t sa = sb + GOFF(t, st) + (row * GSTRIDE + lq * 8) * 2;
                CP_ASYNC16(sa, P + (size_t)row * K + lq * 8);
            }
        }
        CP_COMMIT();
    };

    GEMM_MAINLOOP(acc)

    float* Ts = (float*)smem;
    const int er = lane >> 2;
    const int ec = (lane & 3) * 2;
#pragma unroll
    for (int mf = 0; mf < 4; mf++) {
#pragma unroll
        for (int nf = 0; nf < 4; nf++) {
            int r = warp_m + mf * 16 + er;
            int c = warp_n + nf * 8 + ec;
            *(float2*)&Ts[r * TSTR + c] = make_float2(acc[mf][nf][0], acc[mf][nf][1]);
            *(float2*)&Ts[(r + 8) * TSTR + c] = make_float2(acc[mf][nf][2], acc[mf][nf][3]);
        }
    }
    __syncthreads();

    if (bn < 1280) {
        const bool isq = (bn < 1024);
        const float scl = isq ? 0.125f * 1.4426950408889634f : 1.0f;
        __nv_bfloat16* th = isq ? qh : khp;
        __nv_bfloat16* tl = isq ? ql : klp;
        const int nheads = isq ? NH : NKH;
        const int h0 = isq ? (bn >> 6) : ((bn - 1024) >> 6);

#pragma unroll
        for (int it = 0; it < 8; it++) {
            int idx = tid + it * 256;
            int d0 = (idx & 7) * 4;
            int hh = (idx >> 3) & 1;
            int row = idx >> 4;
            int bs = bm + row;
            int s = bs & (SS - 1);

            const float* tr = &Ts[row * TSTR + hh * 64];
            float4 v0 = *(const float4*)(tr + d0);
            float4 v1 = *(const float4*)(tr + d0 + 32);
            float4 c0 = *(const float4*)(cosb + s * HD + d0);
            float4 c1 = *(const float4*)(cosb + s * HD + d0 + 32);
            float4 s0v = *(const float4*)(sinb + s * HD + d0);
            float4 s1v = *(const float4*)(sinb + s * HD + d0 + 32);

            float r0x = (v0.x * c0.x - v1.x * s0v.x) * scl;
            float r0y = (v0.y * c0.y - v1.y * s0v.y) * scl;
            float r0z = (v0.z * c0.z - v1.z * s0v.z) * scl;
            float r0w = (v0.w * c0.w - v1.w * s0v.w) * scl;
            float r1x = (v1.x * c1.x + v0.x * s1v.x) * scl;
            float r1y = (v1.y * c1.y + v0.y * s1v.y) * scl;
            float r1z = (v1.z * c1.z + v0.z * s1v.z) * scl;
            float r1w = (v1.w * c1.w + v0.w * s1v.w) * scl;

            size_t base = ((size_t)bs * nheads + h0 + hh) * HD;

            __nv_bfloat162 h0a = __float22bfloat162_rn(make_float2(r0x, r0y));
            __nv_bfloat162 h0b = __float22bfloat162_rn(make_float2(r0z, r0w));
            __nv_bfloat162 h1a = __float22bfloat162_rn(make_float2(r1x, r1y));
            __nv_bfloat162 h1b = __float22bfloat162_rn(make_float2(r1z, r1w));
            *(uint2*)(th + base + d0)      = make_uint2(*(uint32_t*)&h0a, *(uint32_t*)&h0b);
            *(uint2*)(th + base + d0 + 32) = make_uint2(*(uint32_t*)&h1a, *(uint32_t*)&h1b);

            __nv_bfloat162 l0a = __float22bfloat162_rn(make_float2(
                r0x - __bfloat162float(h0a.x), r0y - __bfloat162float(h0a.y)));
            __nv_bfloat162 l0b = __float22bfloat162_rn(make_float2(
                r0z - __bfloat162float(h0b.x), r0w - __bfloat162float(h0b.y)));
            __nv_bfloat162 l1a = __float22bfloat162_rn(make_float2(
                r1x - __bfloat162float(h1a.x), r1y - __bfloat162float(h1a.y)));
            __nv_bfloat162 l1b = __float22bfloat162_rn(make_float2(
                r1z - __bfloat162float(h1b.x), r1w - __bfloat162float(h1b.y)));
            *(uint2*)(tl + base + d0)      = make_uint2(*(uint32_t*)&l0a, *(uint32_t*)&l0b);
            *(uint2*)(tl + base + d0 + 32) = make_uint2(*(uint32_t*)&l1a, *(uint32_t*)&l1b);
        }
    } else {
        const int c = tid & 127;
        const int sh = tid >> 7;
        const int khead = ((bn - 1280) >> 6) + (c >> 6);
        const int d = c & 63;
        const int b = bm >> 11;
        const int s0 = (bm & (SS - 1)) + sh * 64;
        size_t base = ((size_t)(b * NKH + khead) * HD + d) * SS + s0;

#pragma unroll 4
        for (int s4 = 0; s4 < 64; s4 += 4) {
            float v0 = Ts[(sh * 64 + s4 + 0) * TSTR + c];
            float v1 = Ts[(sh * 64 + s4 + 1) * TSTR + c];
            float v2 = Ts[(sh * 64 + s4 + 2) * TSTR + c];
            float v3 = Ts[(sh * 64 + s4 + 3) * TSTR + c];
            __half2 p01 = __floats2half2_rn(v0, v1);
            __half2 p23 = __floats2half2_rn(v2, v3);
            *(uint2*)(vh + base + s4) = make_uint2(*(uint32_t*)&p01, *(uint32_t*)&p23);
            __half2 q01 = __floats2half2_rn(v0 - __low2float(p01), v1 - __high2float(p01));
            __half2 q23 = __floats2half2_rn(v2 - __low2float(p23), v3 - __high2float(p23));
            *(uint2*)(vl + base + s4) = make_uint2(*(uint32_t*)&q01, *(uint32_t*)&q23);
        }
    }
}

// ---------------------------------------------------------------------------
// Fused prep.
// ---------------------------------------------------------------------------
#define SPLIT_BLOCKS 4096

__global__ void prep_kernel(
    const float4* __restrict__ x4,
    __nv_bfloat162* __restrict__ xh2, __nv_bfloat162* __restrict__ xl2,
    const float* __restrict__ wq, const float* __restrict__ wk,
    const float* __restrict__ wv, const float* __restrict__ wo,
    __nv_bfloat16* __restrict__ wqkvh, __nv_bfloat16* __restrict__ wqkvl,
    __half* __restrict__ woh, __half* __restrict__ wol)
{
    __shared__ float t[32][33];
    const int tid = threadIdx.x;

    if (blockIdx.x < SPLIT_BLOCKS) {
        int i = blockIdx.x * 256 + tid;
        float4 v = x4[i];
        __nv_bfloat16 h0 = __float2bfloat16(v.x);
        __nv_bfloat16 h1 = __float2bfloat16(v.y);
        __nv_bfloat16 h2 = __float2bfloat16(v.z);
        __nv_bfloat16 h3 = __float2bfloat16(v.w);
        xh2[2 * i]     = __nv_bfloat162(h0, h1);
        xh2[2 * i + 1] = __nv_bfloat162(h2, h3);
        xl2[2 * i]     = __nv_bfloat162(
            __float2bfloat16(v.x - __bfloat162float(h0)),
            __float2bfloat16(v.y - __bfloat162float(h1)));
        xl2[2 * i + 1] = __nv_bfloat162(
            __float2bfloat16(v.z - __bfloat162float(h2)),
            __float2bfloat16(v.w - __bfloat162float(h3)));
    } else {
        const int tile = blockIdx.x - SPLIT_BLOCKS;
        const float* src;
        int N, tloc, iswo = 0;
        __nv_bfloat16 *dh = nullptr, *dl = nullptr;
        if (tile < 1024)      { src = wq; dh = wqkvh;                  dl = wqkvl;                  N = 1024; tloc = tile; }
        else if (tile < 1280) { src = wk; dh = wqkvh + 1024 * DMODEL;  dl = wqkvl + 1024 * DMODEL;  N = 256;  tloc = tile - 1024; }
        else if (tile < 1536) { src = wv; dh = wqkvh + 1280 * DMODEL;  dl = wqkvl + 1280 * DMODEL;  N = 256;  tloc = tile - 1280; }
        else                  { src = wo; iswo = 1;                                                 N = 1024; tloc = tile - 1536; }
        const int nx = N >> 5;
        const int K = 1024;
        const int n0 = (tloc % nx) * 32;
        const int k0 = (tloc / nx) * 32;
        const int tx = tid & 31, ty = tid >> 5;
#pragma unroll
        for (int i = 0; i < 32; i += 8)
            t[ty + i][tx] = src[(size_t)(k0 + ty + i) * N + n0 + tx];
        __syncthreads();
#pragma unroll
        for (int i = 0; i < 32; i += 8) {
            float v = t[tx][ty + i];
            size_t o = (size_t)(n0 + ty + i) * K + k0 + tx;
            if (iswo) {
                __half h = __float2half_rn(v);
                woh[o] = h;
                wol[o] = __float2half_rn(v - __half2float(h));
            } else {
                __nv_bfloat16 h = __float2bfloat16(v);
                dh[o] = h;
                dl[o] = __float2bfloat16(v - __bfloat162float(h));
            }
        }
    }
}

// ---------------------------------------------------------------------------
// HMMA flash attention, causal, GQA.
// BM=128 (8 warps), BN=64; 3-stage; exp2; LPT; Q in regs.
// S: bf16x3 (dependency-broken); PV: fp16 2-term (dependency-broken).
// ---------------------------------------------------------------------------
#define FSTR 72
#define FTILE64 (64 * FSTR * 2)
#define FQ_TILE (128 * FSTR * 2)
#define FQ_H 0
#define FQ_L FQ_TILE
#define FSTG(st) (2 * FQ_TILE + (st) * 4 * FTILE64)
#define FLASH_SMEM (2 * FQ_TILE + 3 * 4 * FTILE64)   // 147456 B

__global__ __launch_bounds__(256) void flash_hmma_kernel(
    const __nv_bfloat16* __restrict__ Qh, const __nv_bfloat16* __restrict__ Ql,
    const __nv_bfloat16* __restrict__ Kh, const __nv_bfloat16* __restrict__ Kl,
    const __half* __restrict__ Vth, const __half* __restrict__ Vtl,
    __half* __restrict__ Of)
{
    extern __shared__ __align__(128) char smem[];
    const uint32_t sb = smem_u32(smem);
    const int tid = threadIdx.x;
    const int wid = tid >> 5;
    const int lane = tid & 31;
    const int qt = gridDim.x - 1 - blockIdx.x;   // LPT
    const int h  = blockIdx.y;
    const int b  = blockIdx.z;
    const int q0 = qt * 128;
    const int khead = h >> 2;
    const int warp_m = wid * 16;

    const int er = lane >> 2;
    const int ec = (lane & 3) * 2;
    const int a_r = lane & 15;
    const int a_c = (lane >> 4) * 8;
    const int g4 = lane >> 3;
    const int b4_r = (g4 >> 1) * 8 + (lane & 7);
    const int b4_c = (g4 & 1) * 8;

    const __nv_bfloat16* qh_g = Qh + ((size_t)(b * SS + q0) * NH + h) * HD;
    const __nv_bfloat16* ql_g = Ql + ((size_t)(b * SS + q0) * NH + h) * HD;
    const __nv_bfloat16* kh_g = Kh + ((size_t)b * SS * NKH + khead) * HD;
    const __nv_bfloat16* kl_g = Kl + ((size_t)b * SS * NKH + khead) * HD;
    const __half* vth_g = Vth + (size_t)(b * NKH + khead) * HD * SS;
    const __half* vtl_g = Vtl + (size_t)(b * NKH + khead) * HD * SS;

    auto load_tile64 = [&](const void* g, size_t rstride_elt, uint32_t sofs) {
#pragma unroll
        for (int it = 0; it < 2; it++) {
            int ch = tid + it * 256;
            int r = ch >> 3;
            int q8 = ch & 7;
            CP_ASYNC16(sb + sofs + (r * FSTR + q8 * 8) * 2,
                       (const char*)g + ((size_t)r * rstride_elt + q8 * 8) * 2);
        }
    };
    auto load_q = [&](const __nv_bfloat16* g, uint32_t sofs) {
#pragma unroll
        for (int it = 0; it < 4; it++) {
            int ch = tid + it * 256;
            int r = ch >> 3;
            int q8 = ch & 7;
            CP_ASYNC16(sb + sofs + (r * FSTR + q8 * 8) * 2,
                       g + (size_t)r * (NH * HD) + q8 * 8);
        }
    };
    auto load_stage = [&](int kt, int st) {
        const int kn = kt * 64;
        load_tile64(kh_g + (size_t)kn * NKH * HD, NKH * HD, FSTG(st) + 0 * FTILE64);
        load_tile64(kl_g + (size_t)kn * NKH * HD, NKH * HD, FSTG(st) + 1 * FTILE64);
        load_tile64(vth_g + kn, SS, FSTG(st) + 2 * FTILE64);
        load_tile64(vtl_g + kn, SS, FSTG(st) + 3 * FTILE64);
        CP_COMMIT();
    };

    const int kt_end = 2 * qt + 1;

    load_q(qh_g, FQ_H);
    load_q(ql_g, FQ_L);
    CP_COMMIT();
    load_stage(0, 0);
    if (kt_end >= 1) { load_stage(1, 1); CP_WAIT(2); }
    else             { CP_WAIT(1); }
    __syncthreads();

    uint32_t qah[4][4], qal[4][4];
#pragma unroll
    for (int kf = 0; kf < 4; kf++) {
        uint32_t ad = ((warp_m + a_r) * FSTR + kf * 16 + a_c) * 2;
        ldsm4(qah[kf][0], qah[kf][1], qah[kf][2], qah[kf][3], sb + FQ_H + ad);
        ldsm4(qal[kf][0], qal[kf][1], qal[kf][2], qal[kf][3], sb + FQ_L + ad);
    }

    float m[2] = {-1e30f, -1e30f};
    float l[2] = {0.0f, 0.0f};
    float acc[8][4];
#pragma unroll
    for (int i = 0; i < 8; i++)
#pragma unroll
        for (int r = 0; r < 4; r++) acc[i][r] = 0.0f;

    for (int kt = 0; kt <= kt_end; kt++) {
        const int st = kt % 3;
        if (kt + 2 <= kt_end) {
            load_stage(kt + 2, (kt + 2) % 3);
            CP_WAIT(2);
        } else if (kt + 1 <= kt_end) {
            CP_WAIT(1);
        } else {
            CP_WAIT(0);
        }
        __syncthreads();

        const int row_lo = q0 + warp_m;
        const bool any  = (kt * 64     <= row_lo + 15);
        const bool full = (kt * 64 + 63 <= row_lo);

        if (any) {
            const uint32_t sKh = sb + FSTG(st) + 0 * FTILE64;
            const uint32_t sKl = sb + FSTG(st) + 1 * FTILE64;
            const uint32_t sVh = sb + FSTG(st) + 2 * FTILE64;
            const uint32_t sVl = sb + FSTG(st) + 3 * FTILE64;

            float sf[8][4];
#pragma unroll
            for (int nf = 0; nf < 8; nf++)
#pragma unroll
                for (int r = 0; r < 4; r++) sf[nf][r] = 0.0f;

            // ---- S = Q K^T (bf16x3), term-outer ordering: no adjacent
            //      MMAs share an accumulator (8-apart reuse) ----
#pragma unroll
            for (int kf = 0; kf < 4; kf++) {
                const int kc = kf * 16;
                uint32_t kbh[4][4], kbl[4][4];
#pragma unroll
                for (int np = 0; np < 4; np++) {
                    uint32_t bd = ((np * 16 + b4_r) * FSTR + kc + b4_c) * 2;
                    ldsm4(kbh[np][0], kbh[np][1], kbh[np][2], kbh[np][3], sKh + bd);
                    ldsm4(kbl[np][0], kbl[np][1], kbl[np][2], kbl[np][3], sKl + bd);
                }
#pragma unroll
                for (int np = 0; np < 4; np++) {
                    mma_bf16(sf[np * 2],     qah[kf], kbh[np]);
                    mma_bf16(sf[np * 2 + 1], qah[kf], kbh[np] + 2);
                }
#pragma unroll
                for (int np = 0; np < 4; np++) {
                    mma_bf16(sf[np * 2],     qah[kf], kbl[np]);
                    mma_bf16(sf[np * 2 + 1], qah[kf], kbl[np] + 2);
                }
#pragma unroll
                for (int np = 0; np < 4; np++) {
                    mma_bf16(sf[np * 2],     qal[kf], kbh[np]);
                    mma_bf16(sf[np * 2 + 1], qal[kf], kbh[np] + 2);
                }
            }

            if (!full) {
                const int i0 = row_lo + er;
#pragma unroll
                for (int nf = 0; nf < 8; nf++) {
                    int j0 = kt * 64 + nf * 8 + ec;
                    if (j0     > i0)     sf[nf][0] = -1e30f;
                    if (j0 + 1 > i0)     sf[nf][1] = -1e30f;
                    if (j0     > i0 + 8) sf[nf][2] = -1e30f;
                    if (j0 + 1 > i0 + 8) sf[nf][3] = -1e30f;
                }
            }

            float rmax0 = -1e30f, rmax1 = -1e30f;
#pragma unroll
            for (int nf = 0; nf < 8; nf++) {
                rmax0 = fmaxf(rmax0, fmaxf(sf[nf][0], sf[nf][1]));
                rmax1 = fmaxf(rmax1, fmaxf(sf[nf][2], sf[nf][3]));
            }
            rmax0 = fmaxf(rmax0, __shfl_xor_sync(0xffffffffu, rmax0, 1));
            rmax0 = fmaxf(rmax0, __shfl_xor_sync(0xffffffffu, rmax0, 2));
            rmax1 = fmaxf(rmax1, __shfl_xor_sync(0xffffffffu, rmax1, 1));
            rmax1 = fmaxf(rmax1, __shfl_xor_sync(0xffffffffu, rmax1, 2));

            float nm0 = fmaxf(m[0], rmax0), nm1 = fmaxf(m[1], rmax1);
            float al0 = exp2f(m[0] - nm0), al1 = exp2f(m[1] - nm1);
            m[0] = nm0; m[1] = nm1;

            float sum0 = 0.0f, sum1 = 0.0f;
#pragma unroll
            for (int nf = 0; nf < 8; nf++) {
                sf[nf][0] = exp2f(sf[nf][0] - nm0);
                sf[nf][1] = exp2f(sf[nf][1] - nm0);
                sf[nf][2] = exp2f(sf[nf][2] - nm1);
                sf[nf][3] = exp2f(sf[nf][3] - nm1);
                sum0 += sf[nf][0] + sf[nf][1];
                sum1 += sf[nf][2] + sf[nf][3];
            }
            sum0 += __shfl_xor_sync(0xffffffffu, sum0, 1);
            sum0 += __shfl_xor_sync(0xffffffffu, sum0, 2);
            sum1 += __shfl_xor_sync(0xffffffffu, sum1, 1);
            sum1 += __shfl_xor_sync(0xffffffffu, sum1, 2);
            l[0] = l[0] * al0 + sum0;
            l[1] = l[1] * al1 + sum1;
#pragma unroll
            for (int i = 0; i < 8; i++) {
                acc[i][0] *= al0; acc[i][1] *= al0;
                acc[i][2] *= al1; acc[i][3] *= al1;
            }

            uint32_t pha[4][4];
#pragma unroll
            for (int kf = 0; kf < 4; kf++) {
#pragma unroll
                for (int half = 0; half < 2; half++) {
                    const float* s2 = sf[kf * 2 + half];
                    __half2 h01 = __floats2half2_rn(s2[0], s2[1]);
                    __half2 h23 = __floats2half2_rn(s2[2], s2[3]);
                    pha[kf][half * 2 + 0] = *(uint32_t*)&h01;
                    pha[kf][half * 2 + 1] = *(uint32_t*)&h23;
                }
            }

            // ---- O += P (Vh + Vl), term-outer ordering ----
#pragma unroll
            for (int kf = 0; kf < 4; kf++) {
                uint32_t vbh[4][4], vbl[4][4];
#pragma unroll
                for (int np = 0; np < 4; np++) {
                    uint32_t bd = ((np * 16 + b4_r) * FSTR + kf * 16 + b4_c) * 2;
                    ldsm4(vbh[np][0], vbh[np][1], vbh[np][2], vbh[np][3], sVh + bd);
                    ldsm4(vbl[np][0], vbl[np][1], vbl[np][2], vbl[np][3], sVl + bd);
                }
#pragma unroll
                for (int np = 0; np < 4; np++) {
                    mma_f16(acc[np * 2],     pha[kf], vbh[np]);
                    mma_f16(acc[np * 2 + 1], pha[kf], vbh[np] + 2);
                }
#pragma unroll
                for (int np = 0; np < 4; np++) {
                    mma_f16(acc[np * 2],     pha[kf], vbl[np]);
                    mma_f16(acc[np * 2 + 1], pha[kf], vbl[np] + 2);
                }
            }
        }
        __syncthreads();
    }

    float inv0 = 1.0f / l[0], inv1 = 1.0f / l[1];
#pragma unroll
    for (int nf = 0; nf < 8; nf++) {
        size_t o0 = ((size_t)(b * SS + q0 + warp_m + er) * NH + h) * HD + nf * 8 + ec;
        size_t o1 = ((size_t)(b * SS + q0 + warp_m + er + 8) * NH + h) * HD + nf * 8 + ec;
        __half2 h0 = __floats2half2_rn(acc[nf][0] * inv0, acc[nf][1] * inv0);
        __half2 h1 = __floats2half2_rn(acc[nf][2] * inv1, acc[nf][3] * inv1);
        *(uint32_t*)(Of + o0) = *(uint32_t*)&h0;
        *(uint32_t*)(Of + o1) = *(uint32_t*)&h1;
    }
}

// ---------------------------------------------------------------------------
extern "C" void kernel_launch(void* const* d_in, const int* in_sizes, int n_in,
                              void* d_out, int out_size)
{
    const float* x    = (const float*)d_in[0];
    const float* cosb = (const float*)d_in[1];
    const float* sinb = (const float*)d_in[2];
    const float* wq   = (const float*)d_in[3];
    const float* wk   = (const float*)d_in[4];
    const float* wv   = (const float*)d_in[5];
    const float* wo   = (const float*)d_in[6];
    float* out = (float*)d_out;

    __nv_bfloat16 *xh, *xl, *wqkvh, *wqkvl;
    __nv_bfloat16 *qh, *ql, *kh2, *kl2;
    __half *of, *woh, *wol, *vth, *vtl;
    cudaGetSymbolAddress((void**)&xh, g_xh);
    cudaGetSymbolAddress((void**)&xl, g_xl);
    cudaGetSymbolAddress((void**)&of, g_of);
    cudaGetSymbolAddress((void**)&wqkvh, g_wqkvh);
    cudaGetSymbolAddress((void**)&wqkvl, g_wqkvl);
    cudaGetSymbolAddress((void**)&woh, g_woh);
    cudaGetSymbolAddress((void**)&wol, g_wol);
    cudaGetSymbolAddress((void**)&qh, g_qh);
    cudaGetSymbolAddress((void**)&ql, g_ql);
    cudaGetSymbolAddress((void**)&kh2, g_kh2);
    cudaGetSymbolAddress((void**)&kl2, g_kl2);
    cudaGetSymbolAddress((void**)&vth, g_vth);
    cudaGetSymbolAddress((void**)&vtl, g_vtl);

    cudaFuncSetAttribute(gemm_qkv_kernel,
                         cudaFuncAttributeMaxDynamicSharedMemorySize, GEMM_SMEM);
    cudaFuncSetAttribute(gemm_out_f16_kernel,
                         cudaFuncAttributeMaxDynamicSharedMemorySize, OUT_SMEM);
    cudaFuncSetAttribute(flash_hmma_kernel,
                         cudaFuncAttributeMaxDynamicSharedMemorySize, FLASH_SMEM);

    const int M = BB * SS;  // 4096

    prep_kernel<<<SPLIT_BLOCKS + 2560, 256>>>(
        (const float4*)x, (__nv_bfloat162*)xh, (__nv_bfloat162*)xl,
        wq, wk, wv, wo, wqkvh, wqkvl, woh, wol);

    gemm_qkv_kernel<<<dim3(NQKV / 128, M / 128), 256, GEMM_SMEM>>>(
        xh, xl, wqkvh, wqkvl, cosb, sinb, qh, ql, kh2, kl2, vth, vtl);

    flash_hmma_kernel<<<dim3(SS / 128, NH, BB), 256, FLASH_SMEM>>>(
        qh, ql, kh2, kl2, vth, vtl, of);

    gemm_out_f16_kernel<<<dim3(DMODEL / 128, M / 128), 256, OUT_SMEM>>>(
        of, woh, wol, out, M, DMODEL, DMODEL);
}

// round 17
// speedup vs baseline: 1.3970x; 1.1498x over previous
#include <cuda_runtime.h>
#include <cuda_bf16.h>
#include <cuda_fp16.h>
#include <cstdint>
#include <math.h>

#define BB 2
#define SS 2048
#define DMODEL 1024
#define NH 16
#define NKH 4
#define HD 64
#define NQKV 1536

// ---------------------------------------------------------------------------
// Scratch (device globals: allocation-free)
// ---------------------------------------------------------------------------
__device__ __nv_bfloat16 g_xh[BB * SS * DMODEL];
__device__ __nv_bfloat16 g_xl[BB * SS * DMODEL];
__device__ __half        g_of[BB * SS * NH * HD];
__device__ __nv_bfloat16 g_wqkvh[NQKV * DMODEL];
__device__ __nv_bfloat16 g_wqkvl[NQKV * DMODEL];
__device__ __half        g_woh[DMODEL * (NH * HD)];
__device__ __half        g_wol[DMODEL * (NH * HD)];

__device__ __half g_qf[BB * SS * NH * HD];     // q single fp16 (scaled)
__device__ __half g_kf[BB * SS * NKH * HD];    // k single fp16
__device__ __half g_vth[BB * NKH * HD * SS];   // [b][kh][d][s]
__device__ __half g_vtl[BB * NKH * HD * SS];

// ---------------------------------------------------------------------------
// Warp-level MMA helpers
// ---------------------------------------------------------------------------
__device__ __forceinline__ uint32_t smem_u32(const void* p) {
    uint32_t a;
    asm("{ .reg .u64 t; cvta.to.shared.u64 t, %1; cvt.u32.u64 %0, t; }"
        : "=r"(a) : "l"(p));
    return a;
}

__device__ __forceinline__ void ldsm4(uint32_t& r0, uint32_t& r1,
                                      uint32_t& r2, uint32_t& r3, uint32_t a) {
    asm volatile("ldmatrix.sync.aligned.m8n8.x4.shared.b16 {%0,%1,%2,%3}, [%4];"
                 : "=r"(r0), "=r"(r1), "=r"(r2), "=r"(r3) : "r"(a));
}

__device__ __forceinline__ void mma_bf16(float* c, const uint32_t* a,
                                         const uint32_t* b) {
    asm volatile(
        "mma.sync.aligned.m16n8k16.row.col.f32.bf16.bf16.f32 "
        "{%0,%1,%2,%3}, {%4,%5,%6,%7}, {%8,%9}, {%0,%1,%2,%3};"
        : "+f"(c[0]), "+f"(c[1]), "+f"(c[2]), "+f"(c[3])
        : "r"(a[0]), "r"(a[1]), "r"(a[2]), "r"(a[3]), "r"(b[0]), "r"(b[1]));
}

__device__ __forceinline__ void mma_f16(float* c, const uint32_t* a,
                                        const uint32_t* b) {
    asm volatile(
        "mma.sync.aligned.m16n8k16.row.col.f32.f16.f16.f32 "
        "{%0,%1,%2,%3}, {%4,%5,%6,%7}, {%8,%9}, {%0,%1,%2,%3};"
        : "+f"(c[0]), "+f"(c[1]), "+f"(c[2]), "+f"(c[3])
        : "r"(a[0]), "r"(a[1]), "r"(a[2]), "r"(a[3]), "r"(b[0]), "r"(b[1]));
}

#define CP_ASYNC16(sa, ga) \
    asm volatile("cp.async.cg.shared.global [%0], [%1], 16;" \
                 :: "r"(sa), "l"(ga))
#define CP_COMMIT() asm volatile("cp.async.commit_group;")
#define CP_WAIT(N)  asm volatile("cp.async.wait_group %0;" :: "n"(N))

// ---------------------------------------------------------------------------
// GEMM common config
// ---------------------------------------------------------------------------
#define BK 32
#define GSTRIDE 40
#define GTILE_B (128 * GSTRIDE * 2)
#define GOFF(t, st) (((st) * 4 + (t)) * GTILE_B)
#define GEMM_SMEM (8 * GTILE_B)
#define OOFF(t, st) (((st) * 3 + (t)) * GTILE_B)
#define OUT_SMEM (9 * GTILE_B)
#define TSTR 132

#define GEMM_MAINLOOP(OUT_ACC)                                                \
    float OUT_ACC[4][4][4];                                                   \
    _Pragma("unroll")                                                         \
    for (int i = 0; i < 4; i++)                                               \
        _Pragma("unroll")                                                     \
        for (int j = 0; j < 4; j++)                                           \
            _Pragma("unroll")                                                 \
            for (int r = 0; r < 4; r++) OUT_ACC[i][j][r] = 0.0f;              \
    const int nchunk = K / BK;                                                \
    load_stage(0, 0);                                                         \
    const int a_r = lane & 15;                                                \
    const int a_c = (lane >> 4) * 8;                                          \
    const int g4 = lane >> 3;                                                 \
    const int b4_r = (g4 >> 1) * 8 + (lane & 7);                              \
    const int b4_c = (g4 & 1) * 8;                                            \
    for (int c = 0; c < nchunk; c++) {                                        \
        const int st = c & 1;                                                 \
        if (c + 1 < nchunk) { load_stage(c + 1, st ^ 1); CP_WAIT(1); }        \
        else { CP_WAIT(0); }                                                  \
        __syncthreads();                                                      \
        const uint32_t sAh = sb + GOFF(0, st);                                \
        const uint32_t sAl = sb + GOFF(1, st);                                \
        const uint32_t sBh = sb + GOFF(2, st);                                \
        const uint32_t sBl = sb + GOFF(3, st);                                \
        _Pragma("unroll")                                                     \
        for (int kf = 0; kf < 2; kf++) {                                      \
            const int kc = kf * 16;                                           \
            uint32_t ah[4][4], al[4][4], bh[4][2], bl[4][2];                  \
            _Pragma("unroll")                                                 \
            for (int mf = 0; mf < 4; mf++) {                                  \
                uint32_t ad = ((warp_m + mf * 16 + a_r) * GSTRIDE + kc + a_c) * 2; \
                ldsm4(ah[mf][0], ah[mf][1], ah[mf][2], ah[mf][3], sAh + ad);  \
            }                                                                 \
            _Pragma("unroll")                                                 \
            for (int np = 0; np < 2; np++) {                                  \
                uint32_t bd = ((warp_n + np * 16 + b4_r) * GSTRIDE + kc + b4_c) * 2; \
                ldsm4(bh[np * 2][0], bh[np * 2][1],                           \
                      bh[np * 2 + 1][0], bh[np * 2 + 1][1], sBh + bd);        \
                ldsm4(bl[np * 2][0], bl[np * 2][1],                           \
                      bl[np * 2 + 1][0], bl[np * 2 + 1][1], sBl + bd);        \
            }                                                                 \
            _Pragma("unroll")                                                 \
            for (int mf = 0; mf < 4; mf++)                                    \
                _Pragma("unroll")                                             \
                for (int nf = 0; nf < 4; nf++)                                \
                    mma_bf16(OUT_ACC[mf][nf], ah[mf], bh[nf]);                \
            _Pragma("unroll")                                                 \
            for (int mf = 0; mf < 4; mf++) {                                  \
                uint32_t ad = ((warp_m + mf * 16 + a_r) * GSTRIDE + kc + a_c) * 2; \
                ldsm4(al[mf][0], al[mf][1], al[mf][2], al[mf][3], sAl + ad);  \
            }                                                                 \
            _Pragma("unroll")                                                 \
            for (int mf = 0; mf < 4; mf++)                                    \
                _Pragma("unroll")                                             \
                for (int nf = 0; nf < 4; nf++)                                \
                    mma_bf16(OUT_ACC[mf][nf], ah[mf], bl[nf]);                \
            _Pragma("unroll")                                                 \
            for (int mf = 0; mf < 4; mf++)                                    \
                _Pragma("unroll")                                             \
                for (int nf = 0; nf < 4; nf++)                                \
                    mma_bf16(OUT_ACC[mf][nf], al[mf], bh[nf]);                \
        }                                                                     \
        __syncthreads();                                                      \
    }

// ---------------------------------------------------------------------------
// Out-projection GEMM: fp16 2-term, 3-stage pipeline.
// ---------------------------------------------------------------------------
__global__ __launch_bounds__(256, 2) void gemm_out_f16_kernel(
    const __half* __restrict__ Af,
    const __half* __restrict__ Bh, const __half* __restrict__ Bl,
    float* __restrict__ C, int M, int N, int K)
{
    extern __shared__ __align__(128) char smem[];
    const uint32_t sb = smem_u32(smem);
    const int tid = threadIdx.x;
    const int wid = tid >> 5;
    const int lane = tid & 31;
    const int bm = blockIdx.y * 128;
    const int bn = blockIdx.x * 128;
    const int warp_m = (wid >> 2) * 64;
    const int warp_n = (wid & 3) * 32;

    const __half* gp[3] = {
        Af + (size_t)bm * K, Bh + (size_t)bn * K, Bl + (size_t)bn * K };

    const int lrow0 = tid >> 2;
    const int lq = tid & 3;

    auto load_stage = [&](int c, int st) {
#pragma unroll
        for (int t = 0; t < 3; t++) {
            const __half* P = gp[t] + (size_t)c * BK;
#pragma unroll
            for (int it = 0; it < 2; it++) {
                int row = lrow0 + it * 64;
                uint32_t sa = sb + OOFF(t, st) + (row * GSTRIDE + lq * 8) * 2;
                CP_ASYNC16(sa, P + (size_t)row * K + lq * 8);
            }
        }
        CP_COMMIT();
    };

    float acc[4][4][4];
#pragma unroll
    for (int i = 0; i < 4; i++)
#pragma unroll
        for (int j = 0; j < 4; j++)
#pragma unroll
            for (int r = 0; r < 4; r++) acc[i][j][r] = 0.0f;

    const int nchunk = K / BK;
    load_stage(0, 0);
    load_stage(1, 1);

    const int a_r = lane & 15;
    const int a_c = (lane >> 4) * 8;
    const int g4 = lane >> 3;
    const int b4_r = (g4 >> 1) * 8 + (lane & 7);
    const int b4_c = (g4 & 1) * 8;

    for (int c = 0; c < nchunk; c++) {
        const int st = c % 3;
        if (c + 2 < nchunk) { load_stage(c + 2, (c + 2) % 3); CP_WAIT(2); }
        else if (c + 1 < nchunk) { CP_WAIT(1); }
        else { CP_WAIT(0); }
        __syncthreads();

        const uint32_t sAf = sb + OOFF(0, st);
        const uint32_t sBh = sb + OOFF(1, st);
        const uint32_t sBl = sb + OOFF(2, st);

#pragma unroll
        for (int kf = 0; kf < 2; kf++) {
            const int kc = kf * 16;
            uint32_t af[4][4], bh[4][2], bl[4][2];
#pragma unroll
            for (int mf = 0; mf < 4; mf++) {
                uint32_t ad = ((warp_m + mf * 16 + a_r) * GSTRIDE + kc + a_c) * 2;
                ldsm4(af[mf][0], af[mf][1], af[mf][2], af[mf][3], sAf + ad);
            }
#pragma unroll
            for (int np = 0; np < 2; np++) {
                uint32_t bd = ((warp_n + np * 16 + b4_r) * GSTRIDE + kc + b4_c) * 2;
                ldsm4(bh[np * 2][0], bh[np * 2][1],
                      bh[np * 2 + 1][0], bh[np * 2 + 1][1], sBh + bd);
                ldsm4(bl[np * 2][0], bl[np * 2][1],
                      bl[np * 2 + 1][0], bl[np * 2 + 1][1], sBl + bd);
            }
#pragma unroll
            for (int mf = 0; mf < 4; mf++)
#pragma unroll
                for (int nf = 0; nf < 4; nf++)
                    mma_f16(acc[mf][nf], af[mf], bh[nf]);
#pragma unroll
            for (int mf = 0; mf < 4; mf++)
#pragma unroll
                for (int nf = 0; nf < 4; nf++)
                    mma_f16(acc[mf][nf], af[mf], bl[nf]);
        }
        __syncthreads();
    }

    const int er = lane >> 2;
    const int ec = (lane & 3) * 2;
#pragma unroll
    for (int mf = 0; mf < 4; mf++) {
#pragma unroll
        for (int nf = 0; nf < 4; nf++) {
            float* base = C + (size_t)(bm + warp_m + mf * 16 + er) * N
                            + bn + warp_n + nf * 8 + ec;
            *(float2*)base = make_float2(acc[mf][nf][0], acc[mf][nf][1]);
            *(float2*)(base + 8 * N) = make_float2(acc[mf][nf][2], acc[mf][nf][3]);
        }
    }
}

// ---------------------------------------------------------------------------
// QKV GEMM (bf16x3) with fused RoPE / V-transpose epilogue.
// q/k written as single fp16 (q pre-scaled by 0.125*log2 e); V fp16 hi/lo.
// ---------------------------------------------------------------------------
__global__ __launch_bounds__(256, 2) void gemm_qkv_kernel(
    const __nv_bfloat16* __restrict__ Ah, const __nv_bfloat16* __restrict__ Al,
    const __nv_bfloat16* __restrict__ Bh, const __nv_bfloat16* __restrict__ Bl,
    const float* __restrict__ cosb, const float* __restrict__ sinb,
    __half* __restrict__ qf, __half* __restrict__ kfp,
    __half* __restrict__ vh, __half* __restrict__ vl)
{
    extern __shared__ __align__(128) char smem[];
    const uint32_t sb = smem_u32(smem);
    const int tid = threadIdx.x;
    const int wid = tid >> 5;
    const int lane = tid & 31;
    const int bm = blockIdx.y * 128;
    const int bn = blockIdx.x * 128;
    const int warp_m = (wid >> 2) * 64;
    const int warp_n = (wid & 3) * 32;
    const int K = DMODEL;

    const __nv_bfloat16* gp[4] = {
        Ah + (size_t)bm * K, Al + (size_t)bm * K,
        Bh + (size_t)bn * K, Bl + (size_t)bn * K };

    const int lrow0 = tid >> 2;
    const int lq = tid & 3;

    auto load_stage = [&](int c, int st) {
#pragma unroll
        for (int t = 0; t < 4; t++) {
            const __nv_bfloat16* P = gp[t] + (size_t)c * BK;
#pragma unroll
            for (int it = 0; it < 2; it++) {
                int row = lrow0 + it * 64;
                uint32_t sa = sb + GOFF(t, st) + (row * GSTRIDE + lq * 8) * 2;
                CP_ASYNC16(sa, P + (size_t)row * K + lq * 8);
            }
        }
        CP_COMMIT();
    };

    GEMM_MAINLOOP(acc)

    float* Ts = (float*)smem;
    const int er = lane >> 2;
    const int ec = (lane & 3) * 2;
#pragma unroll
    for (int mf = 0; mf < 4; mf++) {
#pragma unroll
        for (int nf = 0; nf < 4; nf++) {
            int r = warp_m + mf * 16 + er;
            int c = warp_n + nf * 8 + ec;
            *(float2*)&Ts[r * TSTR + c] = make_float2(acc[mf][nf][0], acc[mf][nf][1]);
            *(float2*)&Ts[(r + 8) * TSTR + c] = make_float2(acc[mf][nf][2], acc[mf][nf][3]);
        }
    }
    __syncthreads();

    if (bn < 1280) {
        const bool isq = (bn < 1024);
        const float scl = isq ? 0.125f * 1.4426950408889634f : 1.0f;
        __half* th = isq ? qf : kfp;
        const int nheads = isq ? NH : NKH;
        const int h0 = isq ? (bn >> 6) : ((bn - 1024) >> 6);

#pragma unroll
        for (int it = 0; it < 8; it++) {
            int idx = tid + it * 256;
            int d0 = (idx & 7) * 4;
            int hh = (idx >> 3) & 1;
            int row = idx >> 4;
            int bs = bm + row;
            int s = bs & (SS - 1);

            const float* tr = &Ts[row * TSTR + hh * 64];
            float4 v0 = *(const float4*)(tr + d0);
            float4 v1 = *(const float4*)(tr + d0 + 32);
            float4 c0 = *(const float4*)(cosb + s * HD + d0);
            float4 c1 = *(const float4*)(cosb + s * HD + d0 + 32);
            float4 s0v = *(const float4*)(sinb + s * HD + d0);
            float4 s1v = *(const float4*)(sinb + s * HD + d0 + 32);

            float r0x = (v0.x * c0.x - v1.x * s0v.x) * scl;
            float r0y = (v0.y * c0.y - v1.y * s0v.y) * scl;
            float r0z = (v0.z * c0.z - v1.z * s0v.z) * scl;
            float r0w = (v0.w * c0.w - v1.w * s0v.w) * scl;
            float r1x = (v1.x * c1.x + v0.x * s1v.x) * scl;
            float r1y = (v1.y * c1.y + v0.y * s1v.y) * scl;
            float r1z = (v1.z * c1.z + v0.z * s1v.z) * scl;
            float r1w = (v1.w * c1.w + v0.w * s1v.w) * scl;

            size_t base = ((size_t)bs * nheads + h0 + hh) * HD;

            __half2 h0a = __floats2half2_rn(r0x, r0y);
            __half2 h0b = __floats2half2_rn(r0z, r0w);
            __half2 h1a = __floats2half2_rn(r1x, r1y);
            __half2 h1b = __floats2half2_rn(r1z, r1w);
            *(uint2*)(th + base + d0)      = make_uint2(*(uint32_t*)&h0a, *(uint32_t*)&h0b);
            *(uint2*)(th + base + d0 + 32) = make_uint2(*(uint32_t*)&h1a, *(uint32_t*)&h1b);
        }
    } else {
        const int c = tid & 127;
        const int sh = tid >> 7;
        const int khead = ((bn - 1280) >> 6) + (c >> 6);
        const int d = c & 63;
        const int b = bm >> 11;
        const int s0 = (bm & (SS - 1)) + sh * 64;
        size_t base = ((size_t)(b * NKH + khead) * HD + d) * SS + s0;

#pragma unroll 4
        for (int s4 = 0; s4 < 64; s4 += 4) {
            float v0 = Ts[(sh * 64 + s4 + 0) * TSTR + c];
            float v1 = Ts[(sh * 64 + s4 + 1) * TSTR + c];
            float v2 = Ts[(sh * 64 + s4 + 2) * TSTR + c];
            float v3 = Ts[(sh * 64 + s4 + 3) * TSTR + c];
            __half2 p01 = __floats2half2_rn(v0, v1);
            __half2 p23 = __floats2half2_rn(v2, v3);
            *(uint2*)(vh + base + s4) = make_uint2(*(uint32_t*)&p01, *(uint32_t*)&p23);
            __half2 q01 = __floats2half2_rn(v0 - __low2float(p01), v1 - __high2float(p01));
            __half2 q23 = __floats2half2_rn(v2 - __low2float(p23), v3 - __high2float(p23));
            *(uint2*)(vl + base + s4) = make_uint2(*(uint32_t*)&q01, *(uint32_t*)&q23);
        }
    }
}

// ---------------------------------------------------------------------------
// Fused prep.
// ---------------------------------------------------------------------------
#define SPLIT_BLOCKS 4096

__global__ void prep_kernel(
    const float4* __restrict__ x4,
    __nv_bfloat162* __restrict__ xh2, __nv_bfloat162* __restrict__ xl2,
    const float* __restrict__ wq, const float* __restrict__ wk,
    const float* __restrict__ wv, const float* __restrict__ wo,
    __nv_bfloat16* __restrict__ wqkvh, __nv_bfloat16* __restrict__ wqkvl,
    __half* __restrict__ woh, __half* __restrict__ wol)
{
    __shared__ float t[32][33];
    const int tid = threadIdx.x;

    if (blockIdx.x < SPLIT_BLOCKS) {
        int i = blockIdx.x * 256 + tid;
        float4 v = x4[i];
        __nv_bfloat16 h0 = __float2bfloat16(v.x);
        __nv_bfloat16 h1 = __float2bfloat16(v.y);
        __nv_bfloat16 h2 = __float2bfloat16(v.z);
        __nv_bfloat16 h3 = __float2bfloat16(v.w);
        xh2[2 * i]     = __nv_bfloat162(h0, h1);
        xh2[2 * i + 1] = __nv_bfloat162(h2, h3);
        xl2[2 * i]     = __nv_bfloat162(
            __float2bfloat16(v.x - __bfloat162float(h0)),
            __float2bfloat16(v.y - __bfloat162float(h1)));
        xl2[2 * i + 1] = __nv_bfloat162(
            __float2bfloat16(v.z - __bfloat162float(h2)),
            __float2bfloat16(v.w - __bfloat162float(h3)));
    } else {
        const int tile = blockIdx.x - SPLIT_BLOCKS;
        const float* src;
        int N, tloc, iswo = 0;
        __nv_bfloat16 *dh = nullptr, *dl = nullptr;
        if (tile < 1024)      { src = wq; dh = wqkvh;                  dl = wqkvl;                  N = 1024; tloc = tile; }
        else if (tile < 1280) { src = wk; dh = wqkvh + 1024 * DMODEL;  dl = wqkvl + 1024 * DMODEL;  N = 256;  tloc = tile - 1024; }
        else if (tile < 1536) { src = wv; dh = wqkvh + 1280 * DMODEL;  dl = wqkvl + 1280 * DMODEL;  N = 256;  tloc = tile - 1280; }
        else                  { src = wo; iswo = 1;                                                 N = 1024; tloc = tile - 1536; }
        const int nx = N >> 5;
        const int K = 1024;
        const int n0 = (tloc % nx) * 32;
        const int k0 = (tloc / nx) * 32;
        const int tx = tid & 31, ty = tid >> 5;
#pragma unroll
        for (int i = 0; i < 32; i += 8)
            t[ty + i][tx] = src[(size_t)(k0 + ty + i) * N + n0 + tx];
        __syncthreads();
#pragma unroll
        for (int i = 0; i < 32; i += 8) {
            float v = t[tx][ty + i];
            size_t o = (size_t)(n0 + ty + i) * K + k0 + tx;
            if (iswo) {
                __half h = __float2half_rn(v);
                woh[o] = h;
                wol[o] = __float2half_rn(v - __half2float(h));
            } else {
                __nv_bfloat16 h = __float2bfloat16(v);
                dh[o] = h;
                dl[o] = __float2bfloat16(v - __bfloat162float(h));
            }
        }
    }
}

// ---------------------------------------------------------------------------
// HMMA flash attention, causal, GQA.
// BM=128 (8 warps), BN=64; 3-stage; exp2; LPT; Q in regs.
// S: fp16 Qf x fp16 Kf (1 MMA).  PV: fp16 P x fp16 V (hi+lo, 2 MMAs).
// ---------------------------------------------------------------------------
#define FSTR 72
#define FTILE64 (64 * FSTR * 2)
#define FQ_TILE (128 * FSTR * 2)
#define FSTG(st) (FQ_TILE + (st) * 3 * FTILE64)
#define FLASH_SMEM (FQ_TILE + 3 * 3 * FTILE64)   // 101376 B

__global__ __launch_bounds__(256) void flash_hmma_kernel(
    const __half* __restrict__ Qf, const __half* __restrict__ Kf,
    const __half* __restrict__ Vth, const __half* __restrict__ Vtl,
    __half* __restrict__ Of)
{
    extern __shared__ __align__(128) char smem[];
    const uint32_t sb = smem_u32(smem);
    const int tid = threadIdx.x;
    const int wid = tid >> 5;
    const int lane = tid & 31;
    const int qt = gridDim.x - 1 - blockIdx.x;   // LPT
    const int h  = blockIdx.y;
    const int b  = blockIdx.z;
    const int q0 = qt * 128;
    const int khead = h >> 2;
    const int warp_m = wid * 16;

    const int er = lane >> 2;
    const int ec = (lane & 3) * 2;
    const int a_r = lane & 15;
    const int a_c = (lane >> 4) * 8;
    const int g4 = lane >> 3;
    const int b4_r = (g4 >> 1) * 8 + (lane & 7);
    const int b4_c = (g4 & 1) * 8;

    const __half* qf_g = Qf + ((size_t)(b * SS + q0) * NH + h) * HD;
    const __half* kf_g = Kf + ((size_t)b * SS * NKH + khead) * HD;
    const __half* vth_g = Vth + (size_t)(b * NKH + khead) * HD * SS;
    const __half* vtl_g = Vtl + (size_t)(b * NKH + khead) * HD * SS;

    auto load_tile64 = [&](const void* g, size_t rstride_elt, uint32_t sofs) {
#pragma unroll
        for (int it = 0; it < 2; it++) {
            int ch = tid + it * 256;
            int r = ch >> 3;
            int q8 = ch & 7;
            CP_ASYNC16(sb + sofs + (r * FSTR + q8 * 8) * 2,
                       (const char*)g + ((size_t)r * rstride_elt + q8 * 8) * 2);
        }
    };
    auto load_q = [&](const __half* g, uint32_t sofs) {
#pragma unroll
        for (int it = 0; it < 4; it++) {
            int ch = tid + it * 256;
            int r = ch >> 3;
            int q8 = ch & 7;
            CP_ASYNC16(sb + sofs + (r * FSTR + q8 * 8) * 2,
                       g + (size_t)r * (NH * HD) + q8 * 8);
        }
    };
    auto load_stage = [&](int kt, int st) {
        const int kn = kt * 64;
        load_tile64(kf_g + (size_t)kn * NKH * HD, NKH * HD, FSTG(st) + 0 * FTILE64);
        load_tile64(vth_g + kn, SS, FSTG(st) + 1 * FTILE64);
        load_tile64(vtl_g + kn, SS, FSTG(st) + 2 * FTILE64);
        CP_COMMIT();
    };

    const int kt_end = 2 * qt + 1;

    load_q(qf_g, 0);
    CP_COMMIT();
    load_stage(0, 0);
    if (kt_end >= 1) { load_stage(1, 1); CP_WAIT(2); }
    else             { CP_WAIT(1); }
    __syncthreads();

    // Q fragments in registers (fp16), live across the loop.
    uint32_t qaf[4][4];
#pragma unroll
    for (int kf = 0; kf < 4; kf++) {
        uint32_t ad = ((warp_m + a_r) * FSTR + kf * 16 + a_c) * 2;
        ldsm4(qaf[kf][0], qaf[kf][1], qaf[kf][2], qaf[kf][3], sb + ad);
    }

    float m[2] = {-1e30f, -1e30f};
    float l[2] = {0.0f, 0.0f};
    float acc[8][4];
#pragma unroll
    for (int i = 0; i < 8; i++)
#pragma unroll
        for (int r = 0; r < 4; r++) acc[i][r] = 0.0f;

    for (int kt = 0; kt <= kt_end; kt++) {
        const int st = kt % 3;
        if (kt + 2 <= kt_end) {
            load_stage(kt + 2, (kt + 2) % 3);
            CP_WAIT(2);
        } else if (kt + 1 <= kt_end) {
            CP_WAIT(1);
        } else {
            CP_WAIT(0);
        }
        __syncthreads();

        const int row_lo = q0 + warp_m;
        const bool any  = (kt * 64     <= row_lo + 15);
        const bool full = (kt * 64 + 63 <= row_lo);

        if (any) {
            const uint32_t sKf = sb + FSTG(st);
            const uint32_t sVh = sKf + FTILE64;
            const uint32_t sVl = sKf + 2 * FTILE64;

            float sf[8][4];
#pragma unroll
            for (int nf = 0; nf < 8; nf++)
#pragma unroll
                for (int r = 0; r < 4; r++) sf[nf][r] = 0.0f;

            // ---- S = Qf Kf^T (single fp16 MMA per fragment) ----
#pragma unroll
            for (int kf = 0; kf < 4; kf++) {
                const int kc = kf * 16;
                uint32_t kbf[4][4];
#pragma unroll
                for (int np = 0; np < 4; np++) {
                    uint32_t bd = ((np * 16 + b4_r) * FSTR + kc + b4_c) * 2;
                    ldsm4(kbf[np][0], kbf[np][1], kbf[np][2], kbf[np][3], sKf + bd);
                }
#pragma unroll
                for (int np = 0; np < 4; np++) {
                    mma_f16(sf[np * 2],     qaf[kf], kbf[np]);
                    mma_f16(sf[np * 2 + 1], qaf[kf], kbf[np] + 2);
                }
            }

            if (!full) {
                const int i0 = row_lo + er;
#pragma unroll
                for (int nf = 0; nf < 8; nf++) {
                    int j0 = kt * 64 + nf * 8 + ec;
                    if (j0     > i0)     sf[nf][0] = -1e30f;
                    if (j0 + 1 > i0)     sf[nf][1] = -1e30f;
                    if (j0     > i0 + 8) sf[nf][2] = -1e30f;
                    if (j0 + 1 > i0 + 8) sf[nf][3] = -1e30f;
                }
            }

            float rmax0 = -1e30f, rmax1 = -1e30f;
#pragma unroll
            for (int nf = 0; nf < 8; nf++) {
                rmax0 = fmaxf(rmax0, fmaxf(sf[nf][0], sf[nf][1]));
                rmax1 = fmaxf(rmax1, fmaxf(sf[nf][2], sf[nf][3]));
            }
            rmax0 = fmaxf(rmax0, __shfl_xor_sync(0xffffffffu, rmax0, 1));
            rmax0 = fmaxf(rmax0, __shfl_xor_sync(0xffffffffu, rmax0, 2));
            rmax1 = fmaxf(rmax1, __shfl_xor_sync(0xffffffffu, rmax1, 1));
            rmax1 = fmaxf(rmax1, __shfl_xor_sync(0xffffffffu, rmax1, 2));

            float nm0 = fmaxf(m[0], rmax0), nm1 = fmaxf(m[1], rmax1);
            float al0 = exp2f(m[0] - nm0), al1 = exp2f(m[1] - nm1);
            m[0] = nm0; m[1] = nm1;

            float sum0 = 0.0f, sum1 = 0.0f;
#pragma unroll
            for (int nf = 0; nf < 8; nf++) {
                sf[nf][0] = exp2f(sf[nf][0] - nm0);
                sf[nf][1] = exp2f(sf[nf][1] - nm0);
                sf[nf][2] = exp2f(sf[nf][2] - nm1);
                sf[nf][3] = exp2f(sf[nf][3] - nm1);
                sum0 += sf[nf][0] + sf[nf][1];
                sum1 += sf[nf][2] + sf[nf][3];
            }
            sum0 += __shfl_xor_sync(0xffffffffu, sum0, 1);
            sum0 += __shfl_xor_sync(0xffffffffu, sum0, 2);
            sum1 += __shfl_xor_sync(0xffffffffu, sum1, 1);
            sum1 += __shfl_xor_sync(0xffffffffu, sum1, 2);
            l[0] = l[0] * al0 + sum0;
            l[1] = l[1] * al1 + sum1;
#pragma unroll
            for (int i = 0; i < 8; i++) {
                acc[i][0] *= al0; acc[i][1] *= al0;
                acc[i][2] *= al1; acc[i][3] *= al1;
            }

            uint32_t pha[4][4];
#pragma unroll
            for (int kf = 0; kf < 4; kf++) {
#pragma unroll
                for (int half = 0; half < 2; half++) {
                    const float* s2 = sf[kf * 2 + half];
                    __half2 h01 = __floats2half2_rn(s2[0], s2[1]);
                    __half2 h23 = __floats2half2_rn(s2[2], s2[3]);
                    pha[kf][half * 2 + 0] = *(uint32_t*)&h01;
                    pha[kf][half * 2 + 1] = *(uint32_t*)&h23;
                }
            }

            // ---- O += P (Vh + Vl) ----
#pragma unroll
            for (int kf = 0; kf < 4; kf++) {
                uint32_t vbh[4][4], vbl[4][4];
#pragma unroll
                for (int np = 0; np < 4; np++) {
                    uint32_t bd = ((np * 16 + b4_r) * FSTR + kf * 16 + b4_c) * 2;
                    ldsm4(vbh[np][0], vbh[np][1], vbh[np][2], vbh[np][3], sVh + bd);
                    ldsm4(vbl[np][0], vbl[np][1], vbl[np][2], vbl[np][3], sVl + bd);
                }
#pragma unroll
                for (int np = 0; np < 4; np++) {
                    mma_f16(acc[np * 2],     pha[kf], vbh[np]);
                    mma_f16(acc[np * 2 + 1], pha[kf], vbh[np] + 2);
                }
#pragma unroll
                for (int np = 0; np < 4; np++) {
                    mma_f16(acc[np * 2],     pha[kf], vbl[np]);
                    mma_f16(acc[np * 2 + 1], pha[kf], vbl[np] + 2);
                }
            }
        }
        __syncthreads();
    }

    float inv0 = 1.0f / l[0], inv1 = 1.0f / l[1];
#pragma unroll
    for (int nf = 0; nf < 8; nf++) {
        size_t o0 = ((size_t)(b * SS + q0 + warp_m + er) * NH + h) * HD + nf * 8 + ec;
        size_t o1 = ((size_t)(b * SS + q0 + warp_m + er + 8) * NH + h) * HD + nf * 8 + ec;
        __half2 h0 = __floats2half2_rn(acc[nf][0] * inv0, acc[nf][1] * inv0);
        __half2 h1 = __floats2half2_rn(acc[nf][2] * inv1, acc[nf][3] * inv1);
        *(uint32_t*)(Of + o0) = *(uint32_t*)&h0;
        *(uint32_t*)(Of + o1) = *(uint32_t*)&h1;
    }
}

// ---------------------------------------------------------------------------
extern "C" void kernel_launch(void* const* d_in, const int* in_sizes, int n_in,
                              void* d_out, int out_size)
{
    const float* x    = (const float*)d_in[0];
    const float* cosb = (const float*)d_in[1];
    const float* sinb = (const float*)d_in[2];
    const float* wq   = (const float*)d_in[3];
    const float* wk   = (const float*)d_in[4];
    const float* wv   = (const float*)d_in[5];
    const float* wo   = (const float*)d_in[6];
    float* out = (float*)d_out;

    __nv_bfloat16 *xh, *xl, *wqkvh, *wqkvl;
    __half *of, *woh, *wol, *qf, *kf, *vth, *vtl;
    cudaGetSymbolAddress((void**)&xh, g_xh);
    cudaGetSymbolAddress((void**)&xl, g_xl);
    cudaGetSymbolAddress((void**)&of, g_of);
    cudaGetSymbolAddress((void**)&wqkvh, g_wqkvh);
    cudaGetSymbolAddress((void**)&wqkvl, g_wqkvl);
    cudaGetSymbolAddress((void**)&woh, g_woh);
    cudaGetSymbolAddress((void**)&wol, g_wol);
    cudaGetSymbolAddress((void**)&qf, g_qf);
    cudaGetSymbolAddress((void**)&kf, g_kf);
    cudaGetSymbolAddress((void**)&vth, g_vth);
    cudaGetSymbolAddress((void**)&vtl, g_vtl);

    cudaFuncSetAttribute(gemm_qkv_kernel,
                         cudaFuncAttributeMaxDynamicSharedMemorySize, GEMM_SMEM);
    cudaFuncSetAttribute(gemm_out_f16_kernel,
                         cudaFuncAttributeMaxDynamicSharedMemorySize, OUT_SMEM);
    cudaFuncSetAttribute(flash_hmma_kernel,
                         cudaFuncAttributeMaxDynamicSharedMemorySize, FLASH_SMEM);

    const int M = BB * SS;  // 4096

    prep_kernel<<<SPLIT_BLOCKS + 2560, 256>>>(
        (const float4*)x, (__nv_bfloat162*)xh, (__nv_bfloat162*)xl,
        wq, wk, wv, wo, wqkvh, wqkvl, woh, wol);

    gemm_qkv_kernel<<<dim3(NQKV / 128, M / 128), 256, GEMM_SMEM>>>(
        xh, xl, wqkvh, wqkvl, cosb, sinb, qf, kf, vth, vtl);

    flash_hmma_kernel<<<dim3(SS / 128, NH, BB), 256, FLASH_SMEM>>>(
        qf, kf, vth, vtl, of);

    gemm_out_f16_kernel<<<dim3(DMODEL / 128, M / 128), 256, OUT_SMEM>>>(
        of, woh, wol, out, M, DMODEL, DMODEL);
}